// round 4
// baseline (speedup 1.0000x reference)
#include <cuda_runtime.h>
#include <math.h>

#define N_NODES 50000
#define IN_CH   256
#define HEADS   3
#define OUT_C   128
#define HC      384
#define NREL    3
#define NEDGE   400000
#define SEMD    128
#define RN      (NREL * N_NODES)     /* 150000 */
#define TOTE    (NREL * NEDGE)       /* 1200000 */
#define XPC     (NREL * HC)          /* 1152 */

/* ------------------------------------------------------------------ */
/* scratch (static device globals — no runtime allocation)             */
/* ------------------------------------------------------------------ */
__device__ float g_xp  [(size_t)N_NODES * XPC];   /* x @ theta, [N][R*HC] */
__device__ float g_gout[(size_t)N_NODES * XPC];   /* relu(gat+bias), [N][R][HC] */
__device__ float g_as  [N_NODES * NREL * HEADS];
__device__ float g_ad  [N_NODES * NREL * HEADS];
__device__ int   g_deg [RN];
__device__ int   g_off [RN + 1];
__device__ int   g_cur [RN];
__device__ int   g_adj [TOTE];
__device__ int   g_part[256];
__device__ int   g_is64;

/* ------------------------------------------------------------------ */
/* edge_index dtype detection: JAX default x64-disabled makes          */
/* jnp.int64 silently int32. Detect at runtime: int64 data read as     */
/* int32 words has every odd (high) word == 0; int32 node ids in       */
/* [0,50000) make that impossible over 64 samples.                     */
/* ------------------------------------------------------------------ */
__global__ void detect_kernel(const int* __restrict__ ei32)
{
    if (threadIdx.x == 0) {
        int is64 = 1;
        for (int i = 1; i < 128; i += 2)
            if (ei32[i] != 0) { is64 = 0; break; }
        g_is64 = is64;
    }
}

__device__ __forceinline__ int load_idx(const void* ei, int is64, size_t pos)
{
    int v = is64 ? (int)((const long long*)ei)[pos]
                 : ((const int*)ei)[pos];
    /* clamp: turn any residual dtype misread into rel_err, not a crash */
    if ((unsigned)v >= (unsigned)N_NODES) v = 0;
    return v;
}

/* ------------------------------------------------------------------ */
/* GEMM1: g_xp[m][j] = sum_k x[m][k] * theta[r][k][hc],  j = r*384+hc  */
/* 128x64 tile, K-step 8, 256 threads, 8x4 micro-tile                  */
/* ------------------------------------------------------------------ */
__global__ void gemm1_kernel(const float* __restrict__ x,
                             const float* __restrict__ theta)
{
    __shared__ float As[8][128];
    __shared__ float Bs[8][64];

    const int tid  = threadIdx.x;
    const int tx   = tid & 15;       /* 0..15 -> 4 cols  */
    const int ty   = tid >> 4;       /* 0..15 -> 8 rows  */
    const int row0 = blockIdx.y * 128;
    const int col0 = blockIdx.x * 64;
    const int rsel = col0 / HC;
    const int hc0  = col0 % HC;
    const float* B = theta + (size_t)rsel * IN_CH * HC;

    float acc[8][4];
#pragma unroll
    for (int i = 0; i < 8; i++)
#pragma unroll
        for (int j = 0; j < 4; j++) acc[i][j] = 0.f;

    const int lm = tid >> 1;          /* 0..127 */
    const int lk = (tid & 1) * 4;     /* 0 or 4 */

    for (int k0 = 0; k0 < IN_CH; k0 += 8) {
        /* A tile: 128 rows x 8 k */
        float4 av = make_float4(0.f, 0.f, 0.f, 0.f);
        int arow = row0 + lm;
        if (arow < N_NODES)
            av = *(const float4*)&x[(size_t)arow * IN_CH + k0 + lk];
        As[lk + 0][lm] = av.x;
        As[lk + 1][lm] = av.y;
        As[lk + 2][lm] = av.z;
        As[lk + 3][lm] = av.w;
        /* B tile: 8 k x 64 cols (cols never straddle a relation: 384%64==0) */
        if (tid < 128) {
            int k = tid >> 4;           /* 0..7  */
            int j = (tid & 15) * 4;     /* 0..60 */
            *(float4*)&Bs[k][j] =
                *(const float4*)&B[(size_t)(k0 + k) * HC + hc0 + j];
        }
        __syncthreads();

#pragma unroll
        for (int kk = 0; kk < 8; kk++) {
            float a[8], b[4];
            *(float4*)&a[0] = *(float4*)&As[kk][ty * 8];
            *(float4*)&a[4] = *(float4*)&As[kk][ty * 8 + 4];
            *(float4*)&b[0] = *(float4*)&Bs[kk][tx * 4];
#pragma unroll
            for (int i = 0; i < 8; i++)
#pragma unroll
                for (int j = 0; j < 4; j++)
                    acc[i][j] = fmaf(a[i], b[j], acc[i][j]);
        }
        __syncthreads();
    }

#pragma unroll
    for (int i = 0; i < 8; i++) {
        int m = row0 + ty * 8 + i;
        if (m < N_NODES) {
            float4 v = make_float4(acc[i][0], acc[i][1], acc[i][2], acc[i][3]);
            *(float4*)&g_xp[(size_t)m * XPC + col0 + tx * 4] = v;
        }
    }
}

/* ------------------------------------------------------------------ */
/* per-node attention logits: a_s/a_d[n][r][h] = sum_c xp*att          */
/* one warp per (n,r,h)                                                */
/* ------------------------------------------------------------------ */
__global__ void asd_kernel(const float* __restrict__ att_src,
                           const float* __restrict__ att_dst)
{
    const int wid  = threadIdx.x >> 5;
    const int lane = threadIdx.x & 31;
    const int item = blockIdx.x * 4 + wid;
    if (item >= N_NODES * NREL * HEADS) return;
    const int n  = item / (NREL * HEADS);
    const int rh = item % (NREL * HEADS);
    const int r  = rh / HEADS;
    const int h  = rh % HEADS;

    const float4 xv = *(const float4*)&g_xp[(size_t)n * XPC + r * HC + h * OUT_C + lane * 4];
    const float4 sv = *(const float4*)&att_src[(size_t)(r * HEADS + h) * OUT_C + lane * 4];
    const float4 dv = *(const float4*)&att_dst[(size_t)(r * HEADS + h) * OUT_C + lane * 4];

    float ds = xv.x * sv.x + xv.y * sv.y + xv.z * sv.z + xv.w * sv.w;
    float dd = xv.x * dv.x + xv.y * dv.y + xv.z * dv.z + xv.w * dv.w;
#pragma unroll
    for (int o = 16; o > 0; o >>= 1) {
        ds += __shfl_xor_sync(0xffffffffu, ds, o);
        dd += __shfl_xor_sync(0xffffffffu, dd, o);
    }
    if (lane == 0) {
        g_as[item] = ds;
        g_ad[item] = dd;
    }
}

/* ------------------------------------------------------------------ */
/* CSR build                                                           */
/* ------------------------------------------------------------------ */
__global__ void zero_deg_kernel()
{
    int i = blockIdx.x * blockDim.x + threadIdx.x;
    if (i < RN) g_deg[i] = 0;
}

__global__ void count_kernel(const void* __restrict__ ei)
{
    int i = blockIdx.x * blockDim.x + threadIdx.x;
    if (i >= TOTE) return;
    const int is64 = g_is64;
    int r = i / NEDGE;
    int e = i % NEDGE;
    int dst = load_idx(ei, is64, (size_t)r * 2 * NEDGE + NEDGE + e);
    atomicAdd(&g_deg[r * N_NODES + dst], 1);
}

#define SCH 1024
__global__ void scan1_kernel()
{
    __shared__ int s[256];
    const int b = blockIdx.x, t = threadIdx.x;
    const int base = b * SCH + t * 4;
    int v[4], sum = 0;
#pragma unroll
    for (int i = 0; i < 4; i++) {
        int idx = base + i;
        v[i] = (idx < RN) ? g_deg[idx] : 0;
        sum += v[i];
    }
    s[t] = sum;
    __syncthreads();
    for (int o = 1; o < 256; o <<= 1) {
        int xv = (t >= o) ? s[t - o] : 0;
        __syncthreads();
        s[t] += xv;
        __syncthreads();
    }
    int run = s[t] - sum;   /* exclusive prefix for this thread */
    if (t == 255) g_part[b] = s[t];
#pragma unroll
    for (int i = 0; i < 4; i++) {
        int idx = base + i;
        if (idx < RN) g_off[idx] = run;
        run += v[i];
    }
}

__global__ void scan2_kernel(int nb)
{
    __shared__ int s[256];
    const int t = threadIdx.x;
    int v = (t < nb) ? g_part[t] : 0;
    s[t] = v;
    __syncthreads();
    for (int o = 1; o < 256; o <<= 1) {
        int xv = (t >= o) ? s[t - o] : 0;
        __syncthreads();
        s[t] += xv;
        __syncthreads();
    }
    g_part[t] = s[t] - v;   /* exclusive */
}

__global__ void scan3_kernel()
{
    int i = blockIdx.x * blockDim.x + threadIdx.x;
    if (i < RN) {
        int v = g_off[i] + g_part[i / SCH];
        g_off[i] = v;
        g_cur[i] = v;
    }
    if (i == 0) g_off[RN] = TOTE;
}

__global__ void fill_kernel(const void* __restrict__ ei)
{
    int i = blockIdx.x * blockDim.x + threadIdx.x;
    if (i >= TOTE) return;
    const int is64 = g_is64;
    int r = i / NEDGE;
    int e = i % NEDGE;
    int src = load_idx(ei, is64, (size_t)r * 2 * NEDGE + e);
    int dst = load_idx(ei, is64, (size_t)r * 2 * NEDGE + NEDGE + e);
    int pos = atomicAdd(&g_cur[r * N_NODES + dst], 1);
    if (pos >= 0 && pos < TOTE) g_adj[pos] = src;
}

/* ------------------------------------------------------------------ */
/* GAT aggregation: one warp per (r,n); local softmax over in-edges    */
/* (incl. implicit self-loop), channel-parallel gather-accumulate      */
/* ------------------------------------------------------------------ */
#define ACAP 64
__device__ __forceinline__ float lrelu(float v) { return v > 0.f ? v : 0.2f * v; }

__global__ void agg_kernel(const float* __restrict__ gat_bias)
{
    __shared__ float pbuf[4][ACAP][3];
    __shared__ int   sbuf[4][ACAP];

    const int w    = threadIdx.x >> 5;
    const int lane = threadIdx.x & 31;
    const int item = blockIdx.x * 4 + w;
    if (item >= RN) return;
    const int r = item / N_NODES;      /* relation-major -> L2 residency of xp[r] */
    const int n = item % N_NODES;

    const int off0 = g_off[r * N_NODES + n];
    const int deg  = g_off[r * N_NODES + n + 1] - off0;
    const int tot  = deg + 1;          /* + self loop */

    const float ad0 = g_ad[(n * NREL + r) * HEADS + 0];
    const float ad1 = g_ad[(n * NREL + r) * HEADS + 1];
    const float ad2 = g_ad[(n * NREL + r) * HEADS + 2];

    /* pass 1: max per head */
    float m0 = -1e30f, m1 = -1e30f, m2 = -1e30f;
    for (int base = 0; base < tot; base += 32) {
        int i = base + lane;
        if (i < tot) {
            int src = (i < deg) ? g_adj[off0 + i] : n;
            const float* as = &g_as[(src * NREL + r) * HEADS];
            m0 = fmaxf(m0, lrelu(as[0] + ad0));
            m1 = fmaxf(m1, lrelu(as[1] + ad1));
            m2 = fmaxf(m2, lrelu(as[2] + ad2));
        }
    }
#pragma unroll
    for (int o = 16; o > 0; o >>= 1) {
        m0 = fmaxf(m0, __shfl_xor_sync(0xffffffffu, m0, o));
        m1 = fmaxf(m1, __shfl_xor_sync(0xffffffffu, m1, o));
        m2 = fmaxf(m2, __shfl_xor_sync(0xffffffffu, m2, o));
    }

    /* pass 2: sum exp */
    float z0 = 0.f, z1 = 0.f, z2 = 0.f;
    for (int base = 0; base < tot; base += 32) {
        int i = base + lane;
        if (i < tot) {
            int src = (i < deg) ? g_adj[off0 + i] : n;
            const float* as = &g_as[(src * NREL + r) * HEADS];
            z0 += expf(lrelu(as[0] + ad0) - m0);
            z1 += expf(lrelu(as[1] + ad1) - m1);
            z2 += expf(lrelu(as[2] + ad2) - m2);
        }
    }
#pragma unroll
    for (int o = 16; o > 0; o >>= 1) {
        z0 += __shfl_xor_sync(0xffffffffu, z0, o);
        z1 += __shfl_xor_sync(0xffffffffu, z1, o);
        z2 += __shfl_xor_sync(0xffffffffu, z2, o);
    }
    const float iv0 = 1.f / (z0 + 1e-16f);
    const float iv1 = 1.f / (z1 + 1e-16f);
    const float iv2 = 1.f / (z2 + 1e-16f);

    /* pass 3: chunked alpha + weighted gather-accumulate */
    float acc[12];
#pragma unroll
    for (int k = 0; k < 12; k++) acc[k] = 0.f;

    for (int c0 = 0; c0 < tot; c0 += ACAP) {
        const int clen = min(ACAP, tot - c0);
        for (int base = 0; base < clen; base += 32) {
            int i = base + lane;
            if (i < clen) {
                int gi  = c0 + i;
                int src = (gi < deg) ? g_adj[off0 + gi] : n;
                sbuf[w][i] = src;
                const float* as = &g_as[(src * NREL + r) * HEADS];
                pbuf[w][i][0] = expf(lrelu(as[0] + ad0) - m0) * iv0;
                pbuf[w][i][1] = expf(lrelu(as[1] + ad1) - m1) * iv1;
                pbuf[w][i][2] = expf(lrelu(as[2] + ad2) - m2) * iv2;
            }
        }
        __syncwarp();
        for (int j = 0; j < clen; j++) {
            const int   src = sbuf[w][j];
            const float a0  = pbuf[w][j][0];
            const float a1  = pbuf[w][j][1];
            const float a2  = pbuf[w][j][2];
            const float* xr = &g_xp[(size_t)src * XPC + r * HC];
#pragma unroll
            for (int k = 0; k < 12; k++) {
                float al = (k < 4) ? a0 : ((k < 8) ? a1 : a2);
                acc[k] = fmaf(al, xr[lane + 32 * k], acc[k]);
            }
        }
        __syncwarp();
    }

    /* epilogue: +bias, relu, store node-major [n][r][hc] */
    const float* bp = &gat_bias[r * HC];
    float* op = &g_gout[((size_t)n * NREL + r) * HC];
#pragma unroll
    for (int k = 0; k < 12; k++) {
        int c = lane + 32 * k;
        op[c] = fmaxf(acc[k] + bp[c], 0.f);
    }
}

/* ------------------------------------------------------------------ */
/* semantic attention + epilogue: W_sem in smem, 1 block/SM            */
/* ------------------------------------------------------------------ */
#define SEM_SMEM ((HC * SEMD + NREL * HC + 16) * 4) /* 201280 B */

__global__ void sem_kernel(const float* __restrict__ W_sem,
                           const float* __restrict__ b_sem,
                           const float* __restrict__ q_sem,
                           const float* __restrict__ mgx,
                           const float* __restrict__ gsrc,
                           const float* __restrict__ gdst,
                           float* __restrict__ out)
{
    extern __shared__ float sm[];
    float* Ws   = sm;                      /* [384][128] */
    float* outs = sm + HC * SEMD;          /* [3][384]   */
    float* red  = outs + NREL * HC;        /* [12]       */

    const int tid  = threadIdx.x;          /* 128 threads */
    const int wid  = tid >> 5;
    const int lane = tid & 31;

    /* stage W_sem */
    {
        const float4* wsrc = (const float4*)W_sem;
        float4* wdst = (float4*)Ws;
        for (int i = tid; i < (HC * SEMD) / 4; i += 128) wdst[i] = wsrc[i];
    }
    __syncthreads();

    const float bs = b_sem[tid];
    const float qv = q_sem[tid];

    for (int node = blockIdx.x; node < N_NODES; node += gridDim.x) {
        /* stage this node's out rows */
        const float4* osrc = (const float4*)&g_gout[(size_t)node * XPC];
        float4* odst = (float4*)outs;
        for (int i = tid; i < XPC / 4; i += 128) odst[i] = osrc[i];
        __syncthreads();

        float acc0 = 0.f, acc1 = 0.f, acc2 = 0.f;
        const float4* o4 = (const float4*)outs;
#pragma unroll 4
        for (int d = 0; d < HC; d += 4) {
            float4 v0 = o4[d >> 2];
            float4 v1 = o4[96 + (d >> 2)];
            float4 v2 = o4[192 + (d >> 2)];
            float w0 = Ws[(d + 0) * SEMD + tid];
            float w1 = Ws[(d + 1) * SEMD + tid];
            float w2 = Ws[(d + 2) * SEMD + tid];
            float w3 = Ws[(d + 3) * SEMD + tid];
            acc0 = fmaf(v0.x, w0, acc0); acc0 = fmaf(v0.y, w1, acc0);
            acc0 = fmaf(v0.z, w2, acc0); acc0 = fmaf(v0.w, w3, acc0);
            acc1 = fmaf(v1.x, w0, acc1); acc1 = fmaf(v1.y, w1, acc1);
            acc1 = fmaf(v1.z, w2, acc1); acc1 = fmaf(v1.w, w3, acc1);
            acc2 = fmaf(v2.x, w0, acc2); acc2 = fmaf(v2.y, w1, acc2);
            acc2 = fmaf(v2.z, w2, acc2); acc2 = fmaf(v2.w, w3, acc2);
        }

        float s0 = tanhf(acc0 + bs) * qv;
        float s1 = tanhf(acc1 + bs) * qv;
        float s2 = tanhf(acc2 + bs) * qv;
#pragma unroll
        for (int o = 16; o > 0; o >>= 1) {
            s0 += __shfl_xor_sync(0xffffffffu, s0, o);
            s1 += __shfl_xor_sync(0xffffffffu, s1, o);
            s2 += __shfl_xor_sync(0xffffffffu, s2, o);
        }
        if (lane == 0) {
            red[wid * 3 + 0] = s0;
            red[wid * 3 + 1] = s1;
            red[wid * 3 + 2] = s2;
        }
        __syncthreads();
        float S0 = red[0] + red[3] + red[6] + red[9];
        float S1 = red[1] + red[4] + red[7] + red[10];
        float S2 = red[2] + red[5] + red[8] + red[11];

        float bm = fmaxf(S0, fmaxf(S1, S2));
        float e0 = expf(S0 - bm), e1 = expf(S1 - bm), e2 = expf(S2 - bm);
        float iden = 1.f / (e0 + e1 + e2);
        float b0 = e0 * iden, b1 = e1 * iden, b2 = e2 * iden;

        for (int c = tid; c < HC; c += 128) {
            float v = b0 * outs[c] + b1 * outs[HC + c] + b2 * outs[2 * HC + c];
            out[(size_t)node * HC + c] = v + mgx[c] * (gsrc[c] + gdst[c]);
        }
        __syncthreads();   /* outs reused next node */
    }
}

/* ------------------------------------------------------------------ */
extern "C" void kernel_launch(void* const* d_in, const int* in_sizes, int n_in,
                              void* d_out, int out_size)
{
    const float* x        = (const float*)d_in[0];
    const float* theta    = (const float*)d_in[1];
    const float* att_src  = (const float*)d_in[2];
    const float* att_dst  = (const float*)d_in[3];
    const float* gat_bias = (const float*)d_in[4];
    const float* W_sem    = (const float*)d_in[5];
    const float* b_sem    = (const float*)d_in[6];
    const float* q_sem    = (const float*)d_in[7];
    const float* mgx      = (const float*)d_in[8];
    const float* gsrc     = (const float*)d_in[9];
    const float* gdst     = (const float*)d_in[10];
    const void*  ei       = d_in[11];
    float* out = (float*)d_out;

    /* 0. edge_index dtype detection (int32 vs int64) */
    detect_kernel<<<1, 32>>>((const int*)ei);

    /* 1. xp = x @ theta (all relations) */
    gemm1_kernel<<<dim3(XPC / 64, (N_NODES + 127) / 128), 256>>>(x, theta);

    /* 2. attention logit components */
    asd_kernel<<<(N_NODES * NREL * HEADS + 3) / 4, 128>>>(att_src, att_dst);

    /* 3. CSR build (group edges by dst) */
    zero_deg_kernel<<<(RN + 255) / 256, 256>>>();
    count_kernel<<<(TOTE + 255) / 256, 256>>>(ei);
    scan1_kernel<<<(RN + SCH - 1) / SCH, 256>>>();
    scan2_kernel<<<1, 256>>>((RN + SCH - 1) / SCH);
    scan3_kernel<<<(RN + 255) / 256, 256>>>();
    fill_kernel<<<(TOTE + 255) / 256, 256>>>(ei);

    /* 4. per-(relation,node) GAT softmax + aggregate */
    agg_kernel<<<RN / 4, 128>>>(gat_bias);

    /* 5. semantic attention + final epilogue */
    cudaFuncSetAttribute(sem_kernel,
                         cudaFuncAttributeMaxDynamicSharedMemorySize, SEM_SMEM);
    sem_kernel<<<148, 128, SEM_SMEM>>>(W_sem, b_sem, q_sem, mgx, gsrc, gdst, out);
}

// round 7
// speedup vs baseline: 1.3335x; 1.3335x over previous
#include <cuda_runtime.h>
#include <math.h>

#define N_NODES 50000
#define IN_CH   256
#define HEADS   3
#define OUT_C   128
#define HC      384
#define NREL    3
#define NEDGE   400000
#define SEMD    128
#define RN      (NREL * N_NODES)     /* 150000 */
#define TOTE    (NREL * NEDGE)       /* 1200000 */
#define XPC     (NREL * HC)          /* 1152 */

/* ------------------------------------------------------------------ */
/* scratch (static device globals — no runtime allocation)             */
/* ------------------------------------------------------------------ */
__device__ float g_xp  [(size_t)N_NODES * XPC];   /* x @ theta, [N][R*HC] */
__device__ float g_gout[(size_t)N_NODES * XPC];   /* relu(gat+bias), [N][R][HC] */
__device__ float g_as  [N_NODES * NREL * HEADS];
__device__ float g_ad  [N_NODES * NREL * HEADS];
__device__ int   g_deg [RN];
__device__ int   g_off [RN + 1];
__device__ int   g_cur [RN];
__device__ int   g_adj [TOTE];
__device__ int   g_part[256];
__device__ int   g_is64;

/* ------------------------------------------------------------------ */
/* edge_index dtype detection (JAX x64-disabled => int32)              */
/* ------------------------------------------------------------------ */
__global__ void detect_kernel(const int* __restrict__ ei32)
{
    if (threadIdx.x == 0) {
        int is64 = 1;
        for (int i = 1; i < 128; i += 2)
            if (ei32[i] != 0) { is64 = 0; break; }
        g_is64 = is64;
    }
}

__device__ __forceinline__ int load_idx(const void* ei, int is64, size_t pos)
{
    int v = is64 ? (int)((const long long*)ei)[pos]
                 : ((const int*)ei)[pos];
    if ((unsigned)v >= (unsigned)N_NODES) v = 0;
    return v;
}

/* ------------------------------------------------------------------ */
/* GEMM1: g_xp[m][j] = sum_k x[m][k] * theta[r][k][hc],  j = r*384+hc  */
/* 128x128 tile, 8x8 micro-tile, 256 threads, double-buffered smem     */
/* ------------------------------------------------------------------ */
__global__ __launch_bounds__(256, 2)
void gemm1_kernel(const float* __restrict__ x,
                  const float* __restrict__ theta)
{
    __shared__ float As[2][8][128];
    __shared__ float Bs[2][8][128];

    const int tid  = threadIdx.x;
    const int tx   = tid & 15;        /* col group: cols tx*4 and 64+tx*4 */
    const int ty   = tid >> 4;        /* row group: rows ty*8 .. ty*8+7   */
    const int row0 = blockIdx.y * 128;
    const int col0 = blockIdx.x * 128;
    const int rsel = col0 / HC;       /* 384 % 128 == 0: no straddle      */
    const int hc0  = col0 % HC;
    const float* B = theta + (size_t)rsel * IN_CH * HC;

    float acc[8][8];
#pragma unroll
    for (int i = 0; i < 8; i++)
#pragma unroll
        for (int j = 0; j < 8; j++) acc[i][j] = 0.f;

    /* load lanes: A 128 rows x 8k (2 threads per row), B 8k x 128 cols */
    const int la_r = tid >> 1;
    const int la_k = (tid & 1) * 4;
    const int lb_k = tid >> 5;
    const int lb_c = (tid & 31) * 4;

    const int arow = row0 + la_r;
    float4 av, bv;

    /* prologue: stage k0 = 0 into buffer 0 */
    av = (arow < N_NODES) ? *(const float4*)&x[(size_t)arow * IN_CH + la_k]
                          : make_float4(0.f, 0.f, 0.f, 0.f);
    bv = *(const float4*)&B[(size_t)lb_k * HC + hc0 + lb_c];
    As[0][la_k + 0][la_r] = av.x;
    As[0][la_k + 1][la_r] = av.y;
    As[0][la_k + 2][la_r] = av.z;
    As[0][la_k + 3][la_r] = av.w;
    *(float4*)&Bs[0][lb_k][lb_c] = bv;
    __syncthreads();

    int buf = 0;
    for (int k0 = 0; k0 < IN_CH; k0 += 8) {
        const int has_next = (k0 + 8 < IN_CH);
        if (has_next) {
            av = (arow < N_NODES)
               ? *(const float4*)&x[(size_t)arow * IN_CH + k0 + 8 + la_k]
               : make_float4(0.f, 0.f, 0.f, 0.f);
            bv = *(const float4*)&B[(size_t)(k0 + 8 + lb_k) * HC + hc0 + lb_c];
        }

#pragma unroll
        for (int kk = 0; kk < 8; kk++) {
            float a[8], b[8];
            *(float4*)&a[0] = *(float4*)&As[buf][kk][ty * 8];
            *(float4*)&a[4] = *(float4*)&As[buf][kk][ty * 8 + 4];
            *(float4*)&b[0] = *(float4*)&Bs[buf][kk][tx * 4];
            *(float4*)&b[4] = *(float4*)&Bs[buf][kk][tx * 4 + 64];
#pragma unroll
            for (int i = 0; i < 8; i++)
#pragma unroll
                for (int j = 0; j < 8; j++)
                    acc[i][j] = fmaf(a[i], b[j], acc[i][j]);
        }

        if (has_next) {
            const int nb = buf ^ 1;
            As[nb][la_k + 0][la_r] = av.x;
            As[nb][la_k + 1][la_r] = av.y;
            As[nb][la_k + 2][la_r] = av.z;
            As[nb][la_k + 3][la_r] = av.w;
            *(float4*)&Bs[nb][lb_k][lb_c] = bv;
            __syncthreads();
            buf = nb;
        }
    }

#pragma unroll
    for (int i = 0; i < 8; i++) {
        const int m = row0 + ty * 8 + i;
        if (m < N_NODES) {
            float4 v0 = make_float4(acc[i][0], acc[i][1], acc[i][2], acc[i][3]);
            float4 v1 = make_float4(acc[i][4], acc[i][5], acc[i][6], acc[i][7]);
            *(float4*)&g_xp[(size_t)m * XPC + col0 + tx * 4]      = v0;
            *(float4*)&g_xp[(size_t)m * XPC + col0 + tx * 4 + 64] = v1;
        }
    }
}

/* ------------------------------------------------------------------ */
/* per-node attention logits: a_s/a_d[n][r][h] = sum_c xp*att          */
/* ------------------------------------------------------------------ */
__global__ void asd_kernel(const float* __restrict__ att_src,
                           const float* __restrict__ att_dst)
{
    const int wid  = threadIdx.x >> 5;
    const int lane = threadIdx.x & 31;
    const int item = blockIdx.x * 4 + wid;
    if (item >= N_NODES * NREL * HEADS) return;
    const int n  = item / (NREL * HEADS);
    const int rh = item % (NREL * HEADS);
    const int r  = rh / HEADS;
    const int h  = rh % HEADS;

    const float4 xv = *(const float4*)&g_xp[(size_t)n * XPC + r * HC + h * OUT_C + lane * 4];
    const float4 sv = *(const float4*)&att_src[(size_t)(r * HEADS + h) * OUT_C + lane * 4];
    const float4 dv = *(const float4*)&att_dst[(size_t)(r * HEADS + h) * OUT_C + lane * 4];

    float ds = xv.x * sv.x + xv.y * sv.y + xv.z * sv.z + xv.w * sv.w;
    float dd = xv.x * dv.x + xv.y * dv.y + xv.z * dv.z + xv.w * dv.w;
#pragma unroll
    for (int o = 16; o > 0; o >>= 1) {
        ds += __shfl_xor_sync(0xffffffffu, ds, o);
        dd += __shfl_xor_sync(0xffffffffu, dd, o);
    }
    if (lane == 0) {
        g_as[item] = ds;
        g_ad[item] = dd;
    }
}

/* ------------------------------------------------------------------ */
/* CSR build                                                           */
/* ------------------------------------------------------------------ */
__global__ void zero_deg_kernel()
{
    int i = blockIdx.x * blockDim.x + threadIdx.x;
    if (i < RN) g_deg[i] = 0;
}

__global__ void count_kernel(const void* __restrict__ ei)
{
    int i = blockIdx.x * blockDim.x + threadIdx.x;
    if (i >= TOTE) return;
    const int is64 = g_is64;
    int r = i / NEDGE;
    int e = i % NEDGE;
    int dst = load_idx(ei, is64, (size_t)r * 2 * NEDGE + NEDGE + e);
    atomicAdd(&g_deg[r * N_NODES + dst], 1);
}

#define SCH 1024
__global__ void scan1_kernel()
{
    __shared__ int s[256];
    const int b = blockIdx.x, t = threadIdx.x;
    const int base = b * SCH + t * 4;
    int v[4], sum = 0;
#pragma unroll
    for (int i = 0; i < 4; i++) {
        int idx = base + i;
        v[i] = (idx < RN) ? g_deg[idx] : 0;
        sum += v[i];
    }
    s[t] = sum;
    __syncthreads();
    for (int o = 1; o < 256; o <<= 1) {
        int xv = (t >= o) ? s[t - o] : 0;
        __syncthreads();
        s[t] += xv;
        __syncthreads();
    }
    int run = s[t] - sum;
    if (t == 255) g_part[b] = s[t];
#pragma unroll
    for (int i = 0; i < 4; i++) {
        int idx = base + i;
        if (idx < RN) g_off[idx] = run;
        run += v[i];
    }
}

__global__ void scan2_kernel(int nb)
{
    __shared__ int s[256];
    const int t = threadIdx.x;
    int v = (t < nb) ? g_part[t] : 0;
    s[t] = v;
    __syncthreads();
    for (int o = 1; o < 256; o <<= 1) {
        int xv = (t >= o) ? s[t - o] : 0;
        __syncthreads();
        s[t] += xv;
        __syncthreads();
    }
    g_part[t] = s[t] - v;
}

__global__ void scan3_kernel()
{
    int i = blockIdx.x * blockDim.x + threadIdx.x;
    if (i < RN) {
        int v = g_off[i] + g_part[i / SCH];
        g_off[i] = v;
        g_cur[i] = v;
    }
    if (i == 0) g_off[RN] = TOTE;
}

__global__ void fill_kernel(const void* __restrict__ ei)
{
    int i = blockIdx.x * blockDim.x + threadIdx.x;
    if (i >= TOTE) return;
    const int is64 = g_is64;
    int r = i / NEDGE;
    int e = i % NEDGE;
    int src = load_idx(ei, is64, (size_t)r * 2 * NEDGE + e);
    int dst = load_idx(ei, is64, (size_t)r * 2 * NEDGE + NEDGE + e);
    int pos = atomicAdd(&g_cur[r * N_NODES + dst], 1);
    if (pos >= 0 && pos < TOTE) g_adj[pos] = src;
}

/* ------------------------------------------------------------------ */
/* GAT aggregation: one warp per (r,n)                                 */
/* ------------------------------------------------------------------ */
#define ACAP 64
__device__ __forceinline__ float lrelu(float v) { return v > 0.f ? v : 0.2f * v; }

__global__ void agg_kernel(const float* __restrict__ gat_bias)
{
    __shared__ float pbuf[4][ACAP][3];
    __shared__ int   sbuf[4][ACAP];

    const int w    = threadIdx.x >> 5;
    const int lane = threadIdx.x & 31;
    const int item = blockIdx.x * 4 + w;
    if (item >= RN) return;
    const int r = item / N_NODES;
    const int n = item % N_NODES;

    const int off0 = g_off[r * N_NODES + n];
    const int deg  = g_off[r * N_NODES + n + 1] - off0;
    const int tot  = deg + 1;

    const float ad0 = g_ad[(n * NREL + r) * HEADS + 0];
    const float ad1 = g_ad[(n * NREL + r) * HEADS + 1];
    const float ad2 = g_ad[(n * NREL + r) * HEADS + 2];

    float m0 = -1e30f, m1 = -1e30f, m2 = -1e30f;
    for (int base = 0; base < tot; base += 32) {
        int i = base + lane;
        if (i < tot) {
            int src = (i < deg) ? g_adj[off0 + i] : n;
            const float* as = &g_as[(src * NREL + r) * HEADS];
            m0 = fmaxf(m0, lrelu(as[0] + ad0));
            m1 = fmaxf(m1, lrelu(as[1] + ad1));
            m2 = fmaxf(m2, lrelu(as[2] + ad2));
        }
    }
#pragma unroll
    for (int o = 16; o > 0; o >>= 1) {
        m0 = fmaxf(m0, __shfl_xor_sync(0xffffffffu, m0, o));
        m1 = fmaxf(m1, __shfl_xor_sync(0xffffffffu, m1, o));
        m2 = fmaxf(m2, __shfl_xor_sync(0xffffffffu, m2, o));
    }

    float z0 = 0.f, z1 = 0.f, z2 = 0.f;
    for (int base = 0; base < tot; base += 32) {
        int i = base + lane;
        if (i < tot) {
            int src = (i < deg) ? g_adj[off0 + i] : n;
            const float* as = &g_as[(src * NREL + r) * HEADS];
            z0 += expf(lrelu(as[0] + ad0) - m0);
            z1 += expf(lrelu(as[1] + ad1) - m1);
            z2 += expf(lrelu(as[2] + ad2) - m2);
        }
    }
#pragma unroll
    for (int o = 16; o > 0; o >>= 1) {
        z0 += __shfl_xor_sync(0xffffffffu, z0, o);
        z1 += __shfl_xor_sync(0xffffffffu, z1, o);
        z2 += __shfl_xor_sync(0xffffffffu, z2, o);
    }
    const float iv0 = 1.f / (z0 + 1e-16f);
    const float iv1 = 1.f / (z1 + 1e-16f);
    const float iv2 = 1.f / (z2 + 1e-16f);

    float acc[12];
#pragma unroll
    for (int k = 0; k < 12; k++) acc[k] = 0.f;

    for (int c0 = 0; c0 < tot; c0 += ACAP) {
        const int clen = min(ACAP, tot - c0);
        for (int base = 0; base < clen; base += 32) {
            int i = base + lane;
            if (i < clen) {
                int gi  = c0 + i;
                int src = (gi < deg) ? g_adj[off0 + gi] : n;
                sbuf[w][i] = src;
                const float* as = &g_as[(src * NREL + r) * HEADS];
                pbuf[w][i][0] = expf(lrelu(as[0] + ad0) - m0) * iv0;
                pbuf[w][i][1] = expf(lrelu(as[1] + ad1) - m1) * iv1;
                pbuf[w][i][2] = expf(lrelu(as[2] + ad2) - m2) * iv2;
            }
        }
        __syncwarp();
        for (int j = 0; j < clen; j++) {
            const int   src = sbuf[w][j];
            const float a0  = pbuf[w][j][0];
            const float a1  = pbuf[w][j][1];
            const float a2  = pbuf[w][j][2];
            const float* xr = &g_xp[(size_t)src * XPC + r * HC];
#pragma unroll
            for (int k = 0; k < 12; k++) {
                float al = (k < 4) ? a0 : ((k < 8) ? a1 : a2);
                acc[k] = fmaf(al, xr[lane + 32 * k], acc[k]);
            }
        }
        __syncwarp();
    }

    const float* bp = &gat_bias[r * HC];
    float* op = &g_gout[((size_t)n * NREL + r) * HC];
#pragma unroll
    for (int k = 0; k < 12; k++) {
        int c = lane + 32 * k;
        op[c] = fmaxf(acc[k] + bp[c], 0.f);
    }
}

/* ------------------------------------------------------------------ */
/* semantic attention + epilogue: W_sem in smem, 2 nodes per block     */
/* iteration (256 threads = 2 groups of 128), 1 block/SM               */
/* ------------------------------------------------------------------ */
#define SEM_SMEM ((HC * SEMD + 2 * XPC + 32) * 4)

__global__ __launch_bounds__(256, 1)
void sem_kernel(const float* __restrict__ W_sem,
                const float* __restrict__ b_sem,
                const float* __restrict__ q_sem,
                const float* __restrict__ mgx,
                const float* __restrict__ gsrc,
                const float* __restrict__ gdst,
                float* __restrict__ out)
{
    extern __shared__ float sm[];
    float* Ws   = sm;                       /* [384][128]   */
    float* outs = sm + HC * SEMD;           /* [2][3][384]  */
    float* red  = outs + 2 * XPC;           /* [2][12]      */

    const int tid  = threadIdx.x;           /* 256 threads  */
    const int g    = tid >> 7;              /* group 0/1    */
    const int t2   = tid & 127;             /* 0..127       */
    const int wid  = t2 >> 5;
    const int lane = t2 & 31;

    float* gouts = outs + g * XPC;
    float* gred  = red + g * 12;

    /* stage W_sem */
    {
        const float4* wsrc = (const float4*)W_sem;
        float4* wdst = (float4*)Ws;
        for (int i = tid; i < (HC * SEMD) / 4; i += 256) wdst[i] = wsrc[i];
    }
    __syncthreads();

    const float bs = b_sem[t2];
    const float qv = q_sem[t2];

    for (int base = blockIdx.x * 2; base < N_NODES; base += gridDim.x * 2) {
        const int node = base + g;          /* N_NODES even: always valid */

        /* stage this node's 3 relation rows */
        const float4* osrc = (const float4*)&g_gout[(size_t)node * XPC];
        float4* odst = (float4*)gouts;
        for (int i = t2; i < XPC / 4; i += 128) odst[i] = osrc[i];
        __syncthreads();

        float acc0 = 0.f, acc1 = 0.f, acc2 = 0.f;
        const float4* o4 = (const float4*)gouts;
#pragma unroll 4
        for (int d = 0; d < HC; d += 4) {
            float4 v0 = o4[d >> 2];
            float4 v1 = o4[96 + (d >> 2)];
            float4 v2 = o4[192 + (d >> 2)];
            float w0 = Ws[(d + 0) * SEMD + t2];
            float w1 = Ws[(d + 1) * SEMD + t2];
            float w2 = Ws[(d + 2) * SEMD + t2];
            float w3 = Ws[(d + 3) * SEMD + t2];
            acc0 = fmaf(v0.x, w0, acc0); acc0 = fmaf(v0.y, w1, acc0);
            acc0 = fmaf(v0.z, w2, acc0); acc0 = fmaf(v0.w, w3, acc0);
            acc1 = fmaf(v1.x, w0, acc1); acc1 = fmaf(v1.y, w1, acc1);
            acc1 = fmaf(v1.z, w2, acc1); acc1 = fmaf(v1.w, w3, acc1);
            acc2 = fmaf(v2.x, w0, acc2); acc2 = fmaf(v2.y, w1, acc2);
            acc2 = fmaf(v2.z, w2, acc2); acc2 = fmaf(v2.w, w3, acc2);
        }

        float s0 = tanhf(acc0 + bs) * qv;
        float s1 = tanhf(acc1 + bs) * qv;
        float s2 = tanhf(acc2 + bs) * qv;
#pragma unroll
        for (int o = 16; o > 0; o >>= 1) {
            s0 += __shfl_xor_sync(0xffffffffu, s0, o);
            s1 += __shfl_xor_sync(0xffffffffu, s1, o);
            s2 += __shfl_xor_sync(0xffffffffu, s2, o);
        }
        if (lane == 0) {
            gred[wid * 3 + 0] = s0;
            gred[wid * 3 + 1] = s1;
            gred[wid * 3 + 2] = s2;
        }
        __syncthreads();
        float S0 = gred[0] + gred[3] + gred[6] + gred[9];
        float S1 = gred[1] + gred[4] + gred[7] + gred[10];
        float S2 = gred[2] + gred[5] + gred[8] + gred[11];

        float bm = fmaxf(S0, fmaxf(S1, S2));
        float e0 = expf(S0 - bm), e1 = expf(S1 - bm), e2 = expf(S2 - bm);
        float iden = 1.f / (e0 + e1 + e2);
        float b0 = e0 * iden, b1 = e1 * iden, b2 = e2 * iden;

        for (int c = t2; c < HC; c += 128) {
            float v = b0 * gouts[c] + b1 * gouts[HC + c] + b2 * gouts[2 * HC + c];
            out[(size_t)node * HC + c] = v + mgx[c] * (gsrc[c] + gdst[c]);
        }
        __syncthreads();   /* outs reused next iteration */
    }
}

/* ------------------------------------------------------------------ */
extern "C" void kernel_launch(void* const* d_in, const int* in_sizes, int n_in,
                              void* d_out, int out_size)
{
    const float* x        = (const float*)d_in[0];
    const float* theta    = (const float*)d_in[1];
    const float* att_src  = (const float*)d_in[2];
    const float* att_dst  = (const float*)d_in[3];
    const float* gat_bias = (const float*)d_in[4];
    const float* W_sem    = (const float*)d_in[5];
    const float* b_sem    = (const float*)d_in[6];
    const float* q_sem    = (const float*)d_in[7];
    const float* mgx      = (const float*)d_in[8];
    const float* gsrc     = (const float*)d_in[9];
    const float* gdst     = (const float*)d_in[10];
    const void*  ei       = d_in[11];
    float* out = (float*)d_out;

    /* 0. edge_index dtype detection (int32 vs int64) */
    detect_kernel<<<1, 32>>>((const int*)ei);

    /* 1. xp = x @ theta (all relations) */
    gemm1_kernel<<<dim3(XPC / 128, (N_NODES + 127) / 128), 256>>>(x, theta);

    /* 2. attention logit components */
    asd_kernel<<<(N_NODES * NREL * HEADS + 3) / 4, 128>>>(att_src, att_dst);

    /* 3. CSR build (group edges by dst) */
    zero_deg_kernel<<<(RN + 255) / 256, 256>>>();
    count_kernel<<<(TOTE + 255) / 256, 256>>>(ei);
    scan1_kernel<<<(RN + SCH - 1) / SCH, 256>>>();
    scan2_kernel<<<1, 256>>>((RN + SCH - 1) / SCH);
    scan3_kernel<<<(RN + 255) / 256, 256>>>();
    fill_kernel<<<(TOTE + 255) / 256, 256>>>(ei);

    /* 4. per-(relation,node) GAT softmax + aggregate */
    agg_kernel<<<RN / 4, 128>>>(gat_bias);

    /* 5. semantic attention + final epilogue (2 nodes / block iter) */
    cudaFuncSetAttribute(sem_kernel,
                         cudaFuncAttributeMaxDynamicSharedMemorySize, SEM_SMEM);
    sem_kernel<<<148, 256, SEM_SMEM>>>(W_sem, b_sem, q_sem, mgx, gsrc, gdst, out);
}

// round 9
// speedup vs baseline: 2.2420x; 1.6814x over previous
#include <cuda_runtime.h>
#include <cuda_bf16.h>
#include <math.h>
#include <stdint.h>

#define N_NODES 50000
#define IN_CH   256
#define HEADS   3
#define OUT_C   128
#define HC      384
#define NREL    3
#define NEDGE   400000
#define SEMD    128
#define RN      (NREL * N_NODES)     /* 150000 */
#define TOTE    (NREL * NEDGE)       /* 1200000 */
#define XPC     (NREL * HC)          /* 1152 */

/* ------------------------------------------------------------------ */
/* scratch (static device globals — no runtime allocation)             */
/* ------------------------------------------------------------------ */
__device__ float g_xp  [(size_t)N_NODES * XPC];   /* x @ theta, [N][R*HC] */
__device__ float g_gout[(size_t)N_NODES * XPC];   /* relu(gat+bias), [N][R][HC] */
__device__ float g_as  [N_NODES * NREL * HEADS];
__device__ float g_ad  [N_NODES * NREL * HEADS];
__device__ int   g_deg [RN];
__device__ int   g_off [RN + 1];
__device__ int   g_cur [RN];
__device__ int   g_adj [TOTE];
__device__ int   g_part[256];
__device__ int   g_is64;

/* bf16 split operands for tensor-core GEMM1 */
__device__ __nv_bfloat16 g_xh[(size_t)N_NODES * IN_CH];
__device__ __nv_bfloat16 g_xl[(size_t)N_NODES * IN_CH];
__device__ __nv_bfloat16 g_th[(size_t)XPC * IN_CH];   /* theta^T [j][k] hi */
__device__ __nv_bfloat16 g_tl[(size_t)XPC * IN_CH];   /* theta^T [j][k] lo */

/* ------------------------------------------------------------------ */
/* edge_index dtype detection (JAX x64-disabled => int32)              */
/* ------------------------------------------------------------------ */
__global__ void detect_kernel(const int* __restrict__ ei32)
{
    if (threadIdx.x == 0) {
        int is64 = 1;
        for (int i = 1; i < 128; i += 2)
            if (ei32[i] != 0) { is64 = 0; break; }
        g_is64 = is64;
    }
}

__device__ __forceinline__ int load_idx(const void* ei, int is64, size_t pos)
{
    int v = is64 ? (int)((const long long*)ei)[pos]
                 : ((const int*)ei)[pos];
    if ((unsigned)v >= (unsigned)N_NODES) v = 0;
    return v;
}

/* ------------------------------------------------------------------ */
/* bf16 split preprocessing                                            */
/* ------------------------------------------------------------------ */
__global__ void split_x_kernel(const float* __restrict__ x)
{
    int i = blockIdx.x * blockDim.x + threadIdx.x;
    if (i >= N_NODES * IN_CH) return;
    float v = x[i];
    __nv_bfloat16 h = __float2bfloat16(v);
    g_xh[i] = h;
    g_xl[i] = __float2bfloat16(v - __bfloat162float(h));
}

__global__ void split_theta_kernel(const float* __restrict__ theta)
{
    int i = blockIdx.x * blockDim.x + threadIdx.x;
    if (i >= XPC * IN_CH) return;
    int j = i / IN_CH;          /* output col 0..1151 */
    int k = i % IN_CH;
    int r  = j / HC;
    int hc = j % HC;
    float v = theta[((size_t)r * IN_CH + k) * HC + hc];
    __nv_bfloat16 h = __float2bfloat16(v);
    g_th[i] = h;
    g_tl[i] = __float2bfloat16(v - __bfloat162float(h));
}

/* ------------------------------------------------------------------ */
/* GEMM1 via mma.sync bf16 (HMMA): 128x128 block, 8 warps, warp 32x64  */
/* 2-term split: D = Ah*Bh + Ah*Bl + Al*Bh, fp32 accumulators          */
/* ------------------------------------------------------------------ */
#define BK   32
#define LDA  40   /* padded bf16 row stride for smem tiles */

__device__ __forceinline__ void mma16816(float* c, const uint32_t* a,
                                         const uint32_t* b)
{
    asm volatile(
        "mma.sync.aligned.m16n8k16.row.col.f32.bf16.bf16.f32 "
        "{%0,%1,%2,%3}, {%4,%5,%6,%7}, {%8,%9}, {%0,%1,%2,%3};"
        : "+f"(c[0]), "+f"(c[1]), "+f"(c[2]), "+f"(c[3])
        : "r"(a[0]), "r"(a[1]), "r"(a[2]), "r"(a[3]),
          "r"(b[0]), "r"(b[1]));
}

__global__ __launch_bounds__(256, 2)
void gemm1_mma_kernel()
{
    __shared__ __nv_bfloat16 sAh[128][LDA];
    __shared__ __nv_bfloat16 sAl[128][LDA];
    __shared__ __nv_bfloat16 sBh[128][LDA];
    __shared__ __nv_bfloat16 sBl[128][LDA];

    const int tid   = threadIdx.x;
    const int wid   = tid >> 5;
    const int lane  = tid & 31;
    const int wm    = wid & 3;         /* warp row 0..3  -> rows wm*32  */
    const int wn    = wid >> 2;        /* warp col 0..1  -> cols wn*64  */
    const int row0  = blockIdx.y * 128;
    const int col0  = blockIdx.x * 128;

    /* fragment coordinates (m16n8k16 thread mapping) */
    const int qrow = lane >> 2;        /* 0..7  */
    const int qk   = (lane & 3) * 2;   /* 0,2,4,6 */

    float c[2][8][4];
#pragma unroll
    for (int i = 0; i < 2; i++)
#pragma unroll
        for (int j = 0; j < 8; j++)
#pragma unroll
            for (int q = 0; q < 4; q++) c[i][j][q] = 0.f;

    /* staging lanes: each thread loads 8 bf16 (uint4) x2 per array    */
    const int sr = tid >> 1;                 /* 0..127 row               */
    const int sc = (tid & 1) * 16;           /* 0 or 16 (k offset)       */

    for (int kc = 0; kc < IN_CH; kc += BK) {
        __syncthreads();
        {
            const int m = row0 + sr;
            uint4 vh = make_uint4(0u, 0u, 0u, 0u), vl = vh;
            uint4 wh = vh, wl = vh;
            if (m < N_NODES) {
                const size_t gi = ((size_t)m * IN_CH + kc + sc) >> 3;
                vh = ((const uint4*)g_xh)[gi];
                vl = ((const uint4*)g_xl)[gi];
                const size_t gi2 = gi + 1;
                wh = ((const uint4*)g_xh)[gi2];
                wl = ((const uint4*)g_xl)[gi2];
            }
            *(uint4*)&sAh[sr][sc]     = vh;
            *(uint4*)&sAl[sr][sc]     = vl;
            *(uint4*)&sAh[sr][sc + 8] = wh;
            *(uint4*)&sAl[sr][sc + 8] = wl;

            const size_t bgi = ((size_t)(col0 + sr) * IN_CH + kc + sc) >> 3;
            uint4 bh = ((const uint4*)g_th)[bgi];
            uint4 bl = ((const uint4*)g_tl)[bgi];
            uint4 bh2 = ((const uint4*)g_th)[bgi + 1];
            uint4 bl2 = ((const uint4*)g_tl)[bgi + 1];
            *(uint4*)&sBh[sr][sc]     = bh;
            *(uint4*)&sBl[sr][sc]     = bl;
            *(uint4*)&sBh[sr][sc + 8] = bh2;
            *(uint4*)&sBl[sr][sc + 8] = bl2;
        }
        __syncthreads();

#pragma unroll
        for (int ks = 0; ks < BK; ks += 16) {
            /* A fragments: 2 m-tiles, hi and lo */
            uint32_t ah[2][4], al[2][4];
#pragma unroll
            for (int i = 0; i < 2; i++) {
                const int r0 = wm * 32 + i * 16 + qrow;
                ah[i][0] = *(const uint32_t*)&sAh[r0][ks + qk];
                ah[i][1] = *(const uint32_t*)&sAh[r0 + 8][ks + qk];
                ah[i][2] = *(const uint32_t*)&sAh[r0][ks + qk + 8];
                ah[i][3] = *(const uint32_t*)&sAh[r0 + 8][ks + qk + 8];
                al[i][0] = *(const uint32_t*)&sAl[r0][ks + qk];
                al[i][1] = *(const uint32_t*)&sAl[r0 + 8][ks + qk];
                al[i][2] = *(const uint32_t*)&sAl[r0][ks + qk + 8];
                al[i][3] = *(const uint32_t*)&sAl[r0 + 8][ks + qk + 8];
            }
            /* B fragments: 8 n-tiles, hi and lo */
            uint32_t bh[8][2], bl[8][2];
#pragma unroll
            for (int j = 0; j < 8; j++) {
                const int n0 = wn * 64 + j * 8 + qrow;
                bh[j][0] = *(const uint32_t*)&sBh[n0][ks + qk];
                bh[j][1] = *(const uint32_t*)&sBh[n0][ks + qk + 8];
                bl[j][0] = *(const uint32_t*)&sBl[n0][ks + qk];
                bl[j][1] = *(const uint32_t*)&sBl[n0][ks + qk + 8];
            }
#pragma unroll
            for (int i = 0; i < 2; i++)
#pragma unroll
                for (int j = 0; j < 8; j++) {
                    mma16816(c[i][j], ah[i], bh[j]);
                    mma16816(c[i][j], ah[i], bl[j]);
                    mma16816(c[i][j], al[i], bh[j]);
                }
        }
    }

    /* epilogue: c[i][j] quad layout -> g_xp */
    const int crow = lane >> 2;
    const int ccol = (lane & 3) * 2;
#pragma unroll
    for (int i = 0; i < 2; i++) {
        const int mbase = row0 + wm * 32 + i * 16;
#pragma unroll
        for (int j = 0; j < 8; j++) {
            const int nbase = col0 + wn * 64 + j * 8 + ccol;
            const int m0 = mbase + crow;
            const int m1 = m0 + 8;
            if (m0 < N_NODES)
                *(float2*)&g_xp[(size_t)m0 * XPC + nbase] =
                    make_float2(c[i][j][0], c[i][j][1]);
            if (m1 < N_NODES)
                *(float2*)&g_xp[(size_t)m1 * XPC + nbase] =
                    make_float2(c[i][j][2], c[i][j][3]);
        }
    }
}

/* ------------------------------------------------------------------ */
/* per-node attention logits: a_s/a_d[n][r][h] = sum_c xp*att          */
/* ------------------------------------------------------------------ */
__global__ void asd_kernel(const float* __restrict__ att_src,
                           const float* __restrict__ att_dst)
{
    const int wid  = threadIdx.x >> 5;
    const int lane = threadIdx.x & 31;
    const int item = blockIdx.x * 4 + wid;
    if (item >= N_NODES * NREL * HEADS) return;
    const int n  = item / (NREL * HEADS);
    const int rh = item % (NREL * HEADS);
    const int r  = rh / HEADS;
    const int h  = rh % HEADS;

    const float4 xv = *(const float4*)&g_xp[(size_t)n * XPC + r * HC + h * OUT_C + lane * 4];
    const float4 sv = *(const float4*)&att_src[(size_t)(r * HEADS + h) * OUT_C + lane * 4];
    const float4 dv = *(const float4*)&att_dst[(size_t)(r * HEADS + h) * OUT_C + lane * 4];

    float ds = xv.x * sv.x + xv.y * sv.y + xv.z * sv.z + xv.w * sv.w;
    float dd = xv.x * dv.x + xv.y * dv.y + xv.z * dv.z + xv.w * dv.w;
#pragma unroll
    for (int o = 16; o > 0; o >>= 1) {
        ds += __shfl_xor_sync(0xffffffffu, ds, o);
        dd += __shfl_xor_sync(0xffffffffu, dd, o);
    }
    if (lane == 0) {
        g_as[item] = ds;
        g_ad[item] = dd;
    }
}

/* ------------------------------------------------------------------ */
/* CSR build                                                           */
/* ------------------------------------------------------------------ */
__global__ void zero_deg_kernel()
{
    int i = blockIdx.x * blockDim.x + threadIdx.x;
    if (i < RN) g_deg[i] = 0;
}

__global__ void count_kernel(const void* __restrict__ ei)
{
    int i = blockIdx.x * blockDim.x + threadIdx.x;
    if (i >= TOTE) return;
    const int is64 = g_is64;
    int r = i / NEDGE;
    int e = i % NEDGE;
    int dst = load_idx(ei, is64, (size_t)r * 2 * NEDGE + NEDGE + e);
    atomicAdd(&g_deg[r * N_NODES + dst], 1);
}

#define SCH 1024
__global__ void scan1_kernel()
{
    __shared__ int s[256];
    const int b = blockIdx.x, t = threadIdx.x;
    const int base = b * SCH + t * 4;
    int v[4], sum = 0;
#pragma unroll
    for (int i = 0; i < 4; i++) {
        int idx = base + i;
        v[i] = (idx < RN) ? g_deg[idx] : 0;
        sum += v[i];
    }
    s[t] = sum;
    __syncthreads();
    for (int o = 1; o < 256; o <<= 1) {
        int xv = (t >= o) ? s[t - o] : 0;
        __syncthreads();
        s[t] += xv;
        __syncthreads();
    }
    int run = s[t] - sum;
    if (t == 255) g_part[b] = s[t];
#pragma unroll
    for (int i = 0; i < 4; i++) {
        int idx = base + i;
        if (idx < RN) g_off[idx] = run;
        run += v[i];
    }
}

__global__ void scan2_kernel(int nb)
{
    __shared__ int s[256];
    const int t = threadIdx.x;
    int v = (t < nb) ? g_part[t] : 0;
    s[t] = v;
    __syncthreads();
    for (int o = 1; o < 256; o <<= 1) {
        int xv = (t >= o) ? s[t - o] : 0;
        __syncthreads();
        s[t] += xv;
        __syncthreads();
    }
    g_part[t] = s[t] - v;
}

__global__ void scan3_kernel()
{
    int i = blockIdx.x * blockDim.x + threadIdx.x;
    if (i < RN) {
        int v = g_off[i] + g_part[i / SCH];
        g_off[i] = v;
        g_cur[i] = v;
    }
    if (i == 0) g_off[RN] = TOTE;
}

__global__ void fill_kernel(const void* __restrict__ ei)
{
    int i = blockIdx.x * blockDim.x + threadIdx.x;
    if (i >= TOTE) return;
    const int is64 = g_is64;
    int r = i / NEDGE;
    int e = i % NEDGE;
    int src = load_idx(ei, is64, (size_t)r * 2 * NEDGE + e);
    int dst = load_idx(ei, is64, (size_t)r * 2 * NEDGE + NEDGE + e);
    int pos = atomicAdd(&g_cur[r * N_NODES + dst], 1);
    if (pos >= 0 && pos < TOTE) g_adj[pos] = src;
}

/* ------------------------------------------------------------------ */
/* GAT aggregation: one warp per (r,n)                                 */
/* ------------------------------------------------------------------ */
#define ACAP 64
__device__ __forceinline__ float lrelu(float v) { return v > 0.f ? v : 0.2f * v; }

__global__ void agg_kernel(const float* __restrict__ gat_bias)
{
    __shared__ float pbuf[4][ACAP][3];
    __shared__ int   sbuf[4][ACAP];

    const int w    = threadIdx.x >> 5;
    const int lane = threadIdx.x & 31;
    const int item = blockIdx.x * 4 + w;
    if (item >= RN) return;
    const int r = item / N_NODES;
    const int n = item % N_NODES;

    const int off0 = g_off[r * N_NODES + n];
    const int deg  = g_off[r * N_NODES + n + 1] - off0;
    const int tot  = deg + 1;

    const float ad0 = g_ad[(n * NREL + r) * HEADS + 0];
    const float ad1 = g_ad[(n * NREL + r) * HEADS + 1];
    const float ad2 = g_ad[(n * NREL + r) * HEADS + 2];

    float m0 = -1e30f, m1 = -1e30f, m2 = -1e30f;
    for (int base = 0; base < tot; base += 32) {
        int i = base + lane;
        if (i < tot) {
            int src = (i < deg) ? g_adj[off0 + i] : n;
            const float* as = &g_as[(src * NREL + r) * HEADS];
            m0 = fmaxf(m0, lrelu(as[0] + ad0));
            m1 = fmaxf(m1, lrelu(as[1] + ad1));
            m2 = fmaxf(m2, lrelu(as[2] + ad2));
        }
    }
#pragma unroll
    for (int o = 16; o > 0; o >>= 1) {
        m0 = fmaxf(m0, __shfl_xor_sync(0xffffffffu, m0, o));
        m1 = fmaxf(m1, __shfl_xor_sync(0xffffffffu, m1, o));
        m2 = fmaxf(m2, __shfl_xor_sync(0xffffffffu, m2, o));
    }

    float z0 = 0.f, z1 = 0.f, z2 = 0.f;
    for (int base = 0; base < tot; base += 32) {
        int i = base + lane;
        if (i < tot) {
            int src = (i < deg) ? g_adj[off0 + i] : n;
            const float* as = &g_as[(src * NREL + r) * HEADS];
            z0 += expf(lrelu(as[0] + ad0) - m0);
            z1 += expf(lrelu(as[1] + ad1) - m1);
            z2 += expf(lrelu(as[2] + ad2) - m2);
        }
    }
#pragma unroll
    for (int o = 16; o > 0; o >>= 1) {
        z0 += __shfl_xor_sync(0xffffffffu, z0, o);
        z1 += __shfl_xor_sync(0xffffffffu, z1, o);
        z2 += __shfl_xor_sync(0xffffffffu, z2, o);
    }
    const float iv0 = 1.f / (z0 + 1e-16f);
    const float iv1 = 1.f / (z1 + 1e-16f);
    const float iv2 = 1.f / (z2 + 1e-16f);

    float acc[12];
#pragma unroll
    for (int k = 0; k < 12; k++) acc[k] = 0.f;

    for (int c0 = 0; c0 < tot; c0 += ACAP) {
        const int clen = min(ACAP, tot - c0);
        for (int base = 0; base < clen; base += 32) {
            int i = base + lane;
            if (i < clen) {
                int gi  = c0 + i;
                int src = (gi < deg) ? g_adj[off0 + gi] : n;
                sbuf[w][i] = src;
                const float* as = &g_as[(src * NREL + r) * HEADS];
                pbuf[w][i][0] = expf(lrelu(as[0] + ad0) - m0) * iv0;
                pbuf[w][i][1] = expf(lrelu(as[1] + ad1) - m1) * iv1;
                pbuf[w][i][2] = expf(lrelu(as[2] + ad2) - m2) * iv2;
            }
        }
        __syncwarp();
        for (int j = 0; j < clen; j++) {
            const int   src = sbuf[w][j];
            const float a0  = pbuf[w][j][0];
            const float a1  = pbuf[w][j][1];
            const float a2  = pbuf[w][j][2];
            const float* xr = &g_xp[(size_t)src * XPC + r * HC];
#pragma unroll
            for (int k = 0; k < 12; k++) {
                float al = (k < 4) ? a0 : ((k < 8) ? a1 : a2);
                acc[k] = fmaf(al, xr[lane + 32 * k], acc[k]);
            }
        }
        __syncwarp();
    }

    const float* bp = &gat_bias[r * HC];
    float* op = &g_gout[((size_t)n * NREL + r) * HC];
#pragma unroll
    for (int k = 0; k < 12; k++) {
        int c = lane + 32 * k;
        op[c] = fmaxf(acc[k] + bp[c], 0.f);
    }
}

/* ------------------------------------------------------------------ */
/* semantic attention + epilogue: W_sem in smem, 2 nodes per block     */
/* iteration (256 threads = 2 groups of 128), 1 block/SM               */
/* ------------------------------------------------------------------ */
#define SEM_SMEM ((HC * SEMD + 2 * XPC + 32) * 4)

__global__ __launch_bounds__(256, 1)
void sem_kernel(const float* __restrict__ W_sem,
                const float* __restrict__ b_sem,
                const float* __restrict__ q_sem,
                const float* __restrict__ mgx,
                const float* __restrict__ gsrc,
                const float* __restrict__ gdst,
                float* __restrict__ out)
{
    extern __shared__ float smf[];
    float* Ws   = smf;                      /* [384][128]   */
    float* outs = smf + HC * SEMD;          /* [2][3][384]  */
    float* red  = outs + 2 * XPC;           /* [2][12]      */

    const int tid  = threadIdx.x;           /* 256 threads  */
    const int g    = tid >> 7;              /* group 0/1    */
    const int t2   = tid & 127;             /* 0..127       */
    const int wid  = t2 >> 5;
    const int lane = t2 & 31;

    float* gouts = outs + g * XPC;
    float* gred  = red + g * 12;

    {
        const float4* wsrc = (const float4*)W_sem;
        float4* wdst = (float4*)Ws;
        for (int i = tid; i < (HC * SEMD) / 4; i += 256) wdst[i] = wsrc[i];
    }
    __syncthreads();

    const float bs = b_sem[t2];
    const float qv = q_sem[t2];

    for (int base = blockIdx.x * 2; base < N_NODES; base += gridDim.x * 2) {
        const int node = base + g;

        const float4* osrc = (const float4*)&g_gout[(size_t)node * XPC];
        float4* odst = (float4*)gouts;
        for (int i = t2; i < XPC / 4; i += 128) odst[i] = osrc[i];
        __syncthreads();

        float acc0 = 0.f, acc1 = 0.f, acc2 = 0.f;
        const float4* o4 = (const float4*)gouts;
#pragma unroll 4
        for (int d = 0; d < HC; d += 4) {
            float4 v0 = o4[d >> 2];
            float4 v1 = o4[96 + (d >> 2)];
            float4 v2 = o4[192 + (d >> 2)];
            float w0 = Ws[(d + 0) * SEMD + t2];
            float w1 = Ws[(d + 1) * SEMD + t2];
            float w2 = Ws[(d + 2) * SEMD + t2];
            float w3 = Ws[(d + 3) * SEMD + t2];
            acc0 = fmaf(v0.x, w0, acc0); acc0 = fmaf(v0.y, w1, acc0);
            acc0 = fmaf(v0.z, w2, acc0); acc0 = fmaf(v0.w, w3, acc0);
            acc1 = fmaf(v1.x, w0, acc1); acc1 = fmaf(v1.y, w1, acc1);
            acc1 = fmaf(v1.z, w2, acc1); acc1 = fmaf(v1.w, w3, acc1);
            acc2 = fmaf(v2.x, w0, acc2); acc2 = fmaf(v2.y, w1, acc2);
            acc2 = fmaf(v2.z, w2, acc2); acc2 = fmaf(v2.w, w3, acc2);
        }

        float s0 = tanhf(acc0 + bs) * qv;
        float s1 = tanhf(acc1 + bs) * qv;
        float s2 = tanhf(acc2 + bs) * qv;
#pragma unroll
        for (int o = 16; o > 0; o >>= 1) {
            s0 += __shfl_xor_sync(0xffffffffu, s0, o);
            s1 += __shfl_xor_sync(0xffffffffu, s1, o);
            s2 += __shfl_xor_sync(0xffffffffu, s2, o);
        }
        if (lane == 0) {
            gred[wid * 3 + 0] = s0;
            gred[wid * 3 + 1] = s1;
            gred[wid * 3 + 2] = s2;
        }
        __syncthreads();
        float S0 = gred[0] + gred[3] + gred[6] + gred[9];
        float S1 = gred[1] + gred[4] + gred[7] + gred[10];
        float S2 = gred[2] + gred[5] + gred[8] + gred[11];

        float bm = fmaxf(S0, fmaxf(S1, S2));
        float e0 = expf(S0 - bm), e1 = expf(S1 - bm), e2 = expf(S2 - bm);
        float iden = 1.f / (e0 + e1 + e2);
        float b0 = e0 * iden, b1 = e1 * iden, b2 = e2 * iden;

        for (int c = t2; c < HC; c += 128) {
            float v = b0 * gouts[c] + b1 * gouts[HC + c] + b2 * gouts[2 * HC + c];
            out[(size_t)node * HC + c] = v + mgx[c] * (gsrc[c] + gdst[c]);
        }
        __syncthreads();
    }
}

/* ------------------------------------------------------------------ */
extern "C" void kernel_launch(void* const* d_in, const int* in_sizes, int n_in,
                              void* d_out, int out_size)
{
    const float* x        = (const float*)d_in[0];
    const float* theta    = (const float*)d_in[1];
    const float* att_src  = (const float*)d_in[2];
    const float* att_dst  = (const float*)d_in[3];
    const float* gat_bias = (const float*)d_in[4];
    const float* W_sem    = (const float*)d_in[5];
    const float* b_sem    = (const float*)d_in[6];
    const float* q_sem    = (const float*)d_in[7];
    const float* mgx      = (const float*)d_in[8];
    const float* gsrc     = (const float*)d_in[9];
    const float* gdst     = (const float*)d_in[10];
    const void*  ei       = d_in[11];
    float* out = (float*)d_out;

    /* 0. edge_index dtype detection (int32 vs int64) */
    detect_kernel<<<1, 32>>>((const int*)ei);

    /* 1. bf16-split operands, then mma.sync (HMMA) GEMM1 */
    split_x_kernel<<<(N_NODES * IN_CH + 255) / 256, 256>>>(x);
    split_theta_kernel<<<(XPC * IN_CH + 255) / 256, 256>>>(theta);
    gemm1_mma_kernel<<<dim3(XPC / 128, (N_NODES + 127) / 128), 256>>>();

    /* 2. attention logit components */
    asd_kernel<<<(N_NODES * NREL * HEADS + 3) / 4, 128>>>(att_src, att_dst);

    /* 3. CSR build (group edges by dst) */
    zero_deg_kernel<<<(RN + 255) / 256, 256>>>();
    count_kernel<<<(TOTE + 255) / 256, 256>>>(ei);
    scan1_kernel<<<(RN + SCH - 1) / SCH, 256>>>();
    scan2_kernel<<<1, 256>>>((RN + SCH - 1) / SCH);
    scan3_kernel<<<(RN + 255) / 256, 256>>>();
    fill_kernel<<<(TOTE + 255) / 256, 256>>>(ei);

    /* 4. per-(relation,node) GAT softmax + aggregate */
    agg_kernel<<<RN / 4, 128>>>(gat_bias);

    /* 5. semantic attention + final epilogue (2 nodes / block iter) */
    cudaFuncSetAttribute(sem_kernel,
                         cudaFuncAttributeMaxDynamicSharedMemorySize, SEM_SMEM);
    sem_kernel<<<148, 256, SEM_SMEM>>>(W_sem, b_sem, q_sem, mgx, gsrc, gdst, out);
}

// round 10
// speedup vs baseline: 2.9190x; 1.3019x over previous
#include <cuda_runtime.h>
#include <cuda_bf16.h>
#include <math.h>
#include <stdint.h>

#define N_NODES 50000
#define IN_CH   256
#define HEADS   3
#define OUT_C   128
#define HC      384
#define NREL    3
#define NEDGE   400000
#define SEMD    128
#define RN      (NREL * N_NODES)     /* 150000 */
#define TOTE    (NREL * NEDGE)       /* 1200000 */
#define XPC     (NREL * HC)          /* 1152 */

/* ------------------------------------------------------------------ */
/* scratch (static device globals — no runtime allocation)             */
/* ------------------------------------------------------------------ */
__device__ float g_xp  [(size_t)N_NODES * XPC];   /* x @ theta, [N][R*HC] */
__device__ float g_gout[(size_t)N_NODES * XPC];   /* relu(gat+bias), [N][R][HC] */
__device__ float g_as  [N_NODES * NREL * HEADS];
__device__ float g_ad  [N_NODES * NREL * HEADS];
__device__ int   g_deg [RN];
__device__ int   g_off [RN + 1];
__device__ int   g_cur [RN];
__device__ int   g_adj [TOTE];
__device__ int   g_part[256];
__device__ int   g_is64;

/* bf16 split operands for tensor-core GEMM1 */
__device__ __nv_bfloat16 g_xh[(size_t)N_NODES * IN_CH];
__device__ __nv_bfloat16 g_xl[(size_t)N_NODES * IN_CH];
__device__ __nv_bfloat16 g_th[(size_t)XPC * IN_CH];   /* theta^T [j][k] hi */
__device__ __nv_bfloat16 g_tl[(size_t)XPC * IN_CH];   /* theta^T [j][k] lo */

/* W_sem^T bf16 split: [s=128][d=384] */
__device__ __nv_bfloat16 g_wh[SEMD * HC];
__device__ __nv_bfloat16 g_wl[SEMD * HC];

/* per-(n,r) semantic scores, 2 partial slabs (warp-col halves) */
__device__ float g_scoreP[2][RN];

/* ------------------------------------------------------------------ */
/* edge_index dtype detection (JAX x64-disabled => int32)              */
/* ------------------------------------------------------------------ */
__global__ void detect_kernel(const int* __restrict__ ei32)
{
    if (threadIdx.x == 0) {
        int is64 = 1;
        for (int i = 1; i < 128; i += 2)
            if (ei32[i] != 0) { is64 = 0; break; }
        g_is64 = is64;
    }
}

__device__ __forceinline__ int load_idx(const void* ei, int is64, size_t pos)
{
    int v = is64 ? (int)((const long long*)ei)[pos]
                 : ((const int*)ei)[pos];
    if ((unsigned)v >= (unsigned)N_NODES) v = 0;
    return v;
}

/* ------------------------------------------------------------------ */
/* bf16 split preprocessing                                            */
/* ------------------------------------------------------------------ */
__global__ void split_x_kernel(const float* __restrict__ x)
{
    int i = blockIdx.x * blockDim.x + threadIdx.x;
    if (i >= N_NODES * IN_CH) return;
    float v = x[i];
    __nv_bfloat16 h = __float2bfloat16(v);
    g_xh[i] = h;
    g_xl[i] = __float2bfloat16(v - __bfloat162float(h));
}

__global__ void split_theta_kernel(const float* __restrict__ theta)
{
    int i = blockIdx.x * blockDim.x + threadIdx.x;
    if (i >= XPC * IN_CH) return;
    int j = i / IN_CH;          /* output col 0..1151 */
    int k = i % IN_CH;
    int r  = j / HC;
    int hc = j % HC;
    float v = theta[((size_t)r * IN_CH + k) * HC + hc];
    __nv_bfloat16 h = __float2bfloat16(v);
    g_th[i] = h;
    g_tl[i] = __float2bfloat16(v - __bfloat162float(h));
}

__global__ void split_wsem_kernel(const float* __restrict__ W_sem)
{
    int i = blockIdx.x * blockDim.x + threadIdx.x;
    if (i >= SEMD * HC) return;
    int s = i / HC;
    int d = i % HC;
    float v = W_sem[(size_t)d * SEMD + s];
    __nv_bfloat16 h = __float2bfloat16(v);
    g_wh[i] = h;
    g_wl[i] = __float2bfloat16(v - __bfloat162float(h));
}

/* ------------------------------------------------------------------ */
/* mma.sync helpers                                                    */
/* ------------------------------------------------------------------ */
__device__ __forceinline__ void mma16816(float* c, const uint32_t* a,
                                         const uint32_t* b)
{
    asm volatile(
        "mma.sync.aligned.m16n8k16.row.col.f32.bf16.bf16.f32 "
        "{%0,%1,%2,%3}, {%4,%5,%6,%7}, {%8,%9}, {%0,%1,%2,%3};"
        : "+f"(c[0]), "+f"(c[1]), "+f"(c[2]), "+f"(c[3])
        : "r"(a[0]), "r"(a[1]), "r"(a[2]), "r"(a[3]),
          "r"(b[0]), "r"(b[1]));
}

__device__ __forceinline__ uint32_t pack_bf2(float a, float b)
{
    uint32_t lo = (uint32_t)__bfloat16_as_ushort(__float2bfloat16(a));
    uint32_t hi = (uint32_t)__bfloat16_as_ushort(__float2bfloat16(b));
    return (hi << 16) | lo;
}

__device__ __forceinline__ float fast_tanh(float x)
{
    float e = __expf(2.f * x);
    return 1.f - __fdividef(2.f, e + 1.f);
}

/* ------------------------------------------------------------------ */
/* GEMM1 via mma.sync bf16 (HMMA): 128x128 block, 8 warps, warp 32x64  */
/* 2-term split: D = Ah*Bh + Ah*Bl + Al*Bh, fp32 accumulators          */
/* ------------------------------------------------------------------ */
#define BK   32
#define LDA  40   /* padded bf16 row stride for smem tiles */

__global__ __launch_bounds__(256, 2)
void gemm1_mma_kernel()
{
    __shared__ __nv_bfloat16 sAh[128][LDA];
    __shared__ __nv_bfloat16 sAl[128][LDA];
    __shared__ __nv_bfloat16 sBh[128][LDA];
    __shared__ __nv_bfloat16 sBl[128][LDA];

    const int tid   = threadIdx.x;
    const int wid   = tid >> 5;
    const int lane  = tid & 31;
    const int wm    = wid & 3;
    const int wn    = wid >> 2;
    const int row0  = blockIdx.y * 128;
    const int col0  = blockIdx.x * 128;

    const int qrow = lane >> 2;
    const int qk   = (lane & 3) * 2;

    float c[2][8][4];
#pragma unroll
    for (int i = 0; i < 2; i++)
#pragma unroll
        for (int j = 0; j < 8; j++)
#pragma unroll
            for (int q = 0; q < 4; q++) c[i][j][q] = 0.f;

    const int sr = tid >> 1;
    const int sc = (tid & 1) * 16;

    for (int kc = 0; kc < IN_CH; kc += BK) {
        __syncthreads();
        {
            const int m = row0 + sr;
            uint4 vh = make_uint4(0u, 0u, 0u, 0u), vl = vh;
            uint4 wh = vh, wl = vh;
            if (m < N_NODES) {
                const size_t gi = ((size_t)m * IN_CH + kc + sc) >> 3;
                vh = ((const uint4*)g_xh)[gi];
                vl = ((const uint4*)g_xl)[gi];
                wh = ((const uint4*)g_xh)[gi + 1];
                wl = ((const uint4*)g_xl)[gi + 1];
            }
            *(uint4*)&sAh[sr][sc]     = vh;
            *(uint4*)&sAl[sr][sc]     = vl;
            *(uint4*)&sAh[sr][sc + 8] = wh;
            *(uint4*)&sAl[sr][sc + 8] = wl;

            const size_t bgi = ((size_t)(col0 + sr) * IN_CH + kc + sc) >> 3;
            uint4 bh = ((const uint4*)g_th)[bgi];
            uint4 bl = ((const uint4*)g_tl)[bgi];
            uint4 bh2 = ((const uint4*)g_th)[bgi + 1];
            uint4 bl2 = ((const uint4*)g_tl)[bgi + 1];
            *(uint4*)&sBh[sr][sc]     = bh;
            *(uint4*)&sBl[sr][sc]     = bl;
            *(uint4*)&sBh[sr][sc + 8] = bh2;
            *(uint4*)&sBl[sr][sc + 8] = bl2;
        }
        __syncthreads();

#pragma unroll
        for (int ks = 0; ks < BK; ks += 16) {
            uint32_t ah[2][4], al[2][4];
#pragma unroll
            for (int i = 0; i < 2; i++) {
                const int r0 = wm * 32 + i * 16 + qrow;
                ah[i][0] = *(const uint32_t*)&sAh[r0][ks + qk];
                ah[i][1] = *(const uint32_t*)&sAh[r0 + 8][ks + qk];
                ah[i][2] = *(const uint32_t*)&sAh[r0][ks + qk + 8];
                ah[i][3] = *(const uint32_t*)&sAh[r0 + 8][ks + qk + 8];
                al[i][0] = *(const uint32_t*)&sAl[r0][ks + qk];
                al[i][1] = *(const uint32_t*)&sAl[r0 + 8][ks + qk];
                al[i][2] = *(const uint32_t*)&sAl[r0][ks + qk + 8];
                al[i][3] = *(const uint32_t*)&sAl[r0 + 8][ks + qk + 8];
            }
            uint32_t bh[8][2], bl[8][2];
#pragma unroll
            for (int j = 0; j < 8; j++) {
                const int n0 = wn * 64 + j * 8 + qrow;
                bh[j][0] = *(const uint32_t*)&sBh[n0][ks + qk];
                bh[j][1] = *(const uint32_t*)&sBh[n0][ks + qk + 8];
                bl[j][0] = *(const uint32_t*)&sBl[n0][ks + qk];
                bl[j][1] = *(const uint32_t*)&sBl[n0][ks + qk + 8];
            }
#pragma unroll
            for (int i = 0; i < 2; i++)
#pragma unroll
                for (int j = 0; j < 8; j++) {
                    mma16816(c[i][j], ah[i], bh[j]);
                    mma16816(c[i][j], ah[i], bl[j]);
                    mma16816(c[i][j], al[i], bh[j]);
                }
        }
    }

    const int crow = lane >> 2;
    const int ccol = (lane & 3) * 2;
#pragma unroll
    for (int i = 0; i < 2; i++) {
        const int mbase = row0 + wm * 32 + i * 16;
#pragma unroll
        for (int j = 0; j < 8; j++) {
            const int nbase = col0 + wn * 64 + j * 8 + ccol;
            const int m0 = mbase + crow;
            const int m1 = m0 + 8;
            if (m0 < N_NODES)
                *(float2*)&g_xp[(size_t)m0 * XPC + nbase] =
                    make_float2(c[i][j][0], c[i][j][1]);
            if (m1 < N_NODES)
                *(float2*)&g_xp[(size_t)m1 * XPC + nbase] =
                    make_float2(c[i][j][2], c[i][j][3]);
        }
    }
}

/* ------------------------------------------------------------------ */
/* semantic GEMM via mma.sync: score_part[wn][row] =                   */
/*   sum_{s in warp cols} tanh((gout[row]@W_sem)[s]+b[s])*q[s]         */
/* row = n*NREL+r (g_gout row-major). A split inline from fp32.        */
/* ------------------------------------------------------------------ */
__global__ __launch_bounds__(256, 2)
void sem_score_kernel(const float* __restrict__ b_sem,
                      const float* __restrict__ q_sem)
{
    __shared__ __nv_bfloat16 sAh[128][LDA];
    __shared__ __nv_bfloat16 sAl[128][LDA];
    __shared__ __nv_bfloat16 sBh[128][LDA];
    __shared__ __nv_bfloat16 sBl[128][LDA];

    const int tid   = threadIdx.x;
    const int wid   = tid >> 5;
    const int lane  = tid & 31;
    const int wm    = wid & 3;
    const int wn    = wid >> 2;
    const int row0  = blockIdx.x * 128;

    const int qrow = lane >> 2;
    const int qk   = (lane & 3) * 2;

    float c[2][8][4];
#pragma unroll
    for (int i = 0; i < 2; i++)
#pragma unroll
        for (int j = 0; j < 8; j++)
#pragma unroll
            for (int q = 0; q < 4; q++) c[i][j][q] = 0.f;

    const int sr = tid >> 1;
    const int sc = (tid & 1) * 16;

    for (int kc = 0; kc < HC; kc += BK) {
        __syncthreads();
        {
            /* A: split fp32 g_gout inline */
            const int m = row0 + sr;
#pragma unroll
            for (int t = 0; t < 4; t++) {
                float4 v = make_float4(0.f, 0.f, 0.f, 0.f);
                if (m < RN)
                    v = *(const float4*)&g_gout[(size_t)m * HC + kc + sc + t * 4];
                float hx = __bfloat162float(__float2bfloat16(v.x));
                float hy = __bfloat162float(__float2bfloat16(v.y));
                float hz = __bfloat162float(__float2bfloat16(v.z));
                float hw = __bfloat162float(__float2bfloat16(v.w));
                *(uint32_t*)&sAh[sr][sc + t * 4]     = pack_bf2(v.x, v.y);
                *(uint32_t*)&sAh[sr][sc + t * 4 + 2] = pack_bf2(v.z, v.w);
                *(uint32_t*)&sAl[sr][sc + t * 4]     = pack_bf2(v.x - hx, v.y - hy);
                *(uint32_t*)&sAl[sr][sc + t * 4 + 2] = pack_bf2(v.z - hz, v.w - hw);
            }
            /* B: W_sem^T hi/lo (pre-split, [s][d]) */
            const size_t bgi = ((size_t)sr * HC + kc + sc) >> 3;
            *(uint4*)&sBh[sr][sc]     = ((const uint4*)g_wh)[bgi];
            *(uint4*)&sBl[sr][sc]     = ((const uint4*)g_wl)[bgi];
            *(uint4*)&sBh[sr][sc + 8] = ((const uint4*)g_wh)[bgi + 1];
            *(uint4*)&sBl[sr][sc + 8] = ((const uint4*)g_wl)[bgi + 1];
        }
        __syncthreads();

#pragma unroll
        for (int ks = 0; ks < BK; ks += 16) {
            uint32_t ah[2][4], al[2][4];
#pragma unroll
            for (int i = 0; i < 2; i++) {
                const int r0 = wm * 32 + i * 16 + qrow;
                ah[i][0] = *(const uint32_t*)&sAh[r0][ks + qk];
                ah[i][1] = *(const uint32_t*)&sAh[r0 + 8][ks + qk];
                ah[i][2] = *(const uint32_t*)&sAh[r0][ks + qk + 8];
                ah[i][3] = *(const uint32_t*)&sAh[r0 + 8][ks + qk + 8];
                al[i][0] = *(const uint32_t*)&sAl[r0][ks + qk];
                al[i][1] = *(const uint32_t*)&sAl[r0 + 8][ks + qk];
                al[i][2] = *(const uint32_t*)&sAl[r0][ks + qk + 8];
                al[i][3] = *(const uint32_t*)&sAl[r0 + 8][ks + qk + 8];
            }
            uint32_t bh[8][2], bl[8][2];
#pragma unroll
            for (int j = 0; j < 8; j++) {
                const int n0 = wn * 64 + j * 8 + qrow;
                bh[j][0] = *(const uint32_t*)&sBh[n0][ks + qk];
                bh[j][1] = *(const uint32_t*)&sBh[n0][ks + qk + 8];
                bl[j][0] = *(const uint32_t*)&sBl[n0][ks + qk];
                bl[j][1] = *(const uint32_t*)&sBl[n0][ks + qk + 8];
            }
#pragma unroll
            for (int i = 0; i < 2; i++)
#pragma unroll
                for (int j = 0; j < 8; j++) {
                    mma16816(c[i][j], ah[i], bh[j]);
                    mma16816(c[i][j], ah[i], bl[j]);
                    mma16816(c[i][j], al[i], bh[j]);
                }
        }
    }

    /* fused epilogue: tanh(w+b)*q, reduce over this warp's 64 cols */
    const int crow = lane >> 2;
    const int ccol = (lane & 3) * 2;
    float rs[2][2] = {{0.f, 0.f}, {0.f, 0.f}};
#pragma unroll
    for (int i = 0; i < 2; i++)
#pragma unroll
        for (int j = 0; j < 8; j++) {
            const int col = wn * 64 + j * 8 + ccol;
            const float b0 = b_sem[col],     b1 = b_sem[col + 1];
            const float q0 = q_sem[col],     q1 = q_sem[col + 1];
            rs[i][0] += fast_tanh(c[i][j][0] + b0) * q0
                      + fast_tanh(c[i][j][1] + b1) * q1;
            rs[i][1] += fast_tanh(c[i][j][2] + b0) * q0
                      + fast_tanh(c[i][j][3] + b1) * q1;
        }
    /* quad reduce (lanes sharing crow) */
#pragma unroll
    for (int o = 1; o <= 2; o <<= 1) {
#pragma unroll
        for (int i = 0; i < 2; i++) {
            rs[i][0] += __shfl_xor_sync(0xffffffffu, rs[i][0], o);
            rs[i][1] += __shfl_xor_sync(0xffffffffu, rs[i][1], o);
        }
    }
    if ((lane & 3) == 0) {
#pragma unroll
        for (int i = 0; i < 2; i++)
#pragma unroll
            for (int h = 0; h < 2; h++) {
                const int row = row0 + wm * 32 + i * 16 + h * 8 + crow;
                if (row < RN) g_scoreP[wn][row] = rs[i][h];
            }
    }
}

/* ------------------------------------------------------------------ */
/* sem_final: softmax over 3 relation scores + weighted combine        */
/* one warp per node                                                   */
/* ------------------------------------------------------------------ */
__global__ void sem_final_kernel(const float* __restrict__ mgx,
                                 const float* __restrict__ gsrc,
                                 const float* __restrict__ gdst,
                                 float* __restrict__ out)
{
    const int node = blockIdx.x * 4 + (threadIdx.x >> 5);
    const int lane = threadIdx.x & 31;
    if (node >= N_NODES) return;

    const int rb = node * NREL;
    const float S0 = g_scoreP[0][rb + 0] + g_scoreP[1][rb + 0];
    const float S1 = g_scoreP[0][rb + 1] + g_scoreP[1][rb + 1];
    const float S2 = g_scoreP[0][rb + 2] + g_scoreP[1][rb + 2];

    const float bm = fmaxf(S0, fmaxf(S1, S2));
    const float e0 = expf(S0 - bm), e1 = expf(S1 - bm), e2 = expf(S2 - bm);
    const float iv = 1.f / (e0 + e1 + e2);
    const float b0 = e0 * iv, b1 = e1 * iv, b2 = e2 * iv;

    const float* gp = &g_gout[(size_t)node * XPC];
#pragma unroll
    for (int t = 0; t < 3; t++) {
        const int cidx = lane * 4 + t * 128;
        float4 v0 = *(const float4*)&gp[cidx];
        float4 v1 = *(const float4*)&gp[HC + cidx];
        float4 v2 = *(const float4*)&gp[2 * HC + cidx];
        float4 mg = *(const float4*)&mgx[cidx];
        float4 gs = *(const float4*)&gsrc[cidx];
        float4 gd = *(const float4*)&gdst[cidx];
        float4 o;
        o.x = b0 * v0.x + b1 * v1.x + b2 * v2.x + mg.x * (gs.x + gd.x);
        o.y = b0 * v0.y + b1 * v1.y + b2 * v2.y + mg.y * (gs.y + gd.y);
        o.z = b0 * v0.z + b1 * v1.z + b2 * v2.z + mg.z * (gs.z + gd.z);
        o.w = b0 * v0.w + b1 * v1.w + b2 * v2.w + mg.w * (gs.w + gd.w);
        *(float4*)&out[(size_t)node * HC + cidx] = o;
    }
}

/* ------------------------------------------------------------------ */
/* per-node attention logits: a_s/a_d[n][r][h] = sum_c xp*att          */
/* ------------------------------------------------------------------ */
__global__ void asd_kernel(const float* __restrict__ att_src,
                           const float* __restrict__ att_dst)
{
    const int wid  = threadIdx.x >> 5;
    const int lane = threadIdx.x & 31;
    const int item = blockIdx.x * 4 + wid;
    if (item >= N_NODES * NREL * HEADS) return;
    const int n  = item / (NREL * HEADS);
    const int rh = item % (NREL * HEADS);
    const int r  = rh / HEADS;
    const int h  = rh % HEADS;

    const float4 xv = *(const float4*)&g_xp[(size_t)n * XPC + r * HC + h * OUT_C + lane * 4];
    const float4 sv = *(const float4*)&att_src[(size_t)(r * HEADS + h) * OUT_C + lane * 4];
    const float4 dv = *(const float4*)&att_dst[(size_t)(r * HEADS + h) * OUT_C + lane * 4];

    float ds = xv.x * sv.x + xv.y * sv.y + xv.z * sv.z + xv.w * sv.w;
    float dd = xv.x * dv.x + xv.y * dv.y + xv.z * dv.z + xv.w * dv.w;
#pragma unroll
    for (int o = 16; o > 0; o >>= 1) {
        ds += __shfl_xor_sync(0xffffffffu, ds, o);
        dd += __shfl_xor_sync(0xffffffffu, dd, o);
    }
    if (lane == 0) {
        g_as[item] = ds;
        g_ad[item] = dd;
    }
}

/* ------------------------------------------------------------------ */
/* CSR build                                                           */
/* ------------------------------------------------------------------ */
__global__ void zero_deg_kernel()
{
    int i = blockIdx.x * blockDim.x + threadIdx.x;
    if (i < RN) g_deg[i] = 0;
}

__global__ void count_kernel(const void* __restrict__ ei)
{
    int i = blockIdx.x * blockDim.x + threadIdx.x;
    if (i >= TOTE) return;
    const int is64 = g_is64;
    int r = i / NEDGE;
    int e = i % NEDGE;
    int dst = load_idx(ei, is64, (size_t)r * 2 * NEDGE + NEDGE + e);
    atomicAdd(&g_deg[r * N_NODES + dst], 1);
}

#define SCH 1024
__global__ void scan1_kernel()
{
    __shared__ int s[256];
    const int b = blockIdx.x, t = threadIdx.x;
    const int base = b * SCH + t * 4;
    int v[4], sum = 0;
#pragma unroll
    for (int i = 0; i < 4; i++) {
        int idx = base + i;
        v[i] = (idx < RN) ? g_deg[idx] : 0;
        sum += v[i];
    }
    s[t] = sum;
    __syncthreads();
    for (int o = 1; o < 256; o <<= 1) {
        int xv = (t >= o) ? s[t - o] : 0;
        __syncthreads();
        s[t] += xv;
        __syncthreads();
    }
    int run = s[t] - sum;
    if (t == 255) g_part[b] = s[t];
#pragma unroll
    for (int i = 0; i < 4; i++) {
        int idx = base + i;
        if (idx < RN) g_off[idx] = run;
        run += v[i];
    }
}

__global__ void scan2_kernel(int nb)
{
    __shared__ int s[256];
    const int t = threadIdx.x;
    int v = (t < nb) ? g_part[t] : 0;
    s[t] = v;
    __syncthreads();
    for (int o = 1; o < 256; o <<= 1) {
        int xv = (t >= o) ? s[t - o] : 0;
        __syncthreads();
        s[t] += xv;
        __syncthreads();
    }
    g_part[t] = s[t] - v;
}

__global__ void scan3_kernel()
{
    int i = blockIdx.x * blockDim.x + threadIdx.x;
    if (i < RN) {
        int v = g_off[i] + g_part[i / SCH];
        g_off[i] = v;
        g_cur[i] = v;
    }
    if (i == 0) g_off[RN] = TOTE;
}

__global__ void fill_kernel(const void* __restrict__ ei)
{
    int i = blockIdx.x * blockDim.x + threadIdx.x;
    if (i >= TOTE) return;
    const int is64 = g_is64;
    int r = i / NEDGE;
    int e = i % NEDGE;
    int src = load_idx(ei, is64, (size_t)r * 2 * NEDGE + e);
    int dst = load_idx(ei, is64, (size_t)r * 2 * NEDGE + NEDGE + e);
    int pos = atomicAdd(&g_cur[r * N_NODES + dst], 1);
    if (pos >= 0 && pos < TOTE) g_adj[pos] = src;
}

/* ------------------------------------------------------------------ */
/* GAT aggregation: one warp per (r,n)                                 */
/* ------------------------------------------------------------------ */
#define ACAP 64
__device__ __forceinline__ float lrelu(float v) { return v > 0.f ? v : 0.2f * v; }

__global__ void agg_kernel(const float* __restrict__ gat_bias)
{
    __shared__ float pbuf[4][ACAP][3];
    __shared__ int   sbuf[4][ACAP];

    const int w    = threadIdx.x >> 5;
    const int lane = threadIdx.x & 31;
    const int item = blockIdx.x * 4 + w;
    if (item >= RN) return;
    const int r = item / N_NODES;
    const int n = item % N_NODES;

    const int off0 = g_off[r * N_NODES + n];
    const int deg  = g_off[r * N_NODES + n + 1] - off0;
    const int tot  = deg + 1;

    const float ad0 = g_ad[(n * NREL + r) * HEADS + 0];
    const float ad1 = g_ad[(n * NREL + r) * HEADS + 1];
    const float ad2 = g_ad[(n * NREL + r) * HEADS + 2];

    float m0 = -1e30f, m1 = -1e30f, m2 = -1e30f;
    for (int base = 0; base < tot; base += 32) {
        int i = base + lane;
        if (i < tot) {
            int src = (i < deg) ? g_adj[off0 + i] : n;
            const float* as = &g_as[(src * NREL + r) * HEADS];
            m0 = fmaxf(m0, lrelu(as[0] + ad0));
            m1 = fmaxf(m1, lrelu(as[1] + ad1));
            m2 = fmaxf(m2, lrelu(as[2] + ad2));
        }
    }
#pragma unroll
    for (int o = 16; o > 0; o >>= 1) {
        m0 = fmaxf(m0, __shfl_xor_sync(0xffffffffu, m0, o));
        m1 = fmaxf(m1, __shfl_xor_sync(0xffffffffu, m1, o));
        m2 = fmaxf(m2, __shfl_xor_sync(0xffffffffu, m2, o));
    }

    float z0 = 0.f, z1 = 0.f, z2 = 0.f;
    for (int base = 0; base < tot; base += 32) {
        int i = base + lane;
        if (i < tot) {
            int src = (i < deg) ? g_adj[off0 + i] : n;
            const float* as = &g_as[(src * NREL + r) * HEADS];
            z0 += expf(lrelu(as[0] + ad0) - m0);
            z1 += expf(lrelu(as[1] + ad1) - m1);
            z2 += expf(lrelu(as[2] + ad2) - m2);
        }
    }
#pragma unroll
    for (int o = 16; o > 0; o >>= 1) {
        z0 += __shfl_xor_sync(0xffffffffu, z0, o);
        z1 += __shfl_xor_sync(0xffffffffu, z1, o);
        z2 += __shfl_xor_sync(0xffffffffu, z2, o);
    }
    const float iv0 = 1.f / (z0 + 1e-16f);
    const float iv1 = 1.f / (z1 + 1e-16f);
    const float iv2 = 1.f / (z2 + 1e-16f);

    float acc[12];
#pragma unroll
    for (int k = 0; k < 12; k++) acc[k] = 0.f;

    for (int c0 = 0; c0 < tot; c0 += ACAP) {
        const int clen = min(ACAP, tot - c0);
        for (int base = 0; base < clen; base += 32) {
            int i = base + lane;
            if (i < clen) {
                int gi  = c0 + i;
                int src = (gi < deg) ? g_adj[off0 + gi] : n;
                sbuf[w][i] = src;
                const float* as = &g_as[(src * NREL + r) * HEADS];
                pbuf[w][i][0] = expf(lrelu(as[0] + ad0) - m0) * iv0;
                pbuf[w][i][1] = expf(lrelu(as[1] + ad1) - m1) * iv1;
                pbuf[w][i][2] = expf(lrelu(as[2] + ad2) - m2) * iv2;
            }
        }
        __syncwarp();
        for (int j = 0; j < clen; j++) {
            const int   src = sbuf[w][j];
            const float a0  = pbuf[w][j][0];
            const float a1  = pbuf[w][j][1];
            const float a2  = pbuf[w][j][2];
            const float* xr = &g_xp[(size_t)src * XPC + r * HC];
#pragma unroll
            for (int k = 0; k < 12; k++) {
                float al = (k < 4) ? a0 : ((k < 8) ? a1 : a2);
                acc[k] = fmaf(al, xr[lane + 32 * k], acc[k]);
            }
        }
        __syncwarp();
    }

    const float* bp = &gat_bias[r * HC];
    float* op = &g_gout[((size_t)n * NREL + r) * HC];
#pragma unroll
    for (int k = 0; k < 12; k++) {
        int c = lane + 32 * k;
        op[c] = fmaxf(acc[k] + bp[c], 0.f);
    }
}

/* ------------------------------------------------------------------ */
extern "C" void kernel_launch(void* const* d_in, const int* in_sizes, int n_in,
                              void* d_out, int out_size)
{
    const float* x        = (const float*)d_in[0];
    const float* theta    = (const float*)d_in[1];
    const float* att_src  = (const float*)d_in[2];
    const float* att_dst  = (const float*)d_in[3];
    const float* gat_bias = (const float*)d_in[4];
    const float* W_sem    = (const float*)d_in[5];
    const float* b_sem    = (const float*)d_in[6];
    const float* q_sem    = (const float*)d_in[7];
    const float* mgx      = (const float*)d_in[8];
    const float* gsrc     = (const float*)d_in[9];
    const float* gdst     = (const float*)d_in[10];
    const void*  ei       = d_in[11];
    float* out = (float*)d_out;

    /* 0. edge_index dtype detection (int32 vs int64) */
    detect_kernel<<<1, 32>>>((const int*)ei);

    /* 1. bf16-split operands, then mma.sync (HMMA) GEMM1 */
    split_x_kernel<<<(N_NODES * IN_CH + 255) / 256, 256>>>(x);
    split_theta_kernel<<<(XPC * IN_CH + 255) / 256, 256>>>(theta);
    split_wsem_kernel<<<(SEMD * HC + 255) / 256, 256>>>(W_sem);
    gemm1_mma_kernel<<<dim3(XPC / 128, (N_NODES + 127) / 128), 256>>>();

    /* 2. attention logit components */
    asd_kernel<<<(N_NODES * NREL * HEADS + 3) / 4, 128>>>(att_src, att_dst);

    /* 3. CSR build (group edges by dst) */
    zero_deg_kernel<<<(RN + 255) / 256, 256>>>();
    count_kernel<<<(TOTE + 255) / 256, 256>>>(ei);
    scan1_kernel<<<(RN + SCH - 1) / SCH, 256>>>();
    scan2_kernel<<<1, 256>>>((RN + SCH - 1) / SCH);
    scan3_kernel<<<(RN + 255) / 256, 256>>>();
    fill_kernel<<<(TOTE + 255) / 256, 256>>>(ei);

    /* 4. per-(relation,node) GAT softmax + aggregate */
    agg_kernel<<<RN / 4, 128>>>(gat_bias);

    /* 5. semantic attention: HMMA score GEMM + softmax combine */
    sem_score_kernel<<<(RN + 127) / 128, 256>>>(b_sem, q_sem);
    sem_final_kernel<<<(N_NODES + 3) / 4, 128>>>(mgx, gsrc, gdst, out);
}

// round 11
// speedup vs baseline: 4.3853x; 1.5023x over previous
#include <cuda_runtime.h>
#include <cuda_bf16.h>
#include <math.h>
#include <stdint.h>

#define N_NODES 50000
#define IN_CH   256
#define HEADS   3
#define OUT_C   128
#define HC      384
#define NREL    3
#define NEDGE   400000
#define SEMD    128
#define RN      (NREL * N_NODES)     /* 150000 */
#define TOTE    (NREL * NEDGE)       /* 1200000 */
#define XPC     (NREL * HC)          /* 1152 */

/* ------------------------------------------------------------------ */
/* scratch (static device globals — no runtime allocation)             */
/* ------------------------------------------------------------------ */
__device__ float g_xp  [(size_t)N_NODES * XPC];   /* x @ theta, [N][R*HC] */
__device__ float g_gout[(size_t)N_NODES * XPC];   /* relu(gat+bias), [N][R][HC] */
__device__ float g_as  [N_NODES * NREL * HEADS];
__device__ float g_ad  [N_NODES * NREL * HEADS];
__device__ int   g_deg [RN];
__device__ int   g_off [RN + 1];
__device__ int   g_cur [RN];
__device__ int   g_adj [TOTE];
__device__ int   g_part[256];
__device__ int   g_is64;

/* bf16 split operands for tensor-core GEMM1 */
__device__ __nv_bfloat16 g_xh[(size_t)N_NODES * IN_CH];
__device__ __nv_bfloat16 g_xl[(size_t)N_NODES * IN_CH];
__device__ __nv_bfloat16 g_th[(size_t)XPC * IN_CH];   /* theta^T [j][k] hi */
__device__ __nv_bfloat16 g_tl[(size_t)XPC * IN_CH];   /* theta^T [j][k] lo */

/* W_sem^T bf16 split: [s=128][d=384] */
__device__ __nv_bfloat16 g_wh[SEMD * HC];
__device__ __nv_bfloat16 g_wl[SEMD * HC];

/* per-(n,r) semantic scores, 2 partial slabs (warp-col halves) */
__device__ float g_scoreP[2][RN];

/* ------------------------------------------------------------------ */
/* edge_index dtype detection (JAX x64-disabled => int32)              */
/* ------------------------------------------------------------------ */
__global__ void detect_kernel(const int* __restrict__ ei32)
{
    if (threadIdx.x == 0) {
        int is64 = 1;
        for (int i = 1; i < 128; i += 2)
            if (ei32[i] != 0) { is64 = 0; break; }
        g_is64 = is64;
    }
}

__device__ __forceinline__ int load_idx(const void* ei, int is64, size_t pos)
{
    int v = is64 ? (int)((const long long*)ei)[pos]
                 : ((const int*)ei)[pos];
    if ((unsigned)v >= (unsigned)N_NODES) v = 0;
    return v;
}

/* ------------------------------------------------------------------ */
/* bf16 split preprocessing                                            */
/* ------------------------------------------------------------------ */
__global__ void split_x_kernel(const float* __restrict__ x)
{
    int i = blockIdx.x * blockDim.x + threadIdx.x;
    if (i >= N_NODES * IN_CH) return;
    float v = x[i];
    __nv_bfloat16 h = __float2bfloat16(v);
    g_xh[i] = h;
    g_xl[i] = __float2bfloat16(v - __bfloat162float(h));
}

__global__ void split_theta_kernel(const float* __restrict__ theta)
{
    int i = blockIdx.x * blockDim.x + threadIdx.x;
    if (i >= XPC * IN_CH) return;
    int j = i / IN_CH;          /* output col 0..1151 */
    int k = i % IN_CH;
    int r  = j / HC;
    int hc = j % HC;
    float v = theta[((size_t)r * IN_CH + k) * HC + hc];
    __nv_bfloat16 h = __float2bfloat16(v);
    g_th[i] = h;
    g_tl[i] = __float2bfloat16(v - __bfloat162float(h));
}

__global__ void split_wsem_kernel(const float* __restrict__ W_sem)
{
    int i = blockIdx.x * blockDim.x + threadIdx.x;
    if (i >= SEMD * HC) return;
    int s = i / HC;
    int d = i % HC;
    float v = W_sem[(size_t)d * SEMD + s];
    __nv_bfloat16 h = __float2bfloat16(v);
    g_wh[i] = h;
    g_wl[i] = __float2bfloat16(v - __bfloat162float(h));
}

/* ------------------------------------------------------------------ */
/* mma.sync / ldmatrix helpers                                         */
/* ------------------------------------------------------------------ */
__device__ __forceinline__ void mma16816(float* c, const uint32_t* a,
                                         const uint32_t* b)
{
    asm volatile(
        "mma.sync.aligned.m16n8k16.row.col.f32.bf16.bf16.f32 "
        "{%0,%1,%2,%3}, {%4,%5,%6,%7}, {%8,%9}, {%0,%1,%2,%3};"
        : "+f"(c[0]), "+f"(c[1]), "+f"(c[2]), "+f"(c[3])
        : "r"(a[0]), "r"(a[1]), "r"(a[2]), "r"(a[3]),
          "r"(b[0]), "r"(b[1]));
}

__device__ __forceinline__ void ldsm_x4(uint32_t* r, uint32_t addr)
{
    asm volatile("ldmatrix.sync.aligned.m8n8.x4.shared.b16 {%0,%1,%2,%3}, [%4];"
                 : "=r"(r[0]), "=r"(r[1]), "=r"(r[2]), "=r"(r[3])
                 : "r"(addr));
}

__device__ __forceinline__ uint32_t cvta_s(const void* p)
{
    return (uint32_t)__cvta_generic_to_shared(p);
}

__device__ __forceinline__ uint32_t pack_bf2(float a, float b)
{
    uint32_t lo = (uint32_t)__bfloat16_as_ushort(__float2bfloat16(a));
    uint32_t hi = (uint32_t)__bfloat16_as_ushort(__float2bfloat16(b));
    return (hi << 16) | lo;
}

__device__ __forceinline__ float fast_tanh(float x)
{
    float e = __expf(2.f * x);
    return 1.f - __fdividef(2.f, e + 1.f);
}

/* ------------------------------------------------------------------ */
/* GEMM1 via mma.sync bf16 (HMMA): 128x128 block, 8 warps, warp 32x64  */
/* 2-term split: D = Ah*Bh + Ah*Bl + Al*Bh, fp32 accumulators          */
/* fragments loaded via ldmatrix.x4 (conflict-free with LDA=40)        */
/* ------------------------------------------------------------------ */
#define BK   32
#define LDA  40   /* padded bf16 row stride for smem tiles */

__global__ __launch_bounds__(256, 2)
void gemm1_mma_kernel()
{
    __shared__ __nv_bfloat16 sAh[128][LDA];
    __shared__ __nv_bfloat16 sAl[128][LDA];
    __shared__ __nv_bfloat16 sBh[128][LDA];
    __shared__ __nv_bfloat16 sBl[128][LDA];

    const int tid   = threadIdx.x;
    const int wid   = tid >> 5;
    const int lane  = tid & 31;
    const int wm    = wid & 3;
    const int wn    = wid >> 2;
    const int row0  = blockIdx.y * 128;
    const int col0  = blockIdx.x * 128;

    float c[2][8][4];
#pragma unroll
    for (int i = 0; i < 2; i++)
#pragma unroll
        for (int j = 0; j < 8; j++)
#pragma unroll
            for (int q = 0; q < 4; q++) c[i][j][q] = 0.f;

    /* ldmatrix lane addresses (constant across kc; +2*ks bytes per step) */
    const int laA_r = lane & 15;
    const int laA_k = (lane >> 4) * 8;
    uint32_t aAH[2], aAL[2];
#pragma unroll
    for (int i = 0; i < 2; i++) {
        const int rr = wm * 32 + i * 16 + laA_r;
        aAH[i] = cvta_s(&sAh[rr][laA_k]);
        aAL[i] = cvta_s(&sAl[rr][laA_k]);
    }
    const int laB_n = (lane & 7) + ((lane >> 4) << 3);
    const int laB_k = ((lane >> 3) & 1) * 8;
    uint32_t aBH[4], aBL[4];
#pragma unroll
    for (int j2 = 0; j2 < 4; j2++) {
        const int nr = wn * 64 + j2 * 16 + laB_n;
        aBH[j2] = cvta_s(&sBh[nr][laB_k]);
        aBL[j2] = cvta_s(&sBl[nr][laB_k]);
    }

    const int sr = tid >> 1;
    const int sc = (tid & 1) * 16;

    for (int kc = 0; kc < IN_CH; kc += BK) {
        __syncthreads();
        {
            const int m = row0 + sr;
            uint4 vh = make_uint4(0u, 0u, 0u, 0u), vl = vh;
            uint4 wh = vh, wl = vh;
            if (m < N_NODES) {
                const size_t gi = ((size_t)m * IN_CH + kc + sc) >> 3;
                vh = ((const uint4*)g_xh)[gi];
                vl = ((const uint4*)g_xl)[gi];
                wh = ((const uint4*)g_xh)[gi + 1];
                wl = ((const uint4*)g_xl)[gi + 1];
            }
            *(uint4*)&sAh[sr][sc]     = vh;
            *(uint4*)&sAl[sr][sc]     = vl;
            *(uint4*)&sAh[sr][sc + 8] = wh;
            *(uint4*)&sAl[sr][sc + 8] = wl;

            const size_t bgi = ((size_t)(col0 + sr) * IN_CH + kc + sc) >> 3;
            uint4 bh = ((const uint4*)g_th)[bgi];
            uint4 bl = ((const uint4*)g_tl)[bgi];
            uint4 bh2 = ((const uint4*)g_th)[bgi + 1];
            uint4 bl2 = ((const uint4*)g_tl)[bgi + 1];
            *(uint4*)&sBh[sr][sc]     = bh;
            *(uint4*)&sBl[sr][sc]     = bl;
            *(uint4*)&sBh[sr][sc + 8] = bh2;
            *(uint4*)&sBl[sr][sc + 8] = bl2;
        }
        __syncthreads();

#pragma unroll
        for (int ks = 0; ks < BK; ks += 16) {
            const uint32_t koff = ks * 2;   /* bytes */
            uint32_t ah[2][4], al[2][4];
#pragma unroll
            for (int i = 0; i < 2; i++) {
                ldsm_x4(ah[i], aAH[i] + koff);
                ldsm_x4(al[i], aAL[i] + koff);
            }
            uint32_t bh[8][2], bl[8][2];
#pragma unroll
            for (int j2 = 0; j2 < 4; j2++) {
                ldsm_x4(&bh[2 * j2][0], aBH[j2] + koff);
                ldsm_x4(&bl[2 * j2][0], aBL[j2] + koff);
            }
#pragma unroll
            for (int i = 0; i < 2; i++)
#pragma unroll
                for (int j = 0; j < 8; j++) {
                    mma16816(c[i][j], ah[i], bh[j]);
                    mma16816(c[i][j], ah[i], bl[j]);
                    mma16816(c[i][j], al[i], bh[j]);
                }
        }
    }

    const int crow = lane >> 2;
    const int ccol = (lane & 3) * 2;
#pragma unroll
    for (int i = 0; i < 2; i++) {
        const int mbase = row0 + wm * 32 + i * 16;
#pragma unroll
        for (int j = 0; j < 8; j++) {
            const int nbase = col0 + wn * 64 + j * 8 + ccol;
            const int m0 = mbase + crow;
            const int m1 = m0 + 8;
            if (m0 < N_NODES)
                *(float2*)&g_xp[(size_t)m0 * XPC + nbase] =
                    make_float2(c[i][j][0], c[i][j][1]);
            if (m1 < N_NODES)
                *(float2*)&g_xp[(size_t)m1 * XPC + nbase] =
                    make_float2(c[i][j][2], c[i][j][3]);
        }
    }
}

/* ------------------------------------------------------------------ */
/* semantic GEMM via mma.sync (ldmatrix fragments), fused tanh epilog  */
/* ------------------------------------------------------------------ */
__global__ __launch_bounds__(256, 2)
void sem_score_kernel(const float* __restrict__ b_sem,
                      const float* __restrict__ q_sem)
{
    __shared__ __nv_bfloat16 sAh[128][LDA];
    __shared__ __nv_bfloat16 sAl[128][LDA];
    __shared__ __nv_bfloat16 sBh[128][LDA];
    __shared__ __nv_bfloat16 sBl[128][LDA];

    const int tid   = threadIdx.x;
    const int wid   = tid >> 5;
    const int lane  = tid & 31;
    const int wm    = wid & 3;
    const int wn    = wid >> 2;
    const int row0  = blockIdx.x * 128;

    float c[2][8][4];
#pragma unroll
    for (int i = 0; i < 2; i++)
#pragma unroll
        for (int j = 0; j < 8; j++)
#pragma unroll
            for (int q = 0; q < 4; q++) c[i][j][q] = 0.f;

    const int laA_r = lane & 15;
    const int laA_k = (lane >> 4) * 8;
    uint32_t aAH[2], aAL[2];
#pragma unroll
    for (int i = 0; i < 2; i++) {
        const int rr = wm * 32 + i * 16 + laA_r;
        aAH[i] = cvta_s(&sAh[rr][laA_k]);
        aAL[i] = cvta_s(&sAl[rr][laA_k]);
    }
    const int laB_n = (lane & 7) + ((lane >> 4) << 3);
    const int laB_k = ((lane >> 3) & 1) * 8;
    uint32_t aBH[4], aBL[4];
#pragma unroll
    for (int j2 = 0; j2 < 4; j2++) {
        const int nr = wn * 64 + j2 * 16 + laB_n;
        aBH[j2] = cvta_s(&sBh[nr][laB_k]);
        aBL[j2] = cvta_s(&sBl[nr][laB_k]);
    }

    const int sr = tid >> 1;
    const int sc = (tid & 1) * 16;

    for (int kc = 0; kc < HC; kc += BK) {
        __syncthreads();
        {
            /* A: split fp32 g_gout inline */
            const int m = row0 + sr;
#pragma unroll
            for (int t = 0; t < 4; t++) {
                float4 v = make_float4(0.f, 0.f, 0.f, 0.f);
                if (m < RN)
                    v = *(const float4*)&g_gout[(size_t)m * HC + kc + sc + t * 4];
                float hx = __bfloat162float(__float2bfloat16(v.x));
                float hy = __bfloat162float(__float2bfloat16(v.y));
                float hz = __bfloat162float(__float2bfloat16(v.z));
                float hw = __bfloat162float(__float2bfloat16(v.w));
                *(uint32_t*)&sAh[sr][sc + t * 4]     = pack_bf2(v.x, v.y);
                *(uint32_t*)&sAh[sr][sc + t * 4 + 2] = pack_bf2(v.z, v.w);
                *(uint32_t*)&sAl[sr][sc + t * 4]     = pack_bf2(v.x - hx, v.y - hy);
                *(uint32_t*)&sAl[sr][sc + t * 4 + 2] = pack_bf2(v.z - hz, v.w - hw);
            }
            /* B: W_sem^T hi/lo (pre-split, [s][d]) */
            const size_t bgi = ((size_t)sr * HC + kc + sc) >> 3;
            *(uint4*)&sBh[sr][sc]     = ((const uint4*)g_wh)[bgi];
            *(uint4*)&sBl[sr][sc]     = ((const uint4*)g_wl)[bgi];
            *(uint4*)&sBh[sr][sc + 8] = ((const uint4*)g_wh)[bgi + 1];
            *(uint4*)&sBl[sr][sc + 8] = ((const uint4*)g_wl)[bgi + 1];
        }
        __syncthreads();

#pragma unroll
        for (int ks = 0; ks < BK; ks += 16) {
            const uint32_t koff = ks * 2;
            uint32_t ah[2][4], al[2][4];
#pragma unroll
            for (int i = 0; i < 2; i++) {
                ldsm_x4(ah[i], aAH[i] + koff);
                ldsm_x4(al[i], aAL[i] + koff);
            }
            uint32_t bh[8][2], bl[8][2];
#pragma unroll
            for (int j2 = 0; j2 < 4; j2++) {
                ldsm_x4(&bh[2 * j2][0], aBH[j2] + koff);
                ldsm_x4(&bl[2 * j2][0], aBL[j2] + koff);
            }
#pragma unroll
            for (int i = 0; i < 2; i++)
#pragma unroll
                for (int j = 0; j < 8; j++) {
                    mma16816(c[i][j], ah[i], bh[j]);
                    mma16816(c[i][j], ah[i], bl[j]);
                    mma16816(c[i][j], al[i], bh[j]);
                }
        }
    }

    /* fused epilogue: tanh(w+b)*q, reduce over this warp's 64 cols */
    const int crow = lane >> 2;
    const int ccol = (lane & 3) * 2;
    float rs[2][2] = {{0.f, 0.f}, {0.f, 0.f}};
#pragma unroll
    for (int i = 0; i < 2; i++)
#pragma unroll
        for (int j = 0; j < 8; j++) {
            const int col = wn * 64 + j * 8 + ccol;
            const float b0 = b_sem[col],     b1 = b_sem[col + 1];
            const float q0 = q_sem[col],     q1 = q_sem[col + 1];
            rs[i][0] += fast_tanh(c[i][j][0] + b0) * q0
                      + fast_tanh(c[i][j][1] + b1) * q1;
            rs[i][1] += fast_tanh(c[i][j][2] + b0) * q0
                      + fast_tanh(c[i][j][3] + b1) * q1;
        }
#pragma unroll
    for (int o = 1; o <= 2; o <<= 1) {
#pragma unroll
        for (int i = 0; i < 2; i++) {
            rs[i][0] += __shfl_xor_sync(0xffffffffu, rs[i][0], o);
            rs[i][1] += __shfl_xor_sync(0xffffffffu, rs[i][1], o);
        }
    }
    if ((lane & 3) == 0) {
#pragma unroll
        for (int i = 0; i < 2; i++)
#pragma unroll
            for (int h = 0; h < 2; h++) {
                const int row = row0 + wm * 32 + i * 16 + h * 8 + crow;
                if (row < RN) g_scoreP[wn][row] = rs[i][h];
            }
    }
}

/* ------------------------------------------------------------------ */
/* sem_final: softmax over 3 relation scores + weighted combine        */
/* ------------------------------------------------------------------ */
__global__ void sem_final_kernel(const float* __restrict__ mgx,
                                 const float* __restrict__ gsrc,
                                 const float* __restrict__ gdst,
                                 float* __restrict__ out)
{
    const int node = blockIdx.x * 4 + (threadIdx.x >> 5);
    const int lane = threadIdx.x & 31;
    if (node >= N_NODES) return;

    const int rb = node * NREL;
    const float S0 = g_scoreP[0][rb + 0] + g_scoreP[1][rb + 0];
    const float S1 = g_scoreP[0][rb + 1] + g_scoreP[1][rb + 1];
    const float S2 = g_scoreP[0][rb + 2] + g_scoreP[1][rb + 2];

    const float bm = fmaxf(S0, fmaxf(S1, S2));
    const float e0 = expf(S0 - bm), e1 = expf(S1 - bm), e2 = expf(S2 - bm);
    const float iv = 1.f / (e0 + e1 + e2);
    const float b0 = e0 * iv, b1 = e1 * iv, b2 = e2 * iv;

    const float* gp = &g_gout[(size_t)node * XPC];
#pragma unroll
    for (int t = 0; t < 3; t++) {
        const int cidx = lane * 4 + t * 128;
        float4 v0 = *(const float4*)&gp[cidx];
        float4 v1 = *(const float4*)&gp[HC + cidx];
        float4 v2 = *(const float4*)&gp[2 * HC + cidx];
        float4 mg = *(const float4*)&mgx[cidx];
        float4 gs = *(const float4*)&gsrc[cidx];
        float4 gd = *(const float4*)&gdst[cidx];
        float4 o;
        o.x = b0 * v0.x + b1 * v1.x + b2 * v2.x + mg.x * (gs.x + gd.x);
        o.y = b0 * v0.y + b1 * v1.y + b2 * v2.y + mg.y * (gs.y + gd.y);
        o.z = b0 * v0.z + b1 * v1.z + b2 * v2.z + mg.z * (gs.z + gd.z);
        o.w = b0 * v0.w + b1 * v1.w + b2 * v2.w + mg.w * (gs.w + gd.w);
        *(float4*)&out[(size_t)node * HC + cidx] = o;
    }
}

/* ------------------------------------------------------------------ */
/* per-node attention logits: a_s/a_d[n][r][h] = sum_c xp*att          */
/* ------------------------------------------------------------------ */
__global__ void asd_kernel(const float* __restrict__ att_src,
                           const float* __restrict__ att_dst)
{
    const int wid  = threadIdx.x >> 5;
    const int lane = threadIdx.x & 31;
    const int item = blockIdx.x * 4 + wid;
    if (item >= N_NODES * NREL * HEADS) return;
    const int n  = item / (NREL * HEADS);
    const int rh = item % (NREL * HEADS);
    const int r  = rh / HEADS;
    const int h  = rh % HEADS;

    const float4 xv = *(const float4*)&g_xp[(size_t)n * XPC + r * HC + h * OUT_C + lane * 4];
    const float4 sv = *(const float4*)&att_src[(size_t)(r * HEADS + h) * OUT_C + lane * 4];
    const float4 dv = *(const float4*)&att_dst[(size_t)(r * HEADS + h) * OUT_C + lane * 4];

    float ds = xv.x * sv.x + xv.y * sv.y + xv.z * sv.z + xv.w * sv.w;
    float dd = xv.x * dv.x + xv.y * dv.y + xv.z * dv.z + xv.w * dv.w;
#pragma unroll
    for (int o = 16; o > 0; o >>= 1) {
        ds += __shfl_xor_sync(0xffffffffu, ds, o);
        dd += __shfl_xor_sync(0xffffffffu, dd, o);
    }
    if (lane == 0) {
        g_as[item] = ds;
        g_ad[item] = dd;
    }
}

/* ------------------------------------------------------------------ */
/* CSR build                                                           */
/* ------------------------------------------------------------------ */
__global__ void zero_deg_kernel()
{
    int i = blockIdx.x * blockDim.x + threadIdx.x;
    if (i < RN) g_deg[i] = 0;
}

__global__ void count_kernel(const void* __restrict__ ei)
{
    int i = blockIdx.x * blockDim.x + threadIdx.x;
    if (i >= TOTE) return;
    const int is64 = g_is64;
    int r = i / NEDGE;
    int e = i % NEDGE;
    int dst = load_idx(ei, is64, (size_t)r * 2 * NEDGE + NEDGE + e);
    atomicAdd(&g_deg[r * N_NODES + dst], 1);
}

#define SCH 1024
__global__ void scan1_kernel()
{
    __shared__ int s[256];
    const int b = blockIdx.x, t = threadIdx.x;
    const int base = b * SCH + t * 4;
    int v[4], sum = 0;
#pragma unroll
    for (int i = 0; i < 4; i++) {
        int idx = base + i;
        v[i] = (idx < RN) ? g_deg[idx] : 0;
        sum += v[i];
    }
    s[t] = sum;
    __syncthreads();
    for (int o = 1; o < 256; o <<= 1) {
        int xv = (t >= o) ? s[t - o] : 0;
        __syncthreads();
        s[t] += xv;
        __syncthreads();
    }
    int run = s[t] - sum;
    if (t == 255) g_part[b] = s[t];
#pragma unroll
    for (int i = 0; i < 4; i++) {
        int idx = base + i;
        if (idx < RN) g_off[idx] = run;
        run += v[i];
    }
}

__global__ void scan2_kernel(int nb)
{
    __shared__ int s[256];
    const int t = threadIdx.x;
    int v = (t < nb) ? g_part[t] : 0;
    s[t] = v;
    __syncthreads();
    for (int o = 1; o < 256; o <<= 1) {
        int xv = (t >= o) ? s[t - o] : 0;
        __syncthreads();
        s[t] += xv;
        __syncthreads();
    }
    g_part[t] = s[t] - v;
}

__global__ void scan3_kernel()
{
    int i = blockIdx.x * blockDim.x + threadIdx.x;
    if (i < RN) {
        int v = g_off[i] + g_part[i / SCH];
        g_off[i] = v;
        g_cur[i] = v;
    }
    if (i == 0) g_off[RN] = TOTE;
}

__global__ void fill_kernel(const void* __restrict__ ei)
{
    int i = blockIdx.x * blockDim.x + threadIdx.x;
    if (i >= TOTE) return;
    const int is64 = g_is64;
    int r = i / NEDGE;
    int e = i % NEDGE;
    int src = load_idx(ei, is64, (size_t)r * 2 * NEDGE + e);
    int dst = load_idx(ei, is64, (size_t)r * 2 * NEDGE + NEDGE + e);
    int pos = atomicAdd(&g_cur[r * N_NODES + dst], 1);
    if (pos >= 0 && pos < TOTE) g_adj[pos] = src;
}

/* ------------------------------------------------------------------ */
/* GAT aggregation: one warp per (r,n)                                 */
/* ------------------------------------------------------------------ */
#define ACAP 64
__device__ __forceinline__ float lrelu(float v) { return v > 0.f ? v : 0.2f * v; }

__global__ void agg_kernel(const float* __restrict__ gat_bias)
{
    __shared__ float pbuf[4][ACAP][3];
    __shared__ int   sbuf[4][ACAP];

    const int w    = threadIdx.x >> 5;
    const int lane = threadIdx.x & 31;
    const int item = blockIdx.x * 4 + w;
    if (item >= RN) return;
    const int r = item / N_NODES;
    const int n = item % N_NODES;

    const int off0 = g_off[r * N_NODES + n];
    const int deg  = g_off[r * N_NODES + n + 1] - off0;
    const int tot  = deg + 1;

    const float ad0 = g_ad[(n * NREL + r) * HEADS + 0];
    const float ad1 = g_ad[(n * NREL + r) * HEADS + 1];
    const float ad2 = g_ad[(n * NREL + r) * HEADS + 2];

    float m0 = -1e30f, m1 = -1e30f, m2 = -1e30f;
    for (int base = 0; base < tot; base += 32) {
        int i = base + lane;
        if (i < tot) {
            int src = (i < deg) ? g_adj[off0 + i] : n;
            const float* as = &g_as[(src * NREL + r) * HEADS];
            m0 = fmaxf(m0, lrelu(as[0] + ad0));
            m1 = fmaxf(m1, lrelu(as[1] + ad1));
            m2 = fmaxf(m2, lrelu(as[2] + ad2));
        }
    }
#pragma unroll
    for (int o = 16; o > 0; o >>= 1) {
        m0 = fmaxf(m0, __shfl_xor_sync(0xffffffffu, m0, o));
        m1 = fmaxf(m1, __shfl_xor_sync(0xffffffffu, m1, o));
        m2 = fmaxf(m2, __shfl_xor_sync(0xffffffffu, m2, o));
    }

    float z0 = 0.f, z1 = 0.f, z2 = 0.f;
    for (int base = 0; base < tot; base += 32) {
        int i = base + lane;
        if (i < tot) {
            int src = (i < deg) ? g_adj[off0 + i] : n;
            const float* as = &g_as[(src * NREL + r) * HEADS];
            z0 += expf(lrelu(as[0] + ad0) - m0);
            z1 += expf(lrelu(as[1] + ad1) - m1);
            z2 += expf(lrelu(as[2] + ad2) - m2);
        }
    }
#pragma unroll
    for (int o = 16; o > 0; o >>= 1) {
        z0 += __shfl_xor_sync(0xffffffffu, z0, o);
        z1 += __shfl_xor_sync(0xffffffffu, z1, o);
        z2 += __shfl_xor_sync(0xffffffffu, z2, o);
    }
    const float iv0 = 1.f / (z0 + 1e-16f);
    const float iv1 = 1.f / (z1 + 1e-16f);
    const float iv2 = 1.f / (z2 + 1e-16f);

    float acc[12];
#pragma unroll
    for (int k = 0; k < 12; k++) acc[k] = 0.f;

    for (int c0 = 0; c0 < tot; c0 += ACAP) {
        const int clen = min(ACAP, tot - c0);
        for (int base = 0; base < clen; base += 32) {
            int i = base + lane;
            if (i < clen) {
                int gi  = c0 + i;
                int src = (gi < deg) ? g_adj[off0 + gi] : n;
                sbuf[w][i] = src;
                const float* as = &g_as[(src * NREL + r) * HEADS];
                pbuf[w][i][0] = expf(lrelu(as[0] + ad0) - m0) * iv0;
                pbuf[w][i][1] = expf(lrelu(as[1] + ad1) - m1) * iv1;
                pbuf[w][i][2] = expf(lrelu(as[2] + ad2) - m2) * iv2;
            }
        }
        __syncwarp();
        for (int j = 0; j < clen; j++) {
            const int   src = sbuf[w][j];
            const float a0  = pbuf[w][j][0];
            const float a1  = pbuf[w][j][1];
            const float a2  = pbuf[w][j][2];
            const float* xr = &g_xp[(size_t)src * XPC + r * HC];
#pragma unroll
            for (int k = 0; k < 12; k++) {
                float al = (k < 4) ? a0 : ((k < 8) ? a1 : a2);
                acc[k] = fmaf(al, xr[lane + 32 * k], acc[k]);
            }
        }
        __syncwarp();
    }

    const float* bp = &gat_bias[r * HC];
    float* op = &g_gout[((size_t)n * NREL + r) * HC];
#pragma unroll
    for (int k = 0; k < 12; k++) {
        int c = lane + 32 * k;
        op[c] = fmaxf(acc[k] + bp[c], 0.f);
    }
}

/* ------------------------------------------------------------------ */
extern "C" void kernel_launch(void* const* d_in, const int* in_sizes, int n_in,
                              void* d_out, int out_size)
{
    const float* x        = (const float*)d_in[0];
    const float* theta    = (const float*)d_in[1];
    const float* att_src  = (const float*)d_in[2];
    const float* att_dst  = (const float*)d_in[3];
    const float* gat_bias = (const float*)d_in[4];
    const float* W_sem    = (const float*)d_in[5];
    const float* b_sem    = (const float*)d_in[6];
    const float* q_sem    = (const float*)d_in[7];
    const float* mgx      = (const float*)d_in[8];
    const float* gsrc     = (const float*)d_in[9];
    const float* gdst     = (const float*)d_in[10];
    const void*  ei       = d_in[11];
    float* out = (float*)d_out;

    /* 0. edge_index dtype detection (int32 vs int64) */
    detect_kernel<<<1, 32>>>((const int*)ei);

    /* 1. bf16-split operands, then mma.sync (HMMA) GEMM1 */
    split_x_kernel<<<(N_NODES * IN_CH + 255) / 256, 256>>>(x);
    split_theta_kernel<<<(XPC * IN_CH + 255) / 256, 256>>>(theta);
    split_wsem_kernel<<<(SEMD * HC + 255) / 256, 256>>>(W_sem);
    gemm1_mma_kernel<<<dim3(XPC / 128, (N_NODES + 127) / 128), 256>>>();

    /* 2. attention logit components */
    asd_kernel<<<(N_NODES * NREL * HEADS + 3) / 4, 128>>>(att_src, att_dst);

    /* 3. CSR build (group edges by dst) */
    zero_deg_kernel<<<(RN + 255) / 256, 256>>>();
    count_kernel<<<(TOTE + 255) / 256, 256>>>(ei);
    scan1_kernel<<<(RN + SCH - 1) / SCH, 256>>>();
    scan2_kernel<<<1, 256>>>((RN + SCH - 1) / SCH);
    scan3_kernel<<<(RN + 255) / 256, 256>>>();
    fill_kernel<<<(TOTE + 255) / 256, 256>>>(ei);

    /* 4. per-(relation,node) GAT softmax + aggregate */
    agg_kernel<<<RN / 4, 128>>>(gat_bias);

    /* 5. semantic attention: HMMA score GEMM + softmax combine */
    sem_score_kernel<<<(RN + 127) / 128, 256>>>(b_sem, q_sem);
    sem_final_kernel<<<(N_NODES + 3) / 4, 128>>>(mgx, gsrc, gdst, out);
}

// round 12
// speedup vs baseline: 4.9596x; 1.1310x over previous
#include <cuda_runtime.h>
#include <cuda_bf16.h>
#include <math.h>
#include <stdint.h>

#define N_NODES 50000
#define IN_CH   256
#define HEADS   3
#define OUT_C   128
#define HC      384
#define NREL    3
#define NEDGE   400000
#define SEMD    128
#define RN      (NREL * N_NODES)     /* 150000 */
#define TOTE    (NREL * NEDGE)       /* 1200000 */
#define XPC     (NREL * HC)          /* 1152 */

/* ------------------------------------------------------------------ */
/* scratch (static device globals — no runtime allocation)             */
/* ------------------------------------------------------------------ */
__device__ float g_xp  [(size_t)N_NODES * XPC];   /* x @ theta, [N][R*HC] */
__device__ float g_gout[(size_t)N_NODES * XPC];   /* relu(gat+bias), [N][R][HC] */
__device__ float g_as  [N_NODES * NREL * HEADS];
__device__ float g_ad  [N_NODES * NREL * HEADS];
__device__ int   g_deg [RN];
__device__ int   g_off [RN + 1];
__device__ int   g_cur [RN];
__device__ int   g_adj [TOTE];
__device__ int   g_part[256];
__device__ int   g_is64;

/* bf16 split operands for tensor-core GEMM1 */
__device__ __nv_bfloat16 g_xh[(size_t)N_NODES * IN_CH];
__device__ __nv_bfloat16 g_xl[(size_t)N_NODES * IN_CH];
__device__ __nv_bfloat16 g_th[(size_t)XPC * IN_CH];   /* theta^T [j][k] hi */
__device__ __nv_bfloat16 g_tl[(size_t)XPC * IN_CH];   /* theta^T [j][k] lo */

/* W_sem^T bf16 split: [s=128][d=384] */
__device__ __nv_bfloat16 g_wh[SEMD * HC];
__device__ __nv_bfloat16 g_wl[SEMD * HC];

/* per-(n,r) semantic scores, 2 partial slabs (warp-col halves) */
__device__ float g_scoreP[2][RN];

/* ------------------------------------------------------------------ */
/* edge_index dtype detection (JAX x64-disabled => int32)              */
/* ------------------------------------------------------------------ */
__global__ void detect_kernel(const int* __restrict__ ei32)
{
    if (threadIdx.x == 0) {
        int is64 = 1;
        for (int i = 1; i < 128; i += 2)
            if (ei32[i] != 0) { is64 = 0; break; }
        g_is64 = is64;
    }
}

__device__ __forceinline__ int load_idx(const void* ei, int is64, size_t pos)
{
    int v = is64 ? (int)((const long long*)ei)[pos]
                 : ((const int*)ei)[pos];
    if ((unsigned)v >= (unsigned)N_NODES) v = 0;
    return v;
}

/* ------------------------------------------------------------------ */
/* bf16 split preprocessing                                            */
/* ------------------------------------------------------------------ */
__global__ void split_x_kernel(const float* __restrict__ x)
{
    int i = blockIdx.x * blockDim.x + threadIdx.x;
    if (i >= N_NODES * IN_CH) return;
    float v = x[i];
    __nv_bfloat16 h = __float2bfloat16(v);
    g_xh[i] = h;
    g_xl[i] = __float2bfloat16(v - __bfloat162float(h));
}

__global__ void split_theta_kernel(const float* __restrict__ theta)
{
    int i = blockIdx.x * blockDim.x + threadIdx.x;
    if (i >= XPC * IN_CH) return;
    int j = i / IN_CH;          /* output col 0..1151 */
    int k = i % IN_CH;
    int r  = j / HC;
    int hc = j % HC;
    float v = theta[((size_t)r * IN_CH + k) * HC + hc];
    __nv_bfloat16 h = __float2bfloat16(v);
    g_th[i] = h;
    g_tl[i] = __float2bfloat16(v - __bfloat162float(h));
}

__global__ void split_wsem_kernel(const float* __restrict__ W_sem)
{
    int i = blockIdx.x * blockDim.x + threadIdx.x;
    if (i >= SEMD * HC) return;
    int s = i / HC;
    int d = i % HC;
    float v = W_sem[(size_t)d * SEMD + s];
    __nv_bfloat16 h = __float2bfloat16(v);
    g_wh[i] = h;
    g_wl[i] = __float2bfloat16(v - __bfloat162float(h));
}

/* ------------------------------------------------------------------ */
/* mma.sync / ldmatrix helpers                                         */
/* ------------------------------------------------------------------ */
__device__ __forceinline__ void mma16816(float* c, const uint32_t* a,
                                         const uint32_t* b)
{
    asm volatile(
        "mma.sync.aligned.m16n8k16.row.col.f32.bf16.bf16.f32 "
        "{%0,%1,%2,%3}, {%4,%5,%6,%7}, {%8,%9}, {%0,%1,%2,%3};"
        : "+f"(c[0]), "+f"(c[1]), "+f"(c[2]), "+f"(c[3])
        : "r"(a[0]), "r"(a[1]), "r"(a[2]), "r"(a[3]),
          "r"(b[0]), "r"(b[1]));
}

__device__ __forceinline__ void ldsm_x4(uint32_t* r, uint32_t addr)
{
    asm volatile("ldmatrix.sync.aligned.m8n8.x4.shared.b16 {%0,%1,%2,%3}, [%4];"
                 : "=r"(r[0]), "=r"(r[1]), "=r"(r[2]), "=r"(r[3])
                 : "r"(addr));
}

__device__ __forceinline__ uint32_t cvta_s(const void* p)
{
    return (uint32_t)__cvta_generic_to_shared(p);
}

__device__ __forceinline__ uint32_t pack_bf2(float a, float b)
{
    uint32_t lo = (uint32_t)__bfloat16_as_ushort(__float2bfloat16(a));
    uint32_t hi = (uint32_t)__bfloat16_as_ushort(__float2bfloat16(b));
    return (hi << 16) | lo;
}

__device__ __forceinline__ float fast_tanh(float x)
{
    float e = __expf(2.f * x);
    return 1.f - __fdividef(2.f, e + 1.f);
}

/* ------------------------------------------------------------------ */
/* GEMM1 via mma.sync bf16 (HMMA): 128x128 block, 8 warps, warp 32x64  */
/* 2-term split: D = Ah*Bh + Ah*Bl + Al*Bh, fp32 accumulators          */
/* fragments loaded via ldmatrix.x4 (conflict-free with LDA=40)        */
/* ------------------------------------------------------------------ */
#define BK   32
#define LDA  40   /* padded bf16 row stride for smem tiles */

__global__ __launch_bounds__(256, 2)
void gemm1_mma_kernel()
{
    __shared__ __nv_bfloat16 sAh[128][LDA];
    __shared__ __nv_bfloat16 sAl[128][LDA];
    __shared__ __nv_bfloat16 sBh[128][LDA];
    __shared__ __nv_bfloat16 sBl[128][LDA];

    const int tid   = threadIdx.x;
    const int wid   = tid >> 5;
    const int lane  = tid & 31;
    const int wm    = wid & 3;
    const int wn    = wid >> 2;
    const int row0  = blockIdx.y * 128;
    const int col0  = blockIdx.x * 128;

    float c[2][8][4];
#pragma unroll
    for (int i = 0; i < 2; i++)
#pragma unroll
        for (int j = 0; j < 8; j++)
#pragma unroll
            for (int q = 0; q < 4; q++) c[i][j][q] = 0.f;

    const int laA_r = lane & 15;
    const int laA_k = (lane >> 4) * 8;
    uint32_t aAH[2], aAL[2];
#pragma unroll
    for (int i = 0; i < 2; i++) {
        const int rr = wm * 32 + i * 16 + laA_r;
        aAH[i] = cvta_s(&sAh[rr][laA_k]);
        aAL[i] = cvta_s(&sAl[rr][laA_k]);
    }
    const int laB_n = (lane & 7) + ((lane >> 4) << 3);
    const int laB_k = ((lane >> 3) & 1) * 8;
    uint32_t aBH[4], aBL[4];
#pragma unroll
    for (int j2 = 0; j2 < 4; j2++) {
        const int nr = wn * 64 + j2 * 16 + laB_n;
        aBH[j2] = cvta_s(&sBh[nr][laB_k]);
        aBL[j2] = cvta_s(&sBl[nr][laB_k]);
    }

    const int sr = tid >> 1;
    const int sc = (tid & 1) * 16;

    for (int kc = 0; kc < IN_CH; kc += BK) {
        __syncthreads();
        {
            const int m = row0 + sr;
            uint4 vh = make_uint4(0u, 0u, 0u, 0u), vl = vh;
            uint4 wh = vh, wl = vh;
            if (m < N_NODES) {
                const size_t gi = ((size_t)m * IN_CH + kc + sc) >> 3;
                vh = ((const uint4*)g_xh)[gi];
                vl = ((const uint4*)g_xl)[gi];
                wh = ((const uint4*)g_xh)[gi + 1];
                wl = ((const uint4*)g_xl)[gi + 1];
            }
            *(uint4*)&sAh[sr][sc]     = vh;
            *(uint4*)&sAl[sr][sc]     = vl;
            *(uint4*)&sAh[sr][sc + 8] = wh;
            *(uint4*)&sAl[sr][sc + 8] = wl;

            const size_t bgi = ((size_t)(col0 + sr) * IN_CH + kc + sc) >> 3;
            uint4 bh = ((const uint4*)g_th)[bgi];
            uint4 bl = ((const uint4*)g_tl)[bgi];
            uint4 bh2 = ((const uint4*)g_th)[bgi + 1];
            uint4 bl2 = ((const uint4*)g_tl)[bgi + 1];
            *(uint4*)&sBh[sr][sc]     = bh;
            *(uint4*)&sBl[sr][sc]     = bl;
            *(uint4*)&sBh[sr][sc + 8] = bh2;
            *(uint4*)&sBl[sr][sc + 8] = bl2;
        }
        __syncthreads();

#pragma unroll
        for (int ks = 0; ks < BK; ks += 16) {
            const uint32_t koff = ks * 2;   /* bytes */
            uint32_t ah[2][4], al[2][4];
#pragma unroll
            for (int i = 0; i < 2; i++) {
                ldsm_x4(ah[i], aAH[i] + koff);
                ldsm_x4(al[i], aAL[i] + koff);
            }
            uint32_t bh[8][2], bl[8][2];
#pragma unroll
            for (int j2 = 0; j2 < 4; j2++) {
                ldsm_x4(&bh[2 * j2][0], aBH[j2] + koff);
                ldsm_x4(&bl[2 * j2][0], aBL[j2] + koff);
            }
#pragma unroll
            for (int i = 0; i < 2; i++)
#pragma unroll
                for (int j = 0; j < 8; j++) {
                    mma16816(c[i][j], ah[i], bh[j]);
                    mma16816(c[i][j], ah[i], bl[j]);
                    mma16816(c[i][j], al[i], bh[j]);
                }
        }
    }

    const int crow = lane >> 2;
    const int ccol = (lane & 3) * 2;
#pragma unroll
    for (int i = 0; i < 2; i++) {
        const int mbase = row0 + wm * 32 + i * 16;
#pragma unroll
        for (int j = 0; j < 8; j++) {
            const int nbase = col0 + wn * 64 + j * 8 + ccol;
            const int m0 = mbase + crow;
            const int m1 = m0 + 8;
            if (m0 < N_NODES)
                *(float2*)&g_xp[(size_t)m0 * XPC + nbase] =
                    make_float2(c[i][j][0], c[i][j][1]);
            if (m1 < N_NODES)
                *(float2*)&g_xp[(size_t)m1 * XPC + nbase] =
                    make_float2(c[i][j][2], c[i][j][3]);
        }
    }
}

/* ------------------------------------------------------------------ */
/* semantic GEMM via mma.sync (ldmatrix fragments), fused tanh epilog  */
/* ------------------------------------------------------------------ */
__global__ __launch_bounds__(256, 2)
void sem_score_kernel(const float* __restrict__ b_sem,
                      const float* __restrict__ q_sem)
{
    __shared__ __nv_bfloat16 sAh[128][LDA];
    __shared__ __nv_bfloat16 sAl[128][LDA];
    __shared__ __nv_bfloat16 sBh[128][LDA];
    __shared__ __nv_bfloat16 sBl[128][LDA];

    const int tid   = threadIdx.x;
    const int wid   = tid >> 5;
    const int lane  = tid & 31;
    const int wm    = wid & 3;
    const int wn    = wid >> 2;
    const int row0  = blockIdx.x * 128;

    float c[2][8][4];
#pragma unroll
    for (int i = 0; i < 2; i++)
#pragma unroll
        for (int j = 0; j < 8; j++)
#pragma unroll
            for (int q = 0; q < 4; q++) c[i][j][q] = 0.f;

    const int laA_r = lane & 15;
    const int laA_k = (lane >> 4) * 8;
    uint32_t aAH[2], aAL[2];
#pragma unroll
    for (int i = 0; i < 2; i++) {
        const int rr = wm * 32 + i * 16 + laA_r;
        aAH[i] = cvta_s(&sAh[rr][laA_k]);
        aAL[i] = cvta_s(&sAl[rr][laA_k]);
    }
    const int laB_n = (lane & 7) + ((lane >> 4) << 3);
    const int laB_k = ((lane >> 3) & 1) * 8;
    uint32_t aBH[4], aBL[4];
#pragma unroll
    for (int j2 = 0; j2 < 4; j2++) {
        const int nr = wn * 64 + j2 * 16 + laB_n;
        aBH[j2] = cvta_s(&sBh[nr][laB_k]);
        aBL[j2] = cvta_s(&sBl[nr][laB_k]);
    }

    const int sr = tid >> 1;
    const int sc = (tid & 1) * 16;

    for (int kc = 0; kc < HC; kc += BK) {
        __syncthreads();
        {
            /* A: split fp32 g_gout inline */
            const int m = row0 + sr;
#pragma unroll
            for (int t = 0; t < 4; t++) {
                float4 v = make_float4(0.f, 0.f, 0.f, 0.f);
                if (m < RN)
                    v = *(const float4*)&g_gout[(size_t)m * HC + kc + sc + t * 4];
                float hx = __bfloat162float(__float2bfloat16(v.x));
                float hy = __bfloat162float(__float2bfloat16(v.y));
                float hz = __bfloat162float(__float2bfloat16(v.z));
                float hw = __bfloat162float(__float2bfloat16(v.w));
                *(uint32_t*)&sAh[sr][sc + t * 4]     = pack_bf2(v.x, v.y);
                *(uint32_t*)&sAh[sr][sc + t * 4 + 2] = pack_bf2(v.z, v.w);
                *(uint32_t*)&sAl[sr][sc + t * 4]     = pack_bf2(v.x - hx, v.y - hy);
                *(uint32_t*)&sAl[sr][sc + t * 4 + 2] = pack_bf2(v.z - hz, v.w - hw);
            }
            /* B: W_sem^T hi/lo (pre-split, [s][d]) */
            const size_t bgi = ((size_t)sr * HC + kc + sc) >> 3;
            *(uint4*)&sBh[sr][sc]     = ((const uint4*)g_wh)[bgi];
            *(uint4*)&sBl[sr][sc]     = ((const uint4*)g_wl)[bgi];
            *(uint4*)&sBh[sr][sc + 8] = ((const uint4*)g_wh)[bgi + 1];
            *(uint4*)&sBl[sr][sc + 8] = ((const uint4*)g_wl)[bgi + 1];
        }
        __syncthreads();

#pragma unroll
        for (int ks = 0; ks < BK; ks += 16) {
            const uint32_t koff = ks * 2;
            uint32_t ah[2][4], al[2][4];
#pragma unroll
            for (int i = 0; i < 2; i++) {
                ldsm_x4(ah[i], aAH[i] + koff);
                ldsm_x4(al[i], aAL[i] + koff);
            }
            uint32_t bh[8][2], bl[8][2];
#pragma unroll
            for (int j2 = 0; j2 < 4; j2++) {
                ldsm_x4(&bh[2 * j2][0], aBH[j2] + koff);
                ldsm_x4(&bl[2 * j2][0], aBL[j2] + koff);
            }
#pragma unroll
            for (int i = 0; i < 2; i++)
#pragma unroll
                for (int j = 0; j < 8; j++) {
                    mma16816(c[i][j], ah[i], bh[j]);
                    mma16816(c[i][j], ah[i], bl[j]);
                    mma16816(c[i][j], al[i], bh[j]);
                }
        }
    }

    /* fused epilogue: tanh(w+b)*q, reduce over this warp's 64 cols */
    const int crow = lane >> 2;
    const int ccol = (lane & 3) * 2;
    float rs[2][2] = {{0.f, 0.f}, {0.f, 0.f}};
#pragma unroll
    for (int i = 0; i < 2; i++)
#pragma unroll
        for (int j = 0; j < 8; j++) {
            const int col = wn * 64 + j * 8 + ccol;
            const float b0 = b_sem[col],     b1 = b_sem[col + 1];
            const float q0 = q_sem[col],     q1 = q_sem[col + 1];
            rs[i][0] += fast_tanh(c[i][j][0] + b0) * q0
                      + fast_tanh(c[i][j][1] + b1) * q1;
            rs[i][1] += fast_tanh(c[i][j][2] + b0) * q0
                      + fast_tanh(c[i][j][3] + b1) * q1;
        }
#pragma unroll
    for (int o = 1; o <= 2; o <<= 1) {
#pragma unroll
        for (int i = 0; i < 2; i++) {
            rs[i][0] += __shfl_xor_sync(0xffffffffu, rs[i][0], o);
            rs[i][1] += __shfl_xor_sync(0xffffffffu, rs[i][1], o);
        }
    }
    if ((lane & 3) == 0) {
#pragma unroll
        for (int i = 0; i < 2; i++)
#pragma unroll
            for (int h = 0; h < 2; h++) {
                const int row = row0 + wm * 32 + i * 16 + h * 8 + crow;
                if (row < RN) g_scoreP[wn][row] = rs[i][h];
            }
    }
}

/* ------------------------------------------------------------------ */
/* sem_final: softmax over 3 relation scores + weighted combine        */
/* ------------------------------------------------------------------ */
__global__ void sem_final_kernel(const float* __restrict__ mgx,
                                 const float* __restrict__ gsrc,
                                 const float* __restrict__ gdst,
                                 float* __restrict__ out)
{
    const int node = blockIdx.x * 4 + (threadIdx.x >> 5);
    const int lane = threadIdx.x & 31;
    if (node >= N_NODES) return;

    const int rb = node * NREL;
    const float S0 = g_scoreP[0][rb + 0] + g_scoreP[1][rb + 0];
    const float S1 = g_scoreP[0][rb + 1] + g_scoreP[1][rb + 1];
    const float S2 = g_scoreP[0][rb + 2] + g_scoreP[1][rb + 2];

    const float bm = fmaxf(S0, fmaxf(S1, S2));
    const float e0 = expf(S0 - bm), e1 = expf(S1 - bm), e2 = expf(S2 - bm);
    const float iv = 1.f / (e0 + e1 + e2);
    const float b0 = e0 * iv, b1 = e1 * iv, b2 = e2 * iv;

    const float* gp = &g_gout[(size_t)node * XPC];
#pragma unroll
    for (int t = 0; t < 3; t++) {
        const int cidx = lane * 4 + t * 128;
        float4 v0 = *(const float4*)&gp[cidx];
        float4 v1 = *(const float4*)&gp[HC + cidx];
        float4 v2 = *(const float4*)&gp[2 * HC + cidx];
        float4 mg = *(const float4*)&mgx[cidx];
        float4 gs = *(const float4*)&gsrc[cidx];
        float4 gd = *(const float4*)&gdst[cidx];
        float4 o;
        o.x = b0 * v0.x + b1 * v1.x + b2 * v2.x + mg.x * (gs.x + gd.x);
        o.y = b0 * v0.y + b1 * v1.y + b2 * v2.y + mg.y * (gs.y + gd.y);
        o.z = b0 * v0.z + b1 * v1.z + b2 * v2.z + mg.z * (gs.z + gd.z);
        o.w = b0 * v0.w + b1 * v1.w + b2 * v2.w + mg.w * (gs.w + gd.w);
        *(float4*)&out[(size_t)node * HC + cidx] = o;
    }
}

/* ------------------------------------------------------------------ */
/* per-node attention logits: a_s/a_d[n][r][h] = sum_c xp*att          */
/* ------------------------------------------------------------------ */
__global__ void asd_kernel(const float* __restrict__ att_src,
                           const float* __restrict__ att_dst)
{
    const int wid  = threadIdx.x >> 5;
    const int lane = threadIdx.x & 31;
    const int item = blockIdx.x * 4 + wid;
    if (item >= N_NODES * NREL * HEADS) return;
    const int n  = item / (NREL * HEADS);
    const int rh = item % (NREL * HEADS);
    const int r  = rh / HEADS;
    const int h  = rh % HEADS;

    const float4 xv = *(const float4*)&g_xp[(size_t)n * XPC + r * HC + h * OUT_C + lane * 4];
    const float4 sv = *(const float4*)&att_src[(size_t)(r * HEADS + h) * OUT_C + lane * 4];
    const float4 dv = *(const float4*)&att_dst[(size_t)(r * HEADS + h) * OUT_C + lane * 4];

    float ds = xv.x * sv.x + xv.y * sv.y + xv.z * sv.z + xv.w * sv.w;
    float dd = xv.x * dv.x + xv.y * dv.y + xv.z * dv.z + xv.w * dv.w;
#pragma unroll
    for (int o = 16; o > 0; o >>= 1) {
        ds += __shfl_xor_sync(0xffffffffu, ds, o);
        dd += __shfl_xor_sync(0xffffffffu, dd, o);
    }
    if (lane == 0) {
        g_as[item] = ds;
        g_ad[item] = dd;
    }
}

/* ------------------------------------------------------------------ */
/* CSR build                                                           */
/* ------------------------------------------------------------------ */
__global__ void zero_deg_kernel()
{
    int i = blockIdx.x * blockDim.x + threadIdx.x;
    if (i < RN) g_deg[i] = 0;
}

__global__ void count_kernel(const void* __restrict__ ei)
{
    int i = blockIdx.x * blockDim.x + threadIdx.x;
    if (i >= TOTE) return;
    const int is64 = g_is64;
    int r = i / NEDGE;
    int e = i % NEDGE;
    int dst = load_idx(ei, is64, (size_t)r * 2 * NEDGE + NEDGE + e);
    atomicAdd(&g_deg[r * N_NODES + dst], 1);
}

#define SCH 1024
__global__ void scan1_kernel()
{
    __shared__ int s[256];
    const int b = blockIdx.x, t = threadIdx.x;
    const int base = b * SCH + t * 4;
    int v[4], sum = 0;
#pragma unroll
    for (int i = 0; i < 4; i++) {
        int idx = base + i;
        v[i] = (idx < RN) ? g_deg[idx] : 0;
        sum += v[i];
    }
    s[t] = sum;
    __syncthreads();
    for (int o = 1; o < 256; o <<= 1) {
        int xv = (t >= o) ? s[t - o] : 0;
        __syncthreads();
        s[t] += xv;
        __syncthreads();
    }
    int run = s[t] - sum;
    if (t == 255) g_part[b] = s[t];
#pragma unroll
    for (int i = 0; i < 4; i++) {
        int idx = base + i;
        if (idx < RN) g_off[idx] = run;
        run += v[i];
    }
}

__global__ void scan2_kernel(int nb)
{
    __shared__ int s[256];
    const int t = threadIdx.x;
    int v = (t < nb) ? g_part[t] : 0;
    s[t] = v;
    __syncthreads();
    for (int o = 1; o < 256; o <<= 1) {
        int xv = (t >= o) ? s[t - o] : 0;
        __syncthreads();
        s[t] += xv;
        __syncthreads();
    }
    g_part[t] = s[t] - v;
}

__global__ void scan3_kernel()
{
    int i = blockIdx.x * blockDim.x + threadIdx.x;
    if (i < RN) {
        int v = g_off[i] + g_part[i / SCH];
        g_off[i] = v;
        g_cur[i] = v;
    }
    if (i == 0) g_off[RN] = TOTE;
}

__global__ void fill_kernel(const void* __restrict__ ei)
{
    int i = blockIdx.x * blockDim.x + threadIdx.x;
    if (i >= TOTE) return;
    const int is64 = g_is64;
    int r = i / NEDGE;
    int e = i % NEDGE;
    int src = load_idx(ei, is64, (size_t)r * 2 * NEDGE + e);
    int dst = load_idx(ei, is64, (size_t)r * 2 * NEDGE + NEDGE + e);
    int pos = atomicAdd(&g_cur[r * N_NODES + dst], 1);
    if (pos >= 0 && pos < TOTE) g_adj[pos] = src;
}

/* ------------------------------------------------------------------ */
/* GAT aggregation: one warp per (r,n); single-exp two-phase softmax,  */
/* float4 gather. Unnormalized accumulate, scale by 1/(z+eps) at end.  */
/* ------------------------------------------------------------------ */
#define ACAP 64
__device__ __forceinline__ float lrelu(float v) { return v > 0.f ? v : 0.2f * v; }

__global__ void agg_kernel(const float* __restrict__ gat_bias)
{
    __shared__ float pbuf[4][ACAP][3];
    __shared__ int   sbuf[4][ACAP];

    const int w    = threadIdx.x >> 5;
    const int lane = threadIdx.x & 31;
    const int item = blockIdx.x * 4 + w;
    if (item >= RN) return;
    const int r = item / N_NODES;      /* relation-major -> L2 residency */
    const int n = item % N_NODES;

    const int off0 = g_off[r * N_NODES + n];
    const int deg  = g_off[r * N_NODES + n + 1] - off0;
    const int tot  = deg + 1;          /* + self loop */

    const float ad0 = g_ad[(n * NREL + r) * HEADS + 0];
    const float ad1 = g_ad[(n * NREL + r) * HEADS + 1];
    const float ad2 = g_ad[(n * NREL + r) * HEADS + 2];

    float4 acc[3];
#pragma unroll
    for (int k = 0; k < 3; k++) acc[k] = make_float4(0.f, 0.f, 0.f, 0.f);
    float z0 = 0.f, z1 = 0.f, z2 = 0.f;

    if (tot <= ACAP) {
        /* --- fast path: cache e-values in smem, single gather pass --- */
        for (int i = lane; i < tot; i += 32) {
            const int src = (i < deg) ? g_adj[off0 + i] : n;
            sbuf[w][i] = src;
            const float* as = &g_as[(src * NREL + r) * HEADS];
            pbuf[w][i][0] = lrelu(as[0] + ad0);
            pbuf[w][i][1] = lrelu(as[1] + ad1);
            pbuf[w][i][2] = lrelu(as[2] + ad2);
        }
        __syncwarp();
        float m0 = -1e30f, m1 = -1e30f, m2 = -1e30f;
        for (int i = lane; i < tot; i += 32) {
            m0 = fmaxf(m0, pbuf[w][i][0]);
            m1 = fmaxf(m1, pbuf[w][i][1]);
            m2 = fmaxf(m2, pbuf[w][i][2]);
        }
#pragma unroll
        for (int o = 16; o > 0; o >>= 1) {
            m0 = fmaxf(m0, __shfl_xor_sync(0xffffffffu, m0, o));
            m1 = fmaxf(m1, __shfl_xor_sync(0xffffffffu, m1, o));
            m2 = fmaxf(m2, __shfl_xor_sync(0xffffffffu, m2, o));
        }
        for (int i = lane; i < tot; i += 32) {
            const float p0 = expf(pbuf[w][i][0] - m0);
            const float p1 = expf(pbuf[w][i][1] - m1);
            const float p2 = expf(pbuf[w][i][2] - m2);
            pbuf[w][i][0] = p0;  z0 += p0;
            pbuf[w][i][1] = p1;  z1 += p1;
            pbuf[w][i][2] = p2;  z2 += p2;
        }
#pragma unroll
        for (int o = 16; o > 0; o >>= 1) {
            z0 += __shfl_xor_sync(0xffffffffu, z0, o);
            z1 += __shfl_xor_sync(0xffffffffu, z1, o);
            z2 += __shfl_xor_sync(0xffffffffu, z2, o);
        }
        __syncwarp();
        for (int j = 0; j < tot; j++) {
            const int   src = sbuf[w][j];
            const float a0  = pbuf[w][j][0];
            const float a1  = pbuf[w][j][1];
            const float a2  = pbuf[w][j][2];
            const float4* xr = (const float4*)&g_xp[(size_t)src * XPC + r * HC];
            const float4 x0 = xr[lane];
            const float4 x1 = xr[lane + 32];
            const float4 x2 = xr[lane + 64];
            acc[0].x = fmaf(a0, x0.x, acc[0].x);
            acc[0].y = fmaf(a0, x0.y, acc[0].y);
            acc[0].z = fmaf(a0, x0.z, acc[0].z);
            acc[0].w = fmaf(a0, x0.w, acc[0].w);
            acc[1].x = fmaf(a1, x1.x, acc[1].x);
            acc[1].y = fmaf(a1, x1.y, acc[1].y);
            acc[1].z = fmaf(a1, x1.z, acc[1].z);
            acc[1].w = fmaf(a1, x1.w, acc[1].w);
            acc[2].x = fmaf(a2, x2.x, acc[2].x);
            acc[2].y = fmaf(a2, x2.y, acc[2].y);
            acc[2].z = fmaf(a2, x2.z, acc[2].z);
            acc[2].w = fmaf(a2, x2.w, acc[2].w);
        }
    } else {
        /* --- general path: 3 passes, chunked --- */
        float m0 = -1e30f, m1 = -1e30f, m2 = -1e30f;
        for (int base = 0; base < tot; base += 32) {
            const int i = base + lane;
            if (i < tot) {
                const int src = (i < deg) ? g_adj[off0 + i] : n;
                const float* as = &g_as[(src * NREL + r) * HEADS];
                m0 = fmaxf(m0, lrelu(as[0] + ad0));
                m1 = fmaxf(m1, lrelu(as[1] + ad1));
                m2 = fmaxf(m2, lrelu(as[2] + ad2));
            }
        }
#pragma unroll
        for (int o = 16; o > 0; o >>= 1) {
            m0 = fmaxf(m0, __shfl_xor_sync(0xffffffffu, m0, o));
            m1 = fmaxf(m1, __shfl_xor_sync(0xffffffffu, m1, o));
            m2 = fmaxf(m2, __shfl_xor_sync(0xffffffffu, m2, o));
        }
        for (int c0 = 0; c0 < tot; c0 += ACAP) {
            const int clen = min(ACAP, tot - c0);
            for (int base = 0; base < clen; base += 32) {
                const int i = base + lane;
                if (i < clen) {
                    const int gi  = c0 + i;
                    const int src = (gi < deg) ? g_adj[off0 + gi] : n;
                    sbuf[w][i] = src;
                    const float* as = &g_as[(src * NREL + r) * HEADS];
                    const float p0 = expf(lrelu(as[0] + ad0) - m0);
                    const float p1 = expf(lrelu(as[1] + ad1) - m1);
                    const float p2 = expf(lrelu(as[2] + ad2) - m2);
                    pbuf[w][i][0] = p0;  z0 += p0;
                    pbuf[w][i][1] = p1;  z1 += p1;
                    pbuf[w][i][2] = p2;  z2 += p2;
                }
            }
            __syncwarp();
            for (int j = 0; j < clen; j++) {
                const int   src = sbuf[w][j];
                const float a0  = pbuf[w][j][0];
                const float a1  = pbuf[w][j][1];
                const float a2  = pbuf[w][j][2];
                const float4* xr = (const float4*)&g_xp[(size_t)src * XPC + r * HC];
                const float4 x0 = xr[lane];
                const float4 x1 = xr[lane + 32];
                const float4 x2 = xr[lane + 64];
                acc[0].x = fmaf(a0, x0.x, acc[0].x);
                acc[0].y = fmaf(a0, x0.y, acc[0].y);
                acc[0].z = fmaf(a0, x0.z, acc[0].z);
                acc[0].w = fmaf(a0, x0.w, acc[0].w);
                acc[1].x = fmaf(a1, x1.x, acc[1].x);
                acc[1].y = fmaf(a1, x1.y, acc[1].y);
                acc[1].z = fmaf(a1, x1.z, acc[1].z);
                acc[1].w = fmaf(a1, x1.w, acc[1].w);
                acc[2].x = fmaf(a2, x2.x, acc[2].x);
                acc[2].y = fmaf(a2, x2.y, acc[2].y);
                acc[2].z = fmaf(a2, x2.z, acc[2].z);
                acc[2].w = fmaf(a2, x2.w, acc[2].w);
            }
            __syncwarp();
        }
#pragma unroll
        for (int o = 16; o > 0; o >>= 1) {
            z0 += __shfl_xor_sync(0xffffffffu, z0, o);
            z1 += __shfl_xor_sync(0xffffffffu, z1, o);
            z2 += __shfl_xor_sync(0xffffffffu, z2, o);
        }
    }

    const float iv0 = 1.f / (z0 + 1e-16f);
    const float iv1 = 1.f / (z1 + 1e-16f);
    const float iv2 = 1.f / (z2 + 1e-16f);

    /* epilogue: scale, +bias, relu, store node-major [n][r][hc] */
    const float4* bp4 = (const float4*)&gat_bias[r * HC];
    float4* op4 = (float4*)&g_gout[((size_t)n * NREL + r) * HC];
    const float ivs[3] = {iv0, iv1, iv2};
#pragma unroll
    for (int k = 0; k < 3; k++) {
        const float4 b = bp4[lane + 32 * k];
        float4 v;
        v.x = fmaxf(fmaf(acc[k].x, ivs[k], b.x), 0.f);
        v.y = fmaxf(fmaf(acc[k].y, ivs[k], b.y), 0.f);
        v.z = fmaxf(fmaf(acc[k].z, ivs[k], b.z), 0.f);
        v.w = fmaxf(fmaf(acc[k].w, ivs[k], b.w), 0.f);
        op4[lane + 32 * k] = v;
    }
}

/* ------------------------------------------------------------------ */
extern "C" void kernel_launch(void* const* d_in, const int* in_sizes, int n_in,
                              void* d_out, int out_size)
{
    const float* x        = (const float*)d_in[0];
    const float* theta    = (const float*)d_in[1];
    const float* att_src  = (const float*)d_in[2];
    const float* att_dst  = (const float*)d_in[3];
    const float* gat_bias = (const float*)d_in[4];
    const float* W_sem    = (const float*)d_in[5];
    const float* b_sem    = (const float*)d_in[6];
    const float* q_sem    = (const float*)d_in[7];
    const float* mgx      = (const float*)d_in[8];
    const float* gsrc     = (const float*)d_in[9];
    const float* gdst     = (const float*)d_in[10];
    const void*  ei       = d_in[11];
    float* out = (float*)d_out;

    /* 0. edge_index dtype detection (int32 vs int64) */
    detect_kernel<<<1, 32>>>((const int*)ei);

    /* 1. bf16-split operands, then mma.sync (HMMA) GEMM1 */
    split_x_kernel<<<(N_NODES * IN_CH + 255) / 256, 256>>>(x);
    split_theta_kernel<<<(XPC * IN_CH + 255) / 256, 256>>>(theta);
    split_wsem_kernel<<<(SEMD * HC + 255) / 256, 256>>>(W_sem);
    gemm1_mma_kernel<<<dim3(XPC / 128, (N_NODES + 127) / 128), 256>>>();

    /* 2. attention logit components */
    asd_kernel<<<(N_NODES * NREL * HEADS + 3) / 4, 128>>>(att_src, att_dst);

    /* 3. CSR build (group edges by dst) */
    zero_deg_kernel<<<(RN + 255) / 256, 256>>>();
    count_kernel<<<(TOTE + 255) / 256, 256>>>(ei);
    scan1_kernel<<<(RN + SCH - 1) / SCH, 256>>>();
    scan2_kernel<<<1, 256>>>((RN + SCH - 1) / SCH);
    scan3_kernel<<<(RN + 255) / 256, 256>>>();
    fill_kernel<<<(TOTE + 255) / 256, 256>>>(ei);

    /* 4. per-(relation,node) GAT softmax + aggregate */
    agg_kernel<<<RN / 4, 128>>>(gat_bias);

    /* 5. semantic attention: HMMA score GEMM + softmax combine */
    sem_score_kernel<<<(RN + 127) / 128, 256>>>(b_sem, q_sem);
    sem_final_kernel<<<(N_NODES + 3) / 4, 128>>>(mgx, gsrc, gdst, out);
}

// round 14
// speedup vs baseline: 5.3925x; 1.0873x over previous
#include <cuda_runtime.h>
#include <cuda_bf16.h>
#include <math.h>
#include <stdint.h>

#define N_NODES 50000
#define IN_CH   256
#define HEADS   3
#define OUT_C   128
#define HC      384
#define NREL    3
#define NEDGE   400000
#define SEMD    128
#define RN      (NREL * N_NODES)     /* 150000 */
#define TOTE    (NREL * NEDGE)       /* 1200000 */
#define XPC     (NREL * HC)          /* 1152 */

/* ------------------------------------------------------------------ */
/* scratch (static device globals — no runtime allocation)             */
/* ------------------------------------------------------------------ */
__device__ float g_xp  [(size_t)N_NODES * XPC];   /* x @ theta, [N][R*HC] */
__device__ float g_gout[(size_t)N_NODES * XPC];   /* relu(gat+bias), [N][R][HC] */
__device__ float g_as  [N_NODES * NREL * HEADS];
__device__ float g_ad  [N_NODES * NREL * HEADS];
__device__ int   g_deg [RN];
__device__ int   g_off [RN + 1];
__device__ int   g_cur [RN];
__device__ int   g_adj [TOTE];
__device__ int   g_part[256];
__device__ int   g_is64;

/* bf16 split operands for tensor-core GEMM1 */
__device__ __nv_bfloat16 g_xh[(size_t)N_NODES * IN_CH];
__device__ __nv_bfloat16 g_xl[(size_t)N_NODES * IN_CH];
__device__ __nv_bfloat16 g_th[(size_t)XPC * IN_CH];   /* theta^T [j][k] hi */
__device__ __nv_bfloat16 g_tl[(size_t)XPC * IN_CH];   /* theta^T [j][k] lo */

/* W_sem^T bf16 split: [s=128][d=384] */
__device__ __nv_bfloat16 g_wh[SEMD * HC];
__device__ __nv_bfloat16 g_wl[SEMD * HC];

/* per-(n,r) semantic scores, 2 partial slabs (warp-col halves) */
__device__ float g_scoreP[2][RN];

/* ------------------------------------------------------------------ */
/* edge_index dtype detection (JAX x64-disabled => int32)              */
/* ------------------------------------------------------------------ */
__global__ void detect_kernel(const int* __restrict__ ei32)
{
    if (threadIdx.x == 0) {
        int is64 = 1;
        for (int i = 1; i < 128; i += 2)
            if (ei32[i] != 0) { is64 = 0; break; }
        g_is64 = is64;
    }
}

__device__ __forceinline__ int load_idx(const void* ei, int is64, size_t pos)
{
    int v = is64 ? (int)((const long long*)ei)[pos]
                 : ((const int*)ei)[pos];
    if ((unsigned)v >= (unsigned)N_NODES) v = 0;
    return v;
}

/* ------------------------------------------------------------------ */
/* bf16 split preprocessing                                            */
/* ------------------------------------------------------------------ */
__global__ void split_x_kernel(const float* __restrict__ x)
{
    int i = blockIdx.x * blockDim.x + threadIdx.x;
    if (i >= N_NODES * IN_CH) return;
    float v = x[i];
    __nv_bfloat16 h = __float2bfloat16(v);
    g_xh[i] = h;
    g_xl[i] = __float2bfloat16(v - __bfloat162float(h));
}

__global__ void split_theta_kernel(const float* __restrict__ theta)
{
    int i = blockIdx.x * blockDim.x + threadIdx.x;
    if (i >= XPC * IN_CH) return;
    int j = i / IN_CH;          /* output col 0..1151 */
    int k = i % IN_CH;
    int r  = j / HC;
    int hc = j % HC;
    float v = theta[((size_t)r * IN_CH + k) * HC + hc];
    __nv_bfloat16 h = __float2bfloat16(v);
    g_th[i] = h;
    g_tl[i] = __float2bfloat16(v - __bfloat162float(h));
}

__global__ void split_wsem_kernel(const float* __restrict__ W_sem)
{
    int i = blockIdx.x * blockDim.x + threadIdx.x;
    if (i >= SEMD * HC) return;
    int s = i / HC;
    int d = i % HC;
    float v = W_sem[(size_t)d * SEMD + s];
    __nv_bfloat16 h = __float2bfloat16(v);
    g_wh[i] = h;
    g_wl[i] = __float2bfloat16(v - __bfloat162float(h));
}

/* ------------------------------------------------------------------ */
/* mma.sync / ldmatrix / cp.async helpers                              */
/* ------------------------------------------------------------------ */
__device__ __forceinline__ void mma16816(float* c, const uint32_t* a,
                                         const uint32_t* b)
{
    asm volatile(
        "mma.sync.aligned.m16n8k16.row.col.f32.bf16.bf16.f32 "
        "{%0,%1,%2,%3}, {%4,%5,%6,%7}, {%8,%9}, {%0,%1,%2,%3};"
        : "+f"(c[0]), "+f"(c[1]), "+f"(c[2]), "+f"(c[3])
        : "r"(a[0]), "r"(a[1]), "r"(a[2]), "r"(a[3]),
          "r"(b[0]), "r"(b[1]));
}

__device__ __forceinline__ void ldsm_x4(uint32_t* r, uint32_t addr)
{
    asm volatile("ldmatrix.sync.aligned.m8n8.x4.shared.b16 {%0,%1,%2,%3}, [%4];"
                 : "=r"(r[0]), "=r"(r[1]), "=r"(r[2]), "=r"(r[3])
                 : "r"(addr));
}

__device__ __forceinline__ uint32_t cvta_s(const void* p)
{
    return (uint32_t)__cvta_generic_to_shared(p);
}

#define CP16(dst, src, sz) \
    asm volatile("cp.async.cg.shared.global [%0], [%1], 16, %2;" \
                 :: "r"(dst), "l"(src), "r"(sz))
#define CP_COMMIT() asm volatile("cp.async.commit_group;")
#define CP_WAIT(n)  asm volatile("cp.async.wait_group %0;" :: "n"(n))

__device__ __forceinline__ uint32_t pack_bf2(float a, float b)
{
    uint32_t lo = (uint32_t)__bfloat16_as_ushort(__float2bfloat16(a));
    uint32_t hi = (uint32_t)__bfloat16_as_ushort(__float2bfloat16(b));
    return (hi << 16) | lo;
}

__device__ __forceinline__ float fast_tanh(float x)
{
    float e = __expf(2.f * x);
    return 1.f - __fdividef(2.f, e + 1.f);
}

/* ------------------------------------------------------------------ */
/* GEMM1 via mma.sync bf16: 128x128 block, 8 warps, warp 32x64.        */
/* cp.async double-buffered staging (dynamic smem, 2 stages).          */
/* Fused epilogue: also computes a_src/a_dst dot products (asd).       */
/* ------------------------------------------------------------------ */
#define BK    32
#define LDA   40                      /* padded bf16 row stride */
#define TILE_ELEMS (128 * LDA)        /* 5120 bf16 per array    */
#define BUF_ELEMS  (4 * TILE_ELEMS)   /* 20480 bf16 per stage   */
#define GEMM_DSMEM (2 * BUF_ELEMS * 2) /* 81920 bytes           */

__global__ __launch_bounds__(256, 2)
void gemm1_mma_kernel(const float* __restrict__ att_src,
                      const float* __restrict__ att_dst)
{
    extern __shared__ __nv_bfloat16 dsm[];
    /* per-stage layout: [sAh | sAl | sBh | sBl], each 128xLDA */

    const int tid   = threadIdx.x;
    const int wid   = tid >> 5;
    const int lane  = tid & 31;
    const int wm    = wid & 3;
    const int wn    = wid >> 2;
    const int row0  = blockIdx.y * 128;
    const int col0  = blockIdx.x * 128;

    float c[2][8][4];
#pragma unroll
    for (int i = 0; i < 2; i++)
#pragma unroll
        for (int j = 0; j < 8; j++)
#pragma unroll
            for (int q = 0; q < 4; q++) c[i][j][q] = 0.f;

    /* ldmatrix lane addresses for stage 0; stage1 = +BUF_ELEMS*2 bytes */
    const int laA_r = lane & 15;
    const int laA_k = (lane >> 4) * 8;
    uint32_t aAH[2], aAL[2];
#pragma unroll
    for (int i = 0; i < 2; i++) {
        const int rr = wm * 32 + i * 16 + laA_r;
        aAH[i] = cvta_s(&dsm[0 * TILE_ELEMS + rr * LDA + laA_k]);
        aAL[i] = cvta_s(&dsm[1 * TILE_ELEMS + rr * LDA + laA_k]);
    }
    const int laB_n = (lane & 7) + ((lane >> 4) << 3);
    const int laB_k = ((lane >> 3) & 1) * 8;
    uint32_t aBH[4], aBL[4];
#pragma unroll
    for (int j2 = 0; j2 < 4; j2++) {
        const int nr = wn * 64 + j2 * 16 + laB_n;
        aBH[j2] = cvta_s(&dsm[2 * TILE_ELEMS + nr * LDA + laB_k]);
        aBL[j2] = cvta_s(&dsm[3 * TILE_ELEMS + nr * LDA + laB_k]);
    }

    /* staging lanes */
    const int sr = tid >> 1;
    const int sc = (tid & 1) * 16;
    const int am = row0 + sr;
    const int asz = (am < N_NODES) ? 16 : 0;
    const uint32_t dA = cvta_s(&dsm[sr * LDA + sc]);
    const size_t agi = (size_t)am * IN_CH + sc;      /* + kc */
    const size_t bgi = (size_t)(col0 + sr) * IN_CH + sc;

    /* prologue: stage kc=0 into stage 0 */
    {
        CP16(dA + 0 * TILE_ELEMS * 2, g_xh + agi, asz);
        CP16(dA + 1 * TILE_ELEMS * 2, g_xl + agi, asz);
        CP16(dA + 2 * TILE_ELEMS * 2, g_th + bgi, 16);
        CP16(dA + 3 * TILE_ELEMS * 2, g_tl + bgi, 16);
        CP16(dA + 0 * TILE_ELEMS * 2 + 16, g_xh + agi + 8, asz);
        CP16(dA + 1 * TILE_ELEMS * 2 + 16, g_xl + agi + 8, asz);
        CP16(dA + 2 * TILE_ELEMS * 2 + 16, g_th + bgi + 8, 16);
        CP16(dA + 3 * TILE_ELEMS * 2 + 16, g_tl + bgi + 8, 16);
        CP_COMMIT();
    }

    int buf = 0;
    for (int kc = 0; kc < IN_CH; kc += BK) {
        __syncthreads();   /* all warps done computing the stage we overwrite */
        const int has_next = (kc + BK < IN_CH);
        if (has_next) {
            const uint32_t dN = dA + (buf ^ 1) * (uint32_t)(BUF_ELEMS * 2);
            const size_t ag = agi + kc + BK;
            const size_t bg = bgi + kc + BK;
            CP16(dN + 0 * TILE_ELEMS * 2, g_xh + ag, asz);
            CP16(dN + 1 * TILE_ELEMS * 2, g_xl + ag, asz);
            CP16(dN + 2 * TILE_ELEMS * 2, g_th + bg, 16);
            CP16(dN + 3 * TILE_ELEMS * 2, g_tl + bg, 16);
            CP16(dN + 0 * TILE_ELEMS * 2 + 16, g_xh + ag + 8, asz);
            CP16(dN + 1 * TILE_ELEMS * 2 + 16, g_xl + ag + 8, asz);
            CP16(dN + 2 * TILE_ELEMS * 2 + 16, g_th + bg + 8, 16);
            CP16(dN + 3 * TILE_ELEMS * 2 + 16, g_tl + bg + 8, 16);
            CP_COMMIT();
            CP_WAIT(1);
        } else {
            CP_WAIT(0);
        }
        __syncthreads();

        const uint32_t boff = buf * (uint32_t)(BUF_ELEMS * 2);
#pragma unroll
        for (int ks = 0; ks < BK; ks += 16) {
            const uint32_t koff = boff + ks * 2;
            uint32_t ah[2][4], al[2][4];
#pragma unroll
            for (int i = 0; i < 2; i++) {
                ldsm_x4(ah[i], aAH[i] + koff);
                ldsm_x4(al[i], aAL[i] + koff);
            }
            uint32_t bh[8][2], bl[8][2];
#pragma unroll
            for (int j2 = 0; j2 < 4; j2++) {
                ldsm_x4(&bh[2 * j2][0], aBH[j2] + koff);
                ldsm_x4(&bl[2 * j2][0], aBL[j2] + koff);
            }
#pragma unroll
            for (int i = 0; i < 2; i++)
#pragma unroll
                for (int j = 0; j < 8; j++) {
                    mma16816(c[i][j], ah[i], bh[j]);
                    mma16816(c[i][j], ah[i], bl[j]);
                    mma16816(c[i][j], al[i], bh[j]);
                }
        }
        buf ^= 1;
    }

    /* ---- epilogue 1: store xp tile ---- */
    const int crow = lane >> 2;
    const int ccol = (lane & 3) * 2;
#pragma unroll
    for (int i = 0; i < 2; i++) {
        const int mbase = row0 + wm * 32 + i * 16;
#pragma unroll
        for (int j = 0; j < 8; j++) {
            const int nbase = col0 + wn * 64 + j * 8 + ccol;
            const int m0 = mbase + crow;
            const int m1 = m0 + 8;
            if (m0 < N_NODES)
                *(float2*)&g_xp[(size_t)m0 * XPC + nbase] =
                    make_float2(c[i][j][0], c[i][j][1]);
            if (m1 < N_NODES)
                *(float2*)&g_xp[(size_t)m1 * XPC + nbase] =
                    make_float2(c[i][j][2], c[i][j][3]);
        }
    }

    /* ---- epilogue 2: fused asd (this block col = one (r,h) pair) ---- */
    float ds[2][2] = {{0.f, 0.f}, {0.f, 0.f}};
    float dd[2][2] = {{0.f, 0.f}, {0.f, 0.f}};
#pragma unroll
    for (int j = 0; j < 8; j++) {
        const int col = col0 + wn * 64 + j * 8 + ccol;
        const float s0 = att_src[col], s1 = att_src[col + 1];
        const float d0 = att_dst[col], d1 = att_dst[col + 1];
#pragma unroll
        for (int i = 0; i < 2; i++) {
            ds[i][0] += c[i][j][0] * s0 + c[i][j][1] * s1;
            ds[i][1] += c[i][j][2] * s0 + c[i][j][3] * s1;
            dd[i][0] += c[i][j][0] * d0 + c[i][j][1] * d1;
            dd[i][1] += c[i][j][2] * d0 + c[i][j][3] * d1;
        }
    }
#pragma unroll
    for (int o = 1; o <= 2; o <<= 1)
#pragma unroll
        for (int i = 0; i < 2; i++) {
            ds[i][0] += __shfl_xor_sync(0xffffffffu, ds[i][0], o);
            ds[i][1] += __shfl_xor_sync(0xffffffffu, ds[i][1], o);
            dd[i][0] += __shfl_xor_sync(0xffffffffu, dd[i][0], o);
            dd[i][1] += __shfl_xor_sync(0xffffffffu, dd[i][1], o);
        }

    float* sred = (float*)dsm;   /* reuse smem: 512 floats */
    __syncthreads();
    if ((lane & 3) == 0) {
#pragma unroll
        for (int i = 0; i < 2; i++)
#pragma unroll
            for (int h = 0; h < 2; h++) {
                const int rowloc = wm * 32 + i * 16 + h * 8 + crow;
                sred[rowloc * 2 + wn]       = ds[i][h];
                sred[512 + rowloc * 2 + wn] = dd[i][h];
            }
    }
    __syncthreads();
    if (tid < 128) {
        const int n = row0 + tid;
        if (n < N_NODES) {
            const int r = col0 / HC;
            const int h = (col0 % HC) / OUT_C;
            const int o = (n * NREL + r) * HEADS + h;
            g_as[o] = sred[tid * 2] + sred[tid * 2 + 1];
            g_ad[o] = sred[512 + tid * 2] + sred[512 + tid * 2 + 1];
        }
    }
}

/* ------------------------------------------------------------------ */
/* semantic GEMM via mma.sync (ldmatrix fragments), fused tanh epilog  */
/* ------------------------------------------------------------------ */
__global__ __launch_bounds__(256, 2)
void sem_score_kernel(const float* __restrict__ b_sem,
                      const float* __restrict__ q_sem)
{
    __shared__ __nv_bfloat16 sAh[128][LDA];
    __shared__ __nv_bfloat16 sAl[128][LDA];
    __shared__ __nv_bfloat16 sBh[128][LDA];
    __shared__ __nv_bfloat16 sBl[128][LDA];

    const int tid   = threadIdx.x;
    const int wid   = tid >> 5;
    const int lane  = tid & 31;
    const int wm    = wid & 3;
    const int wn    = wid >> 2;
    const int row0  = blockIdx.x * 128;

    float c[2][8][4];
#pragma unroll
    for (int i = 0; i < 2; i++)
#pragma unroll
        for (int j = 0; j < 8; j++)
#pragma unroll
            for (int q = 0; q < 4; q++) c[i][j][q] = 0.f;

    const int laA_r = lane & 15;
    const int laA_k = (lane >> 4) * 8;
    uint32_t aAH[2], aAL[2];
#pragma unroll
    for (int i = 0; i < 2; i++) {
        const int rr = wm * 32 + i * 16 + laA_r;
        aAH[i] = cvta_s(&sAh[rr][laA_k]);
        aAL[i] = cvta_s(&sAl[rr][laA_k]);
    }
    const int laB_n = (lane & 7) + ((lane >> 4) << 3);
    const int laB_k = ((lane >> 3) & 1) * 8;
    uint32_t aBH[4], aBL[4];
#pragma unroll
    for (int j2 = 0; j2 < 4; j2++) {
        const int nr = wn * 64 + j2 * 16 + laB_n;
        aBH[j2] = cvta_s(&sBh[nr][laB_k]);
        aBL[j2] = cvta_s(&sBl[nr][laB_k]);
    }

    const int sr = tid >> 1;
    const int sc = (tid & 1) * 16;

    for (int kc = 0; kc < HC; kc += BK) {
        __syncthreads();
        {
            /* A: split fp32 g_gout inline */
            const int m = row0 + sr;
#pragma unroll
            for (int t = 0; t < 4; t++) {
                float4 v = make_float4(0.f, 0.f, 0.f, 0.f);
                if (m < RN)
                    v = *(const float4*)&g_gout[(size_t)m * HC + kc + sc + t * 4];
                float hx = __bfloat162float(__float2bfloat16(v.x));
                float hy = __bfloat162float(__float2bfloat16(v.y));
                float hz = __bfloat162float(__float2bfloat16(v.z));
                float hw = __bfloat162float(__float2bfloat16(v.w));
                *(uint32_t*)&sAh[sr][sc + t * 4]     = pack_bf2(v.x, v.y);
                *(uint32_t*)&sAh[sr][sc + t * 4 + 2] = pack_bf2(v.z, v.w);
                *(uint32_t*)&sAl[sr][sc + t * 4]     = pack_bf2(v.x - hx, v.y - hy);
                *(uint32_t*)&sAl[sr][sc + t * 4 + 2] = pack_bf2(v.z - hz, v.w - hw);
            }
            /* B: W_sem^T hi/lo (pre-split, [s][d]) */
            const size_t bgi = ((size_t)sr * HC + kc + sc) >> 3;
            *(uint4*)&sBh[sr][sc]     = ((const uint4*)g_wh)[bgi];
            *(uint4*)&sBl[sr][sc]     = ((const uint4*)g_wl)[bgi];
            *(uint4*)&sBh[sr][sc + 8] = ((const uint4*)g_wh)[bgi + 1];
            *(uint4*)&sBl[sr][sc + 8] = ((const uint4*)g_wl)[bgi + 1];
        }
        __syncthreads();

#pragma unroll
        for (int ks = 0; ks < BK; ks += 16) {
            const uint32_t koff = ks * 2;
            uint32_t ah[2][4], al[2][4];
#pragma unroll
            for (int i = 0; i < 2; i++) {
                ldsm_x4(ah[i], aAH[i] + koff);
                ldsm_x4(al[i], aAL[i] + koff);
            }
            uint32_t bh[8][2], bl[8][2];
#pragma unroll
            for (int j2 = 0; j2 < 4; j2++) {
                ldsm_x4(&bh[2 * j2][0], aBH[j2] + koff);
                ldsm_x4(&bl[2 * j2][0], aBL[j2] + koff);
            }
#pragma unroll
            for (int i = 0; i < 2; i++)
#pragma unroll
                for (int j = 0; j < 8; j++) {
                    mma16816(c[i][j], ah[i], bh[j]);
                    mma16816(c[i][j], ah[i], bl[j]);
                    mma16816(c[i][j], al[i], bh[j]);
                }
        }
    }

    /* fused epilogue: tanh(w+b)*q, reduce over this warp's 64 cols */
    const int crow = lane >> 2;
    const int ccol = (lane & 3) * 2;
    float rs[2][2] = {{0.f, 0.f}, {0.f, 0.f}};
#pragma unroll
    for (int i = 0; i < 2; i++)
#pragma unroll
        for (int j = 0; j < 8; j++) {
            const int col = wn * 64 + j * 8 + ccol;
            const float b0 = b_sem[col],     b1 = b_sem[col + 1];
            const float q0 = q_sem[col],     q1 = q_sem[col + 1];
            rs[i][0] += fast_tanh(c[i][j][0] + b0) * q0
                      + fast_tanh(c[i][j][1] + b1) * q1;
            rs[i][1] += fast_tanh(c[i][j][2] + b0) * q0
                      + fast_tanh(c[i][j][3] + b1) * q1;
        }
#pragma unroll
    for (int o = 1; o <= 2; o <<= 1) {
#pragma unroll
        for (int i = 0; i < 2; i++) {
            rs[i][0] += __shfl_xor_sync(0xffffffffu, rs[i][0], o);
            rs[i][1] += __shfl_xor_sync(0xffffffffu, rs[i][1], o);
        }
    }
    if ((lane & 3) == 0) {
#pragma unroll
        for (int i = 0; i < 2; i++)
#pragma unroll
            for (int h = 0; h < 2; h++) {
                const int row = row0 + wm * 32 + i * 16 + h * 8 + crow;
                if (row < RN) g_scoreP[wn][row] = rs[i][h];
            }
    }
}

/* ------------------------------------------------------------------ */
/* sem_final: softmax over 3 relation scores + weighted combine        */
/* ------------------------------------------------------------------ */
__global__ void sem_final_kernel(const float* __restrict__ mgx,
                                 const float* __restrict__ gsrc,
                                 const float* __restrict__ gdst,
                                 float* __restrict__ out)
{
    const int node = blockIdx.x * 4 + (threadIdx.x >> 5);
    const int lane = threadIdx.x & 31;
    if (node >= N_NODES) return;

    const int rb = node * NREL;
    const float S0 = g_scoreP[0][rb + 0] + g_scoreP[1][rb + 0];
    const float S1 = g_scoreP[0][rb + 1] + g_scoreP[1][rb + 1];
    const float S2 = g_scoreP[0][rb + 2] + g_scoreP[1][rb + 2];

    const float bm = fmaxf(S0, fmaxf(S1, S2));
    const float e0 = expf(S0 - bm), e1 = expf(S1 - bm), e2 = expf(S2 - bm);
    const float iv = 1.f / (e0 + e1 + e2);
    const float b0 = e0 * iv, b1 = e1 * iv, b2 = e2 * iv;

    const float* gp = &g_gout[(size_t)node * XPC];
#pragma unroll
    for (int t = 0; t < 3; t++) {
        const int cidx = lane * 4 + t * 128;
        float4 v0 = *(const float4*)&gp[cidx];
        float4 v1 = *(const float4*)&gp[HC + cidx];
        float4 v2 = *(const float4*)&gp[2 * HC + cidx];
        float4 mg = *(const float4*)&mgx[cidx];
        float4 gs = *(const float4*)&gsrc[cidx];
        float4 gd = *(const float4*)&gdst[cidx];
        float4 o;
        o.x = b0 * v0.x + b1 * v1.x + b2 * v2.x + mg.x * (gs.x + gd.x);
        o.y = b0 * v0.y + b1 * v1.y + b2 * v2.y + mg.y * (gs.y + gd.y);
        o.z = b0 * v0.z + b1 * v1.z + b2 * v2.z + mg.z * (gs.z + gd.z);
        o.w = b0 * v0.w + b1 * v1.w + b2 * v2.w + mg.w * (gs.w + gd.w);
        *(float4*)&out[(size_t)node * HC + cidx] = o;
    }
}

/* ------------------------------------------------------------------ */
/* CSR build                                                           */
/* ------------------------------------------------------------------ */
__global__ void zero_deg_kernel()
{
    int i = blockIdx.x * blockDim.x + threadIdx.x;
    if (i < RN) g_deg[i] = 0;
}

__global__ void count_kernel(const void* __restrict__ ei)
{
    int i = blockIdx.x * blockDim.x + threadIdx.x;
    if (i >= TOTE) return;
    const int is64 = g_is64;
    int r = i / NEDGE;
    int e = i % NEDGE;
    int dst = load_idx(ei, is64, (size_t)r * 2 * NEDGE + NEDGE + e);
    atomicAdd(&g_deg[r * N_NODES + dst], 1);
}

#define SCH 1024
__global__ void scan1_kernel()
{
    __shared__ int s[256];
    const int b = blockIdx.x, t = threadIdx.x;
    const int base = b * SCH + t * 4;
    int v[4], sum = 0;
#pragma unroll
    for (int i = 0; i < 4; i++) {
        int idx = base + i;
        v[i] = (idx < RN) ? g_deg[idx] : 0;
        sum += v[i];
    }
    s[t] = sum;
    __syncthreads();
    for (int o = 1; o < 256; o <<= 1) {
        int xv = (t >= o) ? s[t - o] : 0;
        __syncthreads();
        s[t] += xv;
        __syncthreads();
    }
    int run = s[t] - sum;
    if (t == 255) g_part[b] = s[t];
#pragma unroll
    for (int i = 0; i < 4; i++) {
        int idx = base + i;
        if (idx < RN) g_off[idx] = run;
        run += v[i];
    }
}

__global__ void scan2_kernel(int nb)
{
    __shared__ int s[256];
    const int t = threadIdx.x;
    int v = (t < nb) ? g_part[t] : 0;
    s[t] = v;
    __syncthreads();
    for (int o = 1; o < 256; o <<= 1) {
        int xv = (t >= o) ? s[t - o] : 0;
        __syncthreads();
        s[t] += xv;
        __syncthreads();
    }
    g_part[t] = s[t] - v;
}

__global__ void scan3_kernel()
{
    int i = blockIdx.x * blockDim.x + threadIdx.x;
    if (i < RN) {
        int v = g_off[i] + g_part[i / SCH];
        g_off[i] = v;
        g_cur[i] = v;
    }
    if (i == 0) g_off[RN] = TOTE;
}

__global__ void fill_kernel(const void* __restrict__ ei)
{
    int i = blockIdx.x * blockDim.x + threadIdx.x;
    if (i >= TOTE) return;
    const int is64 = g_is64;
    int r = i / NEDGE;
    int e = i % NEDGE;
    int src = load_idx(ei, is64, (size_t)r * 2 * NEDGE + e);
    int dst = load_idx(ei, is64, (size_t)r * 2 * NEDGE + NEDGE + e);
    int pos = atomicAdd(&g_cur[r * N_NODES + dst], 1);
    if (pos >= 0 && pos < TOTE) g_adj[pos] = src;
}

/* ------------------------------------------------------------------ */
/* GAT aggregation: one warp per (r,n); single-exp two-phase softmax,  */
/* float4 gather. Unnormalized accumulate, scale by 1/(z+eps) at end.  */
/* ------------------------------------------------------------------ */
#define ACAP 64
__device__ __forceinline__ float lrelu(float v) { return v > 0.f ? v : 0.2f * v; }

__global__ void agg_kernel(const float* __restrict__ gat_bias)
{
    __shared__ float pbuf[4][ACAP][3];
    __shared__ int   sbuf[4][ACAP];

    const int w    = threadIdx.x >> 5;
    const int lane = threadIdx.x & 31;
    const int item = blockIdx.x * 4 + w;
    if (item >= RN) return;
    const int r = item / N_NODES;      /* relation-major -> L2 residency */
    const int n = item % N_NODES;

    const int off0 = g_off[r * N_NODES + n];
    const int deg  = g_off[r * N_NODES + n + 1] - off0;
    const int tot  = deg + 1;          /* + self loop */

    const float ad0 = g_ad[(n * NREL + r) * HEADS + 0];
    const float ad1 = g_ad[(n * NREL + r) * HEADS + 1];
    const float ad2 = g_ad[(n * NREL + r) * HEADS + 2];

    float4 acc[3];
#pragma unroll
    for (int k = 0; k < 3; k++) acc[k] = make_float4(0.f, 0.f, 0.f, 0.f);
    float z0 = 0.f, z1 = 0.f, z2 = 0.f;

    if (tot <= ACAP) {
        for (int i = lane; i < tot; i += 32) {
            const int src = (i < deg) ? g_adj[off0 + i] : n;
            sbuf[w][i] = src;
            const float* as = &g_as[(src * NREL + r) * HEADS];
            pbuf[w][i][0] = lrelu(as[0] + ad0);
            pbuf[w][i][1] = lrelu(as[1] + ad1);
            pbuf[w][i][2] = lrelu(as[2] + ad2);
        }
        __syncwarp();
        float m0 = -1e30f, m1 = -1e30f, m2 = -1e30f;
        for (int i = lane; i < tot; i += 32) {
            m0 = fmaxf(m0, pbuf[w][i][0]);
            m1 = fmaxf(m1, pbuf[w][i][1]);
            m2 = fmaxf(m2, pbuf[w][i][2]);
        }
#pragma unroll
        for (int o = 16; o > 0; o >>= 1) {
            m0 = fmaxf(m0, __shfl_xor_sync(0xffffffffu, m0, o));
            m1 = fmaxf(m1, __shfl_xor_sync(0xffffffffu, m1, o));
            m2 = fmaxf(m2, __shfl_xor_sync(0xffffffffu, m2, o));
        }
        for (int i = lane; i < tot; i += 32) {
            const float p0 = expf(pbuf[w][i][0] - m0);
            const float p1 = expf(pbuf[w][i][1] - m1);
            const float p2 = expf(pbuf[w][i][2] - m2);
            pbuf[w][i][0] = p0;  z0 += p0;
            pbuf[w][i][1] = p1;  z1 += p1;
            pbuf[w][i][2] = p2;  z2 += p2;
        }
#pragma unroll
        for (int o = 16; o > 0; o >>= 1) {
            z0 += __shfl_xor_sync(0xffffffffu, z0, o);
            z1 += __shfl_xor_sync(0xffffffffu, z1, o);
            z2 += __shfl_xor_sync(0xffffffffu, z2, o);
        }
        __syncwarp();
        for (int j = 0; j < tot; j++) {
            const int   src = sbuf[w][j];
            const float a0  = pbuf[w][j][0];
            const float a1  = pbuf[w][j][1];
            const float a2  = pbuf[w][j][2];
            const float4* xr = (const float4*)&g_xp[(size_t)src * XPC + r * HC];
            const float4 x0 = xr[lane];
            const float4 x1 = xr[lane + 32];
            const float4 x2 = xr[lane + 64];
            acc[0].x = fmaf(a0, x0.x, acc[0].x);
            acc[0].y = fmaf(a0, x0.y, acc[0].y);
            acc[0].z = fmaf(a0, x0.z, acc[0].z);
            acc[0].w = fmaf(a0, x0.w, acc[0].w);
            acc[1].x = fmaf(a1, x1.x, acc[1].x);
            acc[1].y = fmaf(a1, x1.y, acc[1].y);
            acc[1].z = fmaf(a1, x1.z, acc[1].z);
            acc[1].w = fmaf(a1, x1.w, acc[1].w);
            acc[2].x = fmaf(a2, x2.x, acc[2].x);
            acc[2].y = fmaf(a2, x2.y, acc[2].y);
            acc[2].z = fmaf(a2, x2.z, acc[2].z);
            acc[2].w = fmaf(a2, x2.w, acc[2].w);
        }
    } else {
        float m0 = -1e30f, m1 = -1e30f, m2 = -1e30f;
        for (int base = 0; base < tot; base += 32) {
            const int i = base + lane;
            if (i < tot) {
                const int src = (i < deg) ? g_adj[off0 + i] : n;
                const float* as = &g_as[(src * NREL + r) * HEADS];
                m0 = fmaxf(m0, lrelu(as[0] + ad0));
                m1 = fmaxf(m1, lrelu(as[1] + ad1));
                m2 = fmaxf(m2, lrelu(as[2] + ad2));
            }
        }
#pragma unroll
        for (int o = 16; o > 0; o >>= 1) {
            m0 = fmaxf(m0, __shfl_xor_sync(0xffffffffu, m0, o));
            m1 = fmaxf(m1, __shfl_xor_sync(0xffffffffu, m1, o));
            m2 = fmaxf(m2, __shfl_xor_sync(0xffffffffu, m2, o));
        }
        for (int c0 = 0; c0 < tot; c0 += ACAP) {
            const int clen = min(ACAP, tot - c0);
            for (int base = 0; base < clen; base += 32) {
                const int i = base + lane;
                if (i < clen) {
                    const int gi  = c0 + i;
                    const int src = (gi < deg) ? g_adj[off0 + gi] : n;
                    sbuf[w][i] = src;
                    const float* as = &g_as[(src * NREL + r) * HEADS];
                    const float p0 = expf(lrelu(as[0] + ad0) - m0);
                    const float p1 = expf(lrelu(as[1] + ad1) - m1);
                    const float p2 = expf(lrelu(as[2] + ad2) - m2);
                    pbuf[w][i][0] = p0;  z0 += p0;
                    pbuf[w][i][1] = p1;  z1 += p1;
                    pbuf[w][i][2] = p2;  z2 += p2;
                }
            }
            __syncwarp();
            for (int j = 0; j < clen; j++) {
                const int   src = sbuf[w][j];
                const float a0  = pbuf[w][j][0];
                const float a1  = pbuf[w][j][1];
                const float a2  = pbuf[w][j][2];
                const float4* xr = (const float4*)&g_xp[(size_t)src * XPC + r * HC];
                const float4 x0 = xr[lane];
                const float4 x1 = xr[lane + 32];
                const float4 x2 = xr[lane + 64];
                acc[0].x = fmaf(a0, x0.x, acc[0].x);
                acc[0].y = fmaf(a0, x0.y, acc[0].y);
                acc[0].z = fmaf(a0, x0.z, acc[0].z);
                acc[0].w = fmaf(a0, x0.w, acc[0].w);
                acc[1].x = fmaf(a1, x1.x, acc[1].x);
                acc[1].y = fmaf(a1, x1.y, acc[1].y);
                acc[1].z = fmaf(a1, x1.z, acc[1].z);
                acc[1].w = fmaf(a1, x1.w, acc[1].w);
                acc[2].x = fmaf(a2, x2.x, acc[2].x);
                acc[2].y = fmaf(a2, x2.y, acc[2].y);
                acc[2].z = fmaf(a2, x2.z, acc[2].z);
                acc[2].w = fmaf(a2, x2.w, acc[2].w);
            }
            __syncwarp();
        }
#pragma unroll
        for (int o = 16; o > 0; o >>= 1) {
            z0 += __shfl_xor_sync(0xffffffffu, z0, o);
            z1 += __shfl_xor_sync(0xffffffffu, z1, o);
            z2 += __shfl_xor_sync(0xffffffffu, z2, o);
        }
    }

    const float iv0 = 1.f / (z0 + 1e-16f);
    const float iv1 = 1.f / (z1 + 1e-16f);
    const float iv2 = 1.f / (z2 + 1e-16f);

    const float4* bp4 = (const float4*)&gat_bias[r * HC];
    float4* op4 = (float4*)&g_gout[((size_t)n * NREL + r) * HC];
    const float ivs[3] = {iv0, iv1, iv2};
#pragma unroll
    for (int k = 0; k < 3; k++) {
        const float4 b = bp4[lane + 32 * k];
        float4 v;
        v.x = fmaxf(fmaf(acc[k].x, ivs[k], b.x), 0.f);
        v.y = fmaxf(fmaf(acc[k].y, ivs[k], b.y), 0.f);
        v.z = fmaxf(fmaf(acc[k].z, ivs[k], b.z), 0.f);
        v.w = fmaxf(fmaf(acc[k].w, ivs[k], b.w), 0.f);
        op4[lane + 32 * k] = v;
    }
}

/* ------------------------------------------------------------------ */
extern "C" void kernel_launch(void* const* d_in, const int* in_sizes, int n_in,
                              void* d_out, int out_size)
{
    const float* x        = (const float*)d_in[0];
    const float* theta    = (const float*)d_in[1];
    const float* att_src  = (const float*)d_in[2];
    const float* att_dst  = (const float*)d_in[3];
    const float* gat_bias = (const float*)d_in[4];
    const float* W_sem    = (const float*)d_in[5];
    const float* b_sem    = (const float*)d_in[6];
    const float* q_sem    = (const float*)d_in[7];
    const float* mgx      = (const float*)d_in[8];
    const float* gsrc     = (const float*)d_in[9];
    const float* gdst     = (const float*)d_in[10];
    const void*  ei       = d_in[11];
    float* out = (float*)d_out;

    /* 0. edge_index dtype detection (int32 vs int64) */
    detect_kernel<<<1, 32>>>((const int*)ei);

    /* 1. bf16-split operands, then cp.async-pipelined HMMA GEMM1
          (fused asd epilogue) */
    split_x_kernel<<<(N_NODES * IN_CH + 255) / 256, 256>>>(x);
    split_theta_kernel<<<(XPC * IN_CH + 255) / 256, 256>>>(theta);
    split_wsem_kernel<<<(SEMD * HC + 255) / 256, 256>>>(W_sem);
    cudaFuncSetAttribute(gemm1_mma_kernel,
                         cudaFuncAttributeMaxDynamicSharedMemorySize, GEMM_DSMEM);
    gemm1_mma_kernel<<<dim3(XPC / 128, (N_NODES + 127) / 128), 256, GEMM_DSMEM>>>(
        att_src, att_dst);

    /* 2. CSR build (group edges by dst) */
    zero_deg_kernel<<<(RN + 255) / 256, 256>>>();
    count_kernel<<<(TOTE + 255) / 256, 256>>>(ei);
    scan1_kernel<<<(RN + SCH - 1) / SCH, 256>>>();
    scan2_kernel<<<1, 256>>>((RN + SCH - 1) / SCH);
    scan3_kernel<<<(RN + 255) / 256, 256>>>();
    fill_kernel<<<(TOTE + 255) / 256, 256>>>(ei);

    /* 3. per-(relation,node) GAT softmax + aggregate */
    agg_kernel<<<RN / 4, 128>>>(gat_bias);

    /* 4. semantic attention: HMMA score GEMM + softmax combine */
    sem_score_kernel<<<(RN + 127) / 128, 256>>>(b_sem, q_sem);
    sem_final_kernel<<<(N_NODES + 3) / 4, 128>>>(mgx, gsrc, gdst, out);
}